// round 14
// baseline (speedup 1.0000x reference)
#include <cuda_runtime.h>
#include <cuda_bf16.h>
#include <cuda_fp16.h>
#include <math.h>
#include <float.h>
#include <stdint.h>

// ============================================================================
// HybridViT forward, round 13: software-pipelined MMA kernels (double-buffered
// smem, LDG->reg prefetch overlapped with MMA), ff2 split-K=4, launch order
// arranged so ncu (-s 5) captures conv2.
// ============================================================================

#define NPATCH 256      // B*NP
#define ROWS   272      // B*(NP+1)

// ---------------- scratch (device globals; allocation-free rule) ------------
__device__ float    g_c1 [(size_t)NPATCH*32*107*107];
__device__ __half   g_p1 [(size_t)NPATCH*32*103*103];
__device__ float    g_c2 [(size_t)NPATCH*64*49*49];
__device__ __half   g_p2 [(size_t)NPATCH*64*45*45];
__device__ float    g_c3 [(size_t)NPATCH*64*20*20];
__device__ __half   g_p3 [(size_t)NPATCH*64*16*16];
__device__ uint32_t g_w2 [(size_t)64*1568];
__device__ uint32_t g_w3 [(size_t)64*3136];
__device__ uint32_t g_qkvw [(size_t)6*1536*512];
__device__ uint32_t g_outw [(size_t)6*512*512];
__device__ uint32_t g_ff1w [(size_t)6*2048*512];
__device__ uint32_t g_ff2w [(size_t)6*512*2048];
__device__ uint32_t g_flatw[(size_t)512*16384];
__device__ float    g_fpart[(size_t)16*NPATCH*512];
__device__ float    g_tok[(size_t)NPATCH*512];
__device__ float    g_x  [(size_t)ROWS*512];
__device__ uint32_t g_hp [(size_t)ROWS*512];
__device__ float    g_qkv[(size_t)ROWS*1536];
__device__ uint32_t g_op [(size_t)ROWS*512];
__device__ uint32_t g_ffp[(size_t)ROWS*2048];
__device__ float    g_cls[(size_t)16*512];

// ---------------- packing helpers -------------------------------------------
__device__ __forceinline__ uint32_t pack_hilo_bf16(float v)
{
    __nv_bfloat16 h = __float2bfloat16(v);
    __nv_bfloat16 l = __float2bfloat16(v - __bfloat162float(h));
    uint32_t hu = *reinterpret_cast<unsigned short*>(&h);
    uint32_t lu = *reinterpret_cast<unsigned short*>(&l);
    return hu | (lu << 16);
}
__device__ __forceinline__ uint32_t pack_hilo_f16(float v)
{
    __half h = __float2half_rn(v);
    __half l = __float2half_rn(v - __half2float(h));
    return (uint32_t)__half_as_ushort(h) | ((uint32_t)__half_as_ushort(l) << 16);
}

__global__ void pack_weights_f16_kernel(const float* __restrict__ in, uint32_t* __restrict__ out, int n)
{
    int idx = blockIdx.x * blockDim.x + threadIdx.x;
    if (idx < n) out[idx] = pack_hilo_f16(in[idx]);
}

template<bool F16>
__global__ void transpose_pack_kernel(const float* __restrict__ in, uint32_t* __restrict__ out,
                                      int K, int N)
{
    __shared__ float tile[32][33];
    const size_t base = (size_t)blockIdx.z * K * N;
    const int n0 = blockIdx.x * 32;
    const int k0 = blockIdx.y * 32;
#pragma unroll
    for (int j = 0; j < 4; j++) {
        int k = k0 + threadIdx.y + j * 8, n = n0 + threadIdx.x;
        if (k < K && n < N) tile[threadIdx.y + j * 8][threadIdx.x] = in[base + (size_t)k * N + n];
    }
    __syncthreads();
#pragma unroll
    for (int j = 0; j < 4; j++) {
        int n = n0 + threadIdx.y + j * 8, k = k0 + threadIdx.x;
        if (n < N && k < K) {
            float v = tile[threadIdx.x][threadIdx.y + j * 8];
            out[base + (size_t)n * K + k] = F16 ? pack_hilo_f16(v) : pack_hilo_bf16(v);
        }
    }
}

// ---------------- warp MMA helpers ------------------------------------------
__device__ __forceinline__ uint32_t smem_u32(const void* p)
{
    uint32_t a;
    asm("{ .reg .u64 t; cvta.to.shared.u64 t, %1; cvt.u32.u64 %0, t; }" : "=r"(a) : "l"(p));
    return a;
}
__device__ __forceinline__ void ldsm4(uint32_t* r, uint32_t addr)
{
    asm volatile("ldmatrix.sync.aligned.m8n8.x4.shared.b16 {%0,%1,%2,%3}, [%4];"
                 : "=r"(r[0]), "=r"(r[1]), "=r"(r[2]), "=r"(r[3]) : "r"(addr));
}
__device__ __forceinline__ void mma_bf16(float* d, const uint32_t* a, const uint32_t* b)
{
    asm volatile("mma.sync.aligned.m16n8k16.row.col.f32.bf16.bf16.f32 "
                 "{%0,%1,%2,%3}, {%4,%5,%6,%7}, {%8,%9}, {%0,%1,%2,%3};"
                 : "+f"(d[0]), "+f"(d[1]), "+f"(d[2]), "+f"(d[3])
                 : "r"(a[0]), "r"(a[1]), "r"(a[2]), "r"(a[3]), "r"(b[0]), "r"(b[1]));
}
__device__ __forceinline__ void mma_f16(float* d, const uint32_t* a, const uint32_t* b)
{
    asm volatile("mma.sync.aligned.m16n8k16.row.col.f32.f16.f16.f32 "
                 "{%0,%1,%2,%3}, {%4,%5,%6,%7}, {%8,%9}, {%0,%1,%2,%3};"
                 : "+f"(d[0]), "+f"(d[1]), "+f"(d[2]), "+f"(d[3])
                 : "r"(a[0]), "r"(a[1]), "r"(a[2]), "r"(a[3]), "r"(b[0]), "r"(b[1]));
}

__device__ __forceinline__ float gelu_f(float x)
{
    return 0.5f * x * (1.0f + erff(x * 0.7071067811865476f));
}

// ---------------- f16 pipelined implicit-GEMM conv7x7 s2 + ReLU -------------
template<int IC, int IN_H, int IN_W, int OUT_HW, int KTOT, int NCHUNK>
__global__ __launch_bounds__(256) void conv_hmma_f16_kernel(const __half* __restrict__ in,
                                                            const uint32_t* __restrict__ w,
                                                            float* __restrict__ out)
{
    constexpr int NPOS = OUT_HW * OUT_HW;
    constexpr int STR  = 72;
    constexpr int BUFE = 256 * STR;            // __half per buffer (A128 + Bhi64 + Blo64)
    extern __shared__ __align__(16) char smem_raw[];
    __half* sb = reinterpret_cast<__half*>(smem_raw);
    const uint32_t uS = smem_u32(sb);

    const int t    = threadIdx.x;
    const int lane = t & 31;
    const int wid  = t >> 5;
    const int tile  = blockIdx.x;
    const int patch = blockIdx.y;
    const int m_base = (wid >> 1) * 32;
    const int n_base = (wid & 1) * 32;

    const int a_row_off = ((lane >> 3) & 1) * 8 + (lane & 7);
    const int a_kcol    = (lane >> 4) * 8;
    const int b_row     = (lane >> 4) * 8 + (lane & 7);
    const int b_kcol    = ((lane >> 3) & 1) * 8;

    const __half* in_p = in + (size_t)patch * IC * IN_H * IN_W;
    const int kloc = (t & 31) * 2;
    const int pos0 = t >> 5;

    float acc[2][4][4];
#pragma unroll
    for (int i = 0; i < 2; i++)
#pragma unroll
        for (int j = 0; j < 4; j++)
#pragma unroll
            for (int e = 0; e < 4; e++) acc[i][j][e] = 0.f;

    uint32_t pa[16], pb0[8], pb1[8];

    auto LDG_CHUNK = [&](int c) {
        const int kbase = c * 64;
        int koff[2]; bool kval[2];
#pragma unroll
        for (int e = 0; e < 2; e++) {
            int k = kbase + kloc + e;
            kval[e] = (k < KTOT);
            int ci = k / 49, r = k - ci * 49;
            int kh = r / 7,  kw = r - kh * 7;
            koff[e] = (ci * IN_H + kh) * IN_W + kw;
        }
        int P  = tile * 128 + pos0;
        int oy = P / OUT_HW;
        int ox = P - oy * OUT_HW;
#pragma unroll
        for (int i = 0; i < 16; i++) {
            bool pv = (P < NPOS);
            int sbase = (2 * oy) * IN_W + 2 * ox;
            uint32_t h0 = (pv && kval[0]) ? (uint32_t)__half_as_ushort(in_p[koff[0] + sbase]) : 0u;
            uint32_t h1 = (pv && kval[1]) ? (uint32_t)__half_as_ushort(in_p[koff[1] + sbase]) : 0u;
            pa[i] = h0 | (h1 << 16);
            P += 8; ox += 8;
            if (ox >= OUT_HW) { ox -= OUT_HW; oy++; }
        }
#pragma unroll
        for (int i = 0; i < 8; i++) {
            int n = pos0 + i * 8;
            const uint32_t* wr = w + (size_t)n * KTOT + kbase + kloc;
            pb0[i] = kval[0] ? wr[0] : 0u;
            pb1[i] = kval[1] ? wr[1] : 0u;
        }
    };
    auto STS_CHUNK = [&](int b) {
        char* A  = reinterpret_cast<char*>(sb + (size_t)b * BUFE);
        char* Bh = A + 128 * STR * 2;
        char* Bl = Bh + 64 * STR * 2;
        uint32_t soff = (uint32_t)(pos0 * STR + kloc) * 2;
#pragma unroll
        for (int i = 0; i < 16; i++) {
            *reinterpret_cast<uint32_t*>(A + soff) = pa[i];
            soff += 8 * STR * 2;
        }
        soff = (uint32_t)(pos0 * STR + kloc) * 2;
#pragma unroll
        for (int i = 0; i < 8; i++) {
            *reinterpret_cast<uint32_t*>(Bh + soff) = __byte_perm(pb0[i], pb1[i], 0x5410);
            *reinterpret_cast<uint32_t*>(Bl + soff) = __byte_perm(pb0[i], pb1[i], 0x7632);
            soff += 8 * STR * 2;
        }
    };

    LDG_CHUNK(0);
    STS_CHUNK(0);
    __syncthreads();

    for (int c = 0; c < NCHUNK; c++) {
        if (c + 1 < NCHUNK) LDG_CHUNK(c + 1);
        const uint32_t base = uS + (uint32_t)(c & 1) * BUFE * 2;
        const uint32_t uA = base, uBh = base + 128 * STR * 2, uBl = base + 192 * STR * 2;
#pragma unroll
        for (int ks = 0; ks < 4; ks++) {
            uint32_t av[2][4], bh[2][4], bl[2][4];
#pragma unroll
            for (int mt = 0; mt < 2; mt++) {
                uint32_t off = (uint32_t)((m_base + mt * 16 + a_row_off) * STR + ks * 16 + a_kcol) * 2;
                ldsm4(av[mt], uA + off);
            }
#pragma unroll
            for (int pr = 0; pr < 2; pr++) {
                uint32_t off = (uint32_t)((n_base + pr * 16 + b_row) * STR + ks * 16 + b_kcol) * 2;
                ldsm4(bh[pr], uBh + off);
                ldsm4(bl[pr], uBl + off);
            }
#pragma unroll
            for (int mt = 0; mt < 2; mt++) {
#pragma unroll
                for (int g = 0; g < 4; g++) {
                    const uint32_t* ph = &bh[g >> 1][(g & 1) * 2];
                    const uint32_t* pl = &bl[g >> 1][(g & 1) * 2];
                    mma_f16(acc[mt][g], av[mt], ph);
                    mma_f16(acc[mt][g], av[mt], pl);
                }
            }
        }
        if (c + 1 < NCHUNK) STS_CHUNK((c + 1) & 1);
        __syncthreads();
    }

    const int gid  = lane >> 2;
    const int tid4 = lane & 3;
    float* out_p = out + (size_t)patch * 64 * NPOS;
#pragma unroll
    for (int mt = 0; mt < 2; mt++) {
#pragma unroll
        for (int g = 0; g < 4; g++) {
            int pos_a = tile * 128 + m_base + mt * 16 + gid;
            int oc0   = n_base + g * 8 + tid4 * 2;
            if (pos_a < NPOS) {
                out_p[(size_t)oc0 * NPOS + pos_a]       = fmaxf(acc[mt][g][0], 0.f);
                out_p[(size_t)(oc0 + 1) * NPOS + pos_a] = fmaxf(acc[mt][g][1], 0.f);
            }
            if (pos_a + 8 < NPOS) {
                out_p[(size_t)oc0 * NPOS + pos_a + 8]       = fmaxf(acc[mt][g][2], 0.f);
                out_p[(size_t)(oc0 + 1) * NPOS + pos_a + 8] = fmaxf(acc[mt][g][3], 0.f);
            }
        }
    }
}

// ---------------- f16 pipelined split-K GEMM (flat linear) ------------------
__global__ __launch_bounds__(256) void hmma_gemm_f16_splitk(const __half* __restrict__ A,
                                                            const uint32_t* __restrict__ B,
                                                            float* __restrict__ Cpart,
                                                            int M, int N, int K, int KC)
{
    constexpr int STR = 72;
    constexpr int BUFE = 256 * STR;
    extern __shared__ __align__(16) char smem_raw[];
    __half* sb = reinterpret_cast<__half*>(smem_raw);
    const uint32_t uS = smem_u32(sb);

    const int t    = threadIdx.x;
    const int lane = t & 31;
    const int wid  = t >> 5;
    const int bn = blockIdx.x * 64;
    const int bm = blockIdx.y * 128;
    const int z  = blockIdx.z;
    const int m_base = (wid >> 1) * 32;
    const int n_base = (wid & 1) * 32;

    const int a_row_off = ((lane >> 3) & 1) * 8 + (lane & 7);
    const int a_kcol    = (lane >> 4) * 8;
    const int b_row     = (lane >> 4) * 8 + (lane & 7);
    const int b_kcol    = ((lane >> 3) & 1) * 8;

    const int kloc = (t & 31) * 2;
    const int r0   = t >> 5;
    const uint32_t* A32 = reinterpret_cast<const uint32_t*>(A);

    float acc[2][4][4];
#pragma unroll
    for (int i = 0; i < 2; i++)
#pragma unroll
        for (int j = 0; j < 4; j++)
#pragma unroll
            for (int e = 0; e < 4; e++) acc[i][j][e] = 0.f;

    uint32_t pa[16], pb0[8], pb1[8];
    const int nchunk = KC / 64;

    auto LDG_CHUNK = [&](int c) {
        const int kbase = z * KC + c * 64;
#pragma unroll
        for (int i = 0; i < 16; i++) {
            int m = bm + r0 + i * 8;
            pa[i] = (m < M) ? A32[((size_t)m * K + kbase + kloc) >> 1] : 0u;
        }
#pragma unroll
        for (int i = 0; i < 8; i++) {
            int n = bn + r0 + i * 8;
            const uint32_t* br = B + (size_t)n * K + kbase + kloc;
            pb0[i] = br[0]; pb1[i] = br[1];
        }
    };
    auto STS_CHUNK = [&](int b) {
        char* Ab = reinterpret_cast<char*>(sb + (size_t)b * BUFE);
        char* Bh = Ab + 128 * STR * 2;
        char* Bl = Bh + 64 * STR * 2;
        uint32_t soff = (uint32_t)(r0 * STR + kloc) * 2;
#pragma unroll
        for (int i = 0; i < 16; i++) {
            *reinterpret_cast<uint32_t*>(Ab + soff) = pa[i];
            soff += 8 * STR * 2;
        }
        soff = (uint32_t)(r0 * STR + kloc) * 2;
#pragma unroll
        for (int i = 0; i < 8; i++) {
            *reinterpret_cast<uint32_t*>(Bh + soff) = __byte_perm(pb0[i], pb1[i], 0x5410);
            *reinterpret_cast<uint32_t*>(Bl + soff) = __byte_perm(pb0[i], pb1[i], 0x7632);
            soff += 8 * STR * 2;
        }
    };

    LDG_CHUNK(0); STS_CHUNK(0); __syncthreads();
    for (int c = 0; c < nchunk; c++) {
        if (c + 1 < nchunk) LDG_CHUNK(c + 1);
        const uint32_t base = uS + (uint32_t)(c & 1) * BUFE * 2;
        const uint32_t uA = base, uBh = base + 128 * STR * 2, uBl = base + 192 * STR * 2;
#pragma unroll
        for (int ks = 0; ks < 4; ks++) {
            uint32_t av[2][4], bh[2][4], bl[2][4];
#pragma unroll
            for (int mt = 0; mt < 2; mt++) {
                uint32_t off = (uint32_t)((m_base + mt * 16 + a_row_off) * STR + ks * 16 + a_kcol) * 2;
                ldsm4(av[mt], uA + off);
            }
#pragma unroll
            for (int pr = 0; pr < 2; pr++) {
                uint32_t off = (uint32_t)((n_base + pr * 16 + b_row) * STR + ks * 16 + b_kcol) * 2;
                ldsm4(bh[pr], uBh + off);
                ldsm4(bl[pr], uBl + off);
            }
#pragma unroll
            for (int mt = 0; mt < 2; mt++) {
#pragma unroll
                for (int g = 0; g < 4; g++) {
                    const uint32_t* ph = &bh[g >> 1][(g & 1) * 2];
                    const uint32_t* pl = &bl[g >> 1][(g & 1) * 2];
                    mma_f16(acc[mt][g], av[mt], ph);
                    mma_f16(acc[mt][g], av[mt], pl);
                }
            }
        }
        if (c + 1 < nchunk) STS_CHUNK((c + 1) & 1);
        __syncthreads();
    }

    const int gid  = lane >> 2;
    const int tid4 = lane & 3;
    float* oF = Cpart + (size_t)z * M * N;
#pragma unroll
    for (int mt = 0; mt < 2; mt++) {
#pragma unroll
        for (int g = 0; g < 4; g++) {
#pragma unroll
            for (int half = 0; half < 2; half++) {
                int m = bm + m_base + mt * 16 + gid + half * 8;
                if (m >= M) continue;
                int n0 = bn + n_base + g * 8 + tid4 * 2;
#pragma unroll
                for (int e = 0; e < 2; e++)
                    oF[(size_t)m * N + n0 + e] = acc[mt][g][half * 2 + e];
            }
        }
    }
}

// ---------------- bf16 3-term pipelined dense GEMM (transformer) ------------
template<int ACT, bool PACKOUT>
__global__ __launch_bounds__(256) void hmma_gemm_kernel(const uint32_t* __restrict__ A,
                                                        const uint32_t* __restrict__ B,
                                                        const float* __restrict__ bias,
                                                        const float* __restrict__ res,
                                                        float* __restrict__ outF,
                                                        uint32_t* __restrict__ outP,
                                                        int M, int N, int K, int KC)
{
    constexpr int STR = 72;
    constexpr int BUFE = 384 * STR;            // bf16 elems: Ahi128+Alo128+Bhi64+Blo64
    extern __shared__ __align__(16) char smem_raw[];
    __nv_bfloat16* sb = reinterpret_cast<__nv_bfloat16*>(smem_raw);
    const uint32_t uS = smem_u32(sb);

    const int t    = threadIdx.x;
    const int lane = t & 31;
    const int wid  = t >> 5;
    const int bn = blockIdx.x * 64;
    const int bm = blockIdx.y * 128;
    const int z  = blockIdx.z;
    const int m_base = (wid >> 1) * 32;
    const int n_base = (wid & 1) * 32;

    const int a_row_off = ((lane >> 3) & 1) * 8 + (lane & 7);
    const int a_kcol    = (lane >> 4) * 8;
    const int b_row     = (lane >> 4) * 8 + (lane & 7);
    const int b_kcol    = ((lane >> 3) & 1) * 8;

    const int kloc = (t & 31) * 2;
    const int r0   = t >> 5;

    float acc[2][4][4];
#pragma unroll
    for (int i = 0; i < 2; i++)
#pragma unroll
        for (int j = 0; j < 4; j++)
#pragma unroll
            for (int e = 0; e < 4; e++) acc[i][j][e] = 0.f;

    uint32_t pa0[16], pa1[16], pb0[8], pb1[8];
    const int nchunk = KC / 64;

    auto LDG_CHUNK = [&](int c) {
        const int kbase = z * KC + c * 64;
#pragma unroll
        for (int i = 0; i < 16; i++) {
            int m = bm + r0 + i * 8;
            uint32_t w0 = 0u, w1 = 0u;
            if (m < M) {
                const uint32_t* ar = A + (size_t)m * K + kbase + kloc;
                w0 = ar[0]; w1 = ar[1];
            }
            pa0[i] = w0; pa1[i] = w1;
        }
#pragma unroll
        for (int i = 0; i < 8; i++) {
            int n = bn + r0 + i * 8;
            const uint32_t* br = B + (size_t)n * K + kbase + kloc;
            pb0[i] = br[0]; pb1[i] = br[1];
        }
    };
    auto STS_CHUNK = [&](int b) {
        char* Ah = reinterpret_cast<char*>(sb + (size_t)b * BUFE);
        char* Al = Ah + 128 * STR * 2;
        char* Bh = Al + 128 * STR * 2;
        char* Bl = Bh + 64 * STR * 2;
        uint32_t soff = (uint32_t)(r0 * STR + kloc) * 2;
#pragma unroll
        for (int i = 0; i < 16; i++) {
            *reinterpret_cast<uint32_t*>(Ah + soff) = __byte_perm(pa0[i], pa1[i], 0x5410);
            *reinterpret_cast<uint32_t*>(Al + soff) = __byte_perm(pa0[i], pa1[i], 0x7632);
            soff += 8 * STR * 2;
        }
        soff = (uint32_t)(r0 * STR + kloc) * 2;
#pragma unroll
        for (int i = 0; i < 8; i++) {
            *reinterpret_cast<uint32_t*>(Bh + soff) = __byte_perm(pb0[i], pb1[i], 0x5410);
            *reinterpret_cast<uint32_t*>(Bl + soff) = __byte_perm(pb0[i], pb1[i], 0x7632);
            soff += 8 * STR * 2;
        }
    };

    LDG_CHUNK(0); STS_CHUNK(0); __syncthreads();
    for (int c = 0; c < nchunk; c++) {
        if (c + 1 < nchunk) LDG_CHUNK(c + 1);
        const uint32_t base = uS + (uint32_t)(c & 1) * BUFE * 2;
        const uint32_t uAh = base;
        const uint32_t uAl = base + 128 * STR * 2;
        const uint32_t uBh = base + 256 * STR * 2;
        const uint32_t uBl = base + 320 * STR * 2;
#pragma unroll
        for (int ks = 0; ks < 4; ks++) {
            uint32_t ah[2][4], al[2][4], bh[2][4], bl[2][4];
#pragma unroll
            for (int mt = 0; mt < 2; mt++) {
                uint32_t off = (uint32_t)((m_base + mt * 16 + a_row_off) * STR + ks * 16 + a_kcol) * 2;
                ldsm4(ah[mt], uAh + off);
                ldsm4(al[mt], uAl + off);
            }
#pragma unroll
            for (int pr = 0; pr < 2; pr++) {
                uint32_t off = (uint32_t)((n_base + pr * 16 + b_row) * STR + ks * 16 + b_kcol) * 2;
                ldsm4(bh[pr], uBh + off);
                ldsm4(bl[pr], uBl + off);
            }
#pragma unroll
            for (int mt = 0; mt < 2; mt++) {
#pragma unroll
                for (int g = 0; g < 4; g++) {
                    const uint32_t* ph = &bh[g >> 1][(g & 1) * 2];
                    const uint32_t* pl = &bl[g >> 1][(g & 1) * 2];
                    mma_bf16(acc[mt][g], ah[mt], ph);
                    mma_bf16(acc[mt][g], ah[mt], pl);
                    mma_bf16(acc[mt][g], al[mt], ph);
                }
            }
        }
        if (c + 1 < nchunk) STS_CHUNK((c + 1) & 1);
        __syncthreads();
    }

    const int gid  = lane >> 2;
    const int tid4 = lane & 3;
    float* oF = outF ? outF + (size_t)z * M * N : nullptr;
#pragma unroll
    for (int mt = 0; mt < 2; mt++) {
#pragma unroll
        for (int g = 0; g < 4; g++) {
#pragma unroll
            for (int half = 0; half < 2; half++) {
                int m = bm + m_base + mt * 16 + gid + half * 8;
                if (m >= M) continue;
                int n0 = bn + n_base + g * 8 + tid4 * 2;
#pragma unroll
                for (int e = 0; e < 2; e++) {
                    int n = n0 + e;
                    float v = acc[mt][g][half * 2 + e];
                    if (bias) v += bias[n];
                    if (ACT == 1) v = gelu_f(v);
                    if (res) v += res[(size_t)m * N + n];
                    if (PACKOUT) outP[(size_t)m * N + n] = pack_hilo_bf16(v);
                    else         oF[(size_t)m * N + n] = v;
                }
            }
        }
    }
}

// ---------------- direct conv 7x7 stride 2 + ReLU (conv1, fp32) -------------
template<bool FROM_IMG, int IC, int OC, int IN_H, int IN_W, int OUT_H, int OUT_W,
         int TH, int PX, int NT>
__global__ __launch_bounds__(NT) void conv7s2_v2(const float* __restrict__ in,
                                                 const float* __restrict__ w,
                                                 float* __restrict__ out)
{
    constexpr int ITH  = (TH - 1) * 2 + 7;
    constexpr int SW   = ((IN_W + 1) & ~1);
    constexpr int CX   = (OUT_W + PX - 1) / PX;
    constexpr int OCG  = OC / 8;
    constexpr int ACTIVE = TH * CX * OCG;
    constexpr int WSTR = 72;
    __shared__ __align__(16) float s_w[49 * WSTR];
    __shared__ __align__(16) float s_in[ITH * SW + 16];

    const int patch = blockIdx.x;
    const int strip = blockIdx.y;
    const int t   = threadIdx.x;
    const int ocg = t % OCG;
    const int pg  = t / OCG;
    const int row = pg / CX;
    const int chunk = pg % CX;
    const int oc0 = ocg * 8;
    const int x0  = chunk * PX;
    const int oy  = strip * TH + row;
    const int iy0 = strip * TH * 2;

    size_t img_base = 0;
    if (FROM_IMG) {
        int b = patch >> 4, gh = (patch >> 2) & 3, gw = patch & 3;
        img_base = ((size_t)(b * 880 + gh * 220)) * 880 + gw * 220;
    }

    float acc[8][PX];
#pragma unroll
    for (int i = 0; i < 8; i++)
#pragma unroll
        for (int j = 0; j < PX; j++) acc[i][j] = 0.f;

    for (int ci = 0; ci < IC; ci++) {
        __syncthreads();
        for (int idx = t; idx < OC * 49; idx += NT) {
            int oc = idx / 49, k = idx - oc * 49;
            s_w[k * WSTR + oc] = w[((size_t)oc * IC + ci) * 49 + k];
        }
        if (FROM_IMG) {
            for (int idx = t; idx < ITH * IN_W; idx += NT) {
                int ly = idx / IN_W, lx = idx - ly * IN_W;
                int iy = iy0 + ly;
                s_in[ly * SW + lx] = (iy < IN_H) ? in[img_base + (size_t)iy * 880 + lx] : 0.f;
            }
        } else {
            const float* ic_ptr = in + ((size_t)patch * IC + ci) * IN_H * IN_W;
            for (int idx = t; idx < ITH * IN_W; idx += NT) {
                int ly = idx / IN_W, lx = idx - ly * IN_W;
                int iy = iy0 + ly;
                s_in[ly * SW + lx] = (iy < IN_H) ? ic_ptr[(size_t)iy * IN_W + lx] : 0.f;
            }
        }
        __syncthreads();

        if (t < ACTIVE) {
#pragma unroll 1
            for (int kh = 0; kh < 7; kh++) {
                const float* rbase = &s_in[(row * 2 + kh) * SW + x0 * 2];
#pragma unroll
                for (int kw = 0; kw < 7; kw += 2) {
                    float2 v2[PX];
#pragma unroll
                    for (int j = 0; j < PX; j++)
                        v2[j] = *(const float2*)(rbase + 2 * j + kw);
                    {
                        const int k = kh * 7 + kw;
                        const float4 wa = *(const float4*)&s_w[k * WSTR + oc0];
                        const float4 wb = *(const float4*)&s_w[k * WSTR + oc0 + 4];
                        const float wv[8] = {wa.x, wa.y, wa.z, wa.w, wb.x, wb.y, wb.z, wb.w};
#pragma unroll
                        for (int i = 0; i < 8; i++)
#pragma unroll
                            for (int j = 0; j < PX; j++)
                                acc[i][j] = fmaf(wv[i], v2[j].x, acc[i][j]);
                    }
                    if (kw + 1 < 7) {
                        const int k = kh * 7 + kw + 1;
                        const float4 wa = *(const float4*)&s_w[k * WSTR + oc0];
                        const float4 wb = *(const float4*)&s_w[k * WSTR + oc0 + 4];
                        const float wv[8] = {wa.x, wa.y, wa.z, wa.w, wb.x, wb.y, wb.z, wb.w};
#pragma unroll
                        for (int i = 0; i < 8; i++)
#pragma unroll
                            for (int j = 0; j < PX; j++)
                                acc[i][j] = fmaf(wv[i], v2[j].y, acc[i][j]);
                    }
                }
            }
        }
    }

    if (t < ACTIVE && oy < OUT_H) {
#pragma unroll
        for (int i = 0; i < 8; i++) {
            float* op = out + (((size_t)patch * OC + oc0 + i) * OUT_H + oy) * OUT_W;
#pragma unroll
            for (int j = 0; j < PX; j++) {
                int ox = x0 + j;
                if (ox < OUT_W) op[ox] = fmaxf(acc[i][j], 0.f);
            }
        }
    }
}

// ---------------- pool helpers ----------------------------------------------
__device__ __forceinline__ void win7x4(const float* tp, float* o)
{
    float p[9], q[7];
#pragma unroll
    for (int i = 0; i < 9; i++) p[i] = fmaxf(tp[i], tp[i + 1]);
#pragma unroll
    for (int i = 0; i < 7; i++) q[i] = fmaxf(p[i], p[i + 2]);
#pragma unroll
    for (int j = 0; j < 4; j++) o[j] = fmaxf(q[j], fmaxf(p[j + 4], tp[j + 6]));
}

template<int IN_HW, int NT>
__global__ __launch_bounds__(NT) void pool_plane_kernel(const float* __restrict__ in,
                                                        __half* __restrict__ out)
{
    constexpr int OUT = IN_HW - 4;
    constexpr int CW4 = (OUT + 3) / 4;
    __shared__ float s_raw[IN_HW * IN_HW];
    __shared__ float s_col[IN_HW * OUT];
    const size_t plane = blockIdx.x;
    const float* ip = in + plane * IN_HW * IN_HW;
    for (int idx = threadIdx.x; idx < IN_HW * IN_HW; idx += NT) s_raw[idx] = ip[idx];
    __syncthreads();
    for (int idx = threadIdx.x; idx < IN_HW * CW4; idx += NT) {
        int r = idx / CW4, ox0 = (idx - r * CW4) * 4;
        const float* rowp = &s_raw[r * IN_HW];
        float tp[10], o[4];
#pragma unroll
        for (int j = 0; j < 10; j++) {
            int xi = min(max(ox0 - 1 + j, 0), IN_HW - 1);
            tp[j] = rowp[xi];
        }
        win7x4(tp, o);
#pragma unroll
        for (int j = 0; j < 4; j++)
            if (ox0 + j < OUT) s_col[r * OUT + ox0 + j] = o[j];
    }
    __syncthreads();
    __half* op = out + plane * OUT * OUT;
    for (int idx = threadIdx.x; idx < CW4 * OUT; idx += NT) {
        int oy0 = (idx / OUT) * 4, ox = idx - (idx / OUT) * OUT;
        float tp[10], o[4];
#pragma unroll
        for (int j = 0; j < 10; j++) {
            int yi = min(max(oy0 - 1 + j, 0), IN_HW - 1);
            tp[j] = s_col[yi * OUT + ox];
        }
        win7x4(tp, o);
#pragma unroll
        for (int j = 0; j < 4; j++) {
            int oyy = oy0 + j;
            if (oyy < OUT) op[(size_t)oyy * OUT + ox] = __float2half_rn(o[j]);
        }
    }
}

template<int IN_H, int IN_W, int TH, int NT>
__global__ __launch_bounds__(NT) void pool_strip_kernel(const float* __restrict__ in,
                                                        __half* __restrict__ out)
{
    constexpr int OUT_W = IN_W - 4;
    constexpr int OUT_H = IN_H - 4;
    constexpr int MAXR  = TH + 6;
    constexpr int CW4   = (OUT_W + 3) / 4;
    constexpr int TH4   = (TH + 3) / 4;
    __shared__ float s_raw[MAXR * IN_W];
    __shared__ float s_col[MAXR * OUT_W];
    const size_t plane = blockIdx.x;
    const int r0    = blockIdx.y * TH;
    const int lbase = max(r0 - 1, 0);
    const int lend  = min(r0 + TH + 4, IN_H - 1);
    const int nrows = lend - lbase + 1;
    const float* ip = in + plane * IN_H * IN_W;
    for (int idx = threadIdx.x; idx < nrows * IN_W; idx += NT)
        s_raw[idx] = ip[(size_t)lbase * IN_W + idx];
    __syncthreads();
    for (int idx = threadIdx.x; idx < nrows * CW4; idx += NT) {
        int r = idx / CW4, ox0 = (idx - r * CW4) * 4;
        const float* rowp = &s_raw[r * IN_W];
        float tp[10], o[4];
#pragma unroll
        for (int j = 0; j < 10; j++) {
            int xi = min(max(ox0 - 1 + j, 0), IN_W - 1);
            tp[j] = rowp[xi];
        }
        win7x4(tp, o);
#pragma unroll
        for (int j = 0; j < 4; j++)
            if (ox0 + j < OUT_W) s_col[r * OUT_W + ox0 + j] = o[j];
    }
    __syncthreads();
    __half* op = out + plane * OUT_H * OUT_W;
    for (int idx = threadIdx.x; idx < TH4 * OUT_W; idx += NT) {
        int oy0 = r0 + (idx / OUT_W) * 4, ox = idx - (idx / OUT_W) * OUT_W;
        float tp[10], o[4];
#pragma unroll
        for (int j = 0; j < 10; j++) {
            int yi = min(max(oy0 - 1 + j, lbase), lend) - lbase;
            tp[j] = s_col[yi * OUT_W + ox];
        }
        win7x4(tp, o);
#pragma unroll
        for (int j = 0; j < 4; j++) {
            int oyy = oy0 + j;
            if (oyy < min(r0 + TH, OUT_H))
                op[(size_t)oyy * OUT_W + ox] = __float2half_rn(o[j]);
        }
    }
}

// ---------------- fp32 GEMM (head only) -------------------------------------
template<int ACT>
__global__ void gemm_kernel(const float* __restrict__ A, const float* __restrict__ Bm,
                            const float* __restrict__ bias, const float* __restrict__ res,
                            float* __restrict__ C, int M, int N, int K)
{
    __shared__ float sA[16][33];
    __shared__ float sB[16][64];
    const int bm = blockIdx.y * 32;
    const int bn = blockIdx.x * 64;
    const int t  = threadIdx.x;
    const int tm = (t >> 4) << 1;
    const int tn = (t & 15) << 2;
    float acc[2][4] = {{0, 0, 0, 0}, {0, 0, 0, 0}};
    for (int k0 = 0; k0 < K; k0 += 16) {
#pragma unroll
        for (int i = 0; i < 2; i++) {
            int e = t * 2 + i, m = e >> 4, kk = e & 15;
            sA[kk][m] = (bm + m < M) ? A[(size_t)(bm + m) * K + k0 + kk] : 0.f;
        }
#pragma unroll
        for (int i = 0; i < 4; i++) {
            int e = t * 4 + i, kk = e >> 6, n = e & 63;
            sB[kk][n] = (bn + n < N) ? Bm[(size_t)(k0 + kk) * N + bn + n] : 0.f;
        }
        __syncthreads();
#pragma unroll
        for (int kk = 0; kk < 16; kk++) {
            float a0 = sA[kk][tm], a1 = sA[kk][tm + 1];
            float b0 = sB[kk][tn + 0], b1 = sB[kk][tn + 1];
            float b2 = sB[kk][tn + 2], b3 = sB[kk][tn + 3];
            acc[0][0] = fmaf(a0, b0, acc[0][0]); acc[0][1] = fmaf(a0, b1, acc[0][1]);
            acc[0][2] = fmaf(a0, b2, acc[0][2]); acc[0][3] = fmaf(a0, b3, acc[0][3]);
            acc[1][0] = fmaf(a1, b0, acc[1][0]); acc[1][1] = fmaf(a1, b1, acc[1][1]);
            acc[1][2] = fmaf(a1, b2, acc[1][2]); acc[1][3] = fmaf(a1, b3, acc[1][3]);
        }
        __syncthreads();
    }
#pragma unroll
    for (int i = 0; i < 2; i++) {
        int m = bm + tm + i;
        if (m >= M) continue;
#pragma unroll
        for (int j = 0; j < 4; j++) {
            int n = bn + tn + j;
            if (n >= N) continue;
            float v = acc[i][j];
            if (bias) v += bias[n];
            if (ACT == 1) v = gelu_f(v);
            if (res) v += res[(size_t)m * N + n];
            C[(size_t)m * N + n] = v;
        }
    }
}

__global__ void flat_reduce_kernel(const float* __restrict__ part, const float* __restrict__ bias,
                                   float* __restrict__ outp, int M, int N, int S)
{
    int idx = blockIdx.x * blockDim.x + threadIdx.x;
    if (idx >= M * N) return;
    float v = bias[idx % N];
    for (int s = 0; s < S; s++) v += part[(size_t)s * M * N + idx];
    outp[idx] = v;
}

// ff2 split-K reduce: x = x + bias + sum(partials)
__global__ void resadd_reduce_kernel(const float* __restrict__ part, const float* __restrict__ bias,
                                     float* __restrict__ x, int M, int N, int S)
{
    int idx = blockIdx.x * blockDim.x + threadIdx.x;
    if (idx >= M * N) return;
    float v = x[idx] + bias[idx % N];
    for (int s = 0; s < S; s++) v += part[(size_t)s * M * N + idx];
    x[idx] = v;
}

// ---------------- LayerNorm over 512 ----------------------------------------
template<bool PACK, typename OT>
__global__ void ln_kernel(const float* __restrict__ x, const float* __restrict__ g,
                          const float* __restrict__ bb, OT* __restrict__ out,
                          int row_stride)
{
    const int row = blockIdx.x;
    const float* xr = x + (size_t)row * row_stride;
    OT* orow = out + (size_t)row * 512;
    const int t = threadIdx.x;
    float v[4], s = 0.f, s2 = 0.f;
#pragma unroll
    for (int i = 0; i < 4; i++) { v[i] = xr[i * 128 + t]; s += v[i]; s2 += v[i] * v[i]; }
#pragma unroll
    for (int o = 16; o; o >>= 1) {
        s  += __shfl_xor_sync(0xffffffffu, s,  o);
        s2 += __shfl_xor_sync(0xffffffffu, s2, o);
    }
    __shared__ float rs[4], rs2[4];
    if ((t & 31) == 0) { rs[t >> 5] = s; rs2[t >> 5] = s2; }
    __syncthreads();
    float tot  = rs[0] + rs[1] + rs[2] + rs[3];
    float tot2 = rs2[0] + rs2[1] + rs2[2] + rs2[3];
    float mean = tot  * (1.f / 512.f);
    float var  = tot2 * (1.f / 512.f) - mean * mean;
    float rstd = rsqrtf(var + 1e-5f);
#pragma unroll
    for (int i = 0; i < 4; i++) {
        int c = i * 128 + t;
        float ov = (v[i] - mean) * rstd * g[c] + bb[c];
        if (PACK) orow[c] = (OT)pack_hilo_bf16(ov);
        else      orow[c] = (OT)ov;
    }
}

// ---------------- token assembly --------------------------------------------
__global__ void embed_kernel(const float* __restrict__ cls_token, const float* __restrict__ pos_emb)
{
    int idx = blockIdx.x * blockDim.x + threadIdx.x;
    if (idx >= ROWS * 512) return;
    int row = idx >> 9, c = idx & 511;
    int b = row / 17, n = row - b * 17;
    float v = (n == 0) ? cls_token[c] : g_tok[(size_t)(b * 16 + n - 1) * 512 + c];
    g_x[idx] = v + pos_emb[n * 512 + c];
}

// ---------------- attention (writes packed bf16 output) ----------------------
__global__ void attn_kernel()
{
    const int bh = blockIdx.x;
    const int b = bh >> 3, h = bh & 7;
    __shared__ float q[17][64], kk[17][64], vv[17][64], s[17][17];
    const int t = threadIdx.x;
    for (int idx = t; idx < 17 * 64; idx += 128) {
        int n = idx >> 6, d = idx & 63;
        const float* base = g_qkv + (size_t)(b * 17 + n) * 1536 + h * 64 + d;
        q[n][d]  = base[0];
        kk[n][d] = base[512];
        vv[n][d] = base[1024];
    }
    __syncthreads();
    for (int idx = t; idx < 289; idx += 128) {
        int i = idx / 17, j = idx - i * 17;
        float a = 0.f;
#pragma unroll
        for (int d = 0; d < 64; d++) a = fmaf(q[i][d], kk[j][d], a);
        s[i][j] = a * 0.125f;
    }
    __syncthreads();
    if (t < 17) {
        float mx = -FLT_MAX;
        for (int j = 0; j < 17; j++) mx = fmaxf(mx, s[t][j]);
        float sum = 0.f;
        for (int j = 0; j < 17; j++) { float e = expf(s[t][j] - mx); s[t][j] = e; sum += e; }
        float inv = 1.f / sum;
        for (int j = 0; j < 17; j++) s[t][j] *= inv;
    }
    __syncthreads();
    for (int idx = t; idx < 17 * 64; idx += 128) {
        int n = idx >> 6, d = idx & 63;
        float a = 0.f;
#pragma unroll
        for (int j = 0; j < 17; j++) a = fmaf(s[n][j], vv[j][d], a);
        g_op[(size_t)(b * 17 + n) * 512 + h * 64 + d] = pack_hilo_bf16(a);
    }
}

// ---------------- host ------------------------------------------------------
extern "C" void kernel_launch(void* const* d_in, const int* in_sizes, int n_in,
                              void* d_out, int out_size)
{
    (void)in_sizes; (void)n_in; (void)out_size;
    const float* img     = (const float*)d_in[0];
    const float* conv1_w = (const float*)d_in[1];
    const float* conv2_w = (const float*)d_in[2];
    const float* conv3_w = (const float*)d_in[3];
    const float* flat_w  = (const float*)d_in[4];
    const float* flat_b  = (const float*)d_in[5];
    const float* cls_tok = (const float*)d_in[6];
    const float* pos_emb = (const float*)d_in[7];
    const float* ln1_g   = (const float*)d_in[8];
    const float* ln1_b   = (const float*)d_in[9];
    const float* qkv_w   = (const float*)d_in[10];
    const float* out_w   = (const float*)d_in[11];
    const float* out_b   = (const float*)d_in[12];
    const float* ln2_g   = (const float*)d_in[13];
    const float* ln2_b   = (const float*)d_in[14];
    const float* ff1_w   = (const float*)d_in[15];
    const float* ff1_b   = (const float*)d_in[16];
    const float* ff2_w   = (const float*)d_in[17];
    const float* ff2_b   = (const float*)d_in[18];
    const float* hln_g   = (const float*)d_in[19];
    const float* hln_b   = (const float*)d_in[20];
    const float* head_w  = (const float*)d_in[21];
    const float* head_b  = (const float*)d_in[22];
    float* out = (float*)d_out;

    float *p_c1, *p_c2, *p_c3;
    __half *p_p1, *p_p2, *p_p3;
    uint32_t *p_w2, *p_w3;
    uint32_t *p_qkvw, *p_outw, *p_ff1w, *p_ff2w, *p_flatw, *p_hp, *p_op, *p_ffp;
    float *p_fpart, *p_tok, *p_x, *p_qkv, *p_cls;
    cudaGetSymbolAddress((void**)&p_c1, g_c1);
    cudaGetSymbolAddress((void**)&p_p1, g_p1);
    cudaGetSymbolAddress((void**)&p_c2, g_c2);
    cudaGetSymbolAddress((void**)&p_p2, g_p2);
    cudaGetSymbolAddress((void**)&p_c3, g_c3);
    cudaGetSymbolAddress((void**)&p_p3, g_p3);
    cudaGetSymbolAddress((void**)&p_w2, g_w2);
    cudaGetSymbolAddress((void**)&p_w3, g_w3);
    cudaGetSymbolAddress((void**)&p_qkvw, g_qkvw);
    cudaGetSymbolAddress((void**)&p_outw, g_outw);
    cudaGetSymbolAddress((void**)&p_ff1w, g_ff1w);
    cudaGetSymbolAddress((void**)&p_ff2w, g_ff2w);
    cudaGetSymbolAddress((void**)&p_flatw, g_flatw);
    cudaGetSymbolAddress((void**)&p_hp,  g_hp);
    cudaGetSymbolAddress((void**)&p_op,  g_op);
    cudaGetSymbolAddress((void**)&p_ffp, g_ffp);
    cudaGetSymbolAddress((void**)&p_fpart, g_fpart);
    cudaGetSymbolAddress((void**)&p_tok, g_tok);
    cudaGetSymbolAddress((void**)&p_x,   g_x);
    cudaGetSymbolAddress((void**)&p_qkv, g_qkv);
    cudaGetSymbolAddress((void**)&p_cls, g_cls);

    const int F16_SMEM = 2 * 256 * 72 * 2;     // 73728  (double-buffered)
    const int BF_SMEM  = 2 * 384 * 72 * 2;     // 110592 (double-buffered)
    cudaFuncSetAttribute(conv_hmma_f16_kernel<32, 103, 103, 49, 1568, 25>,
                         cudaFuncAttributeMaxDynamicSharedMemorySize, F16_SMEM);
    cudaFuncSetAttribute(conv_hmma_f16_kernel<64, 45, 45, 20, 3136, 49>,
                         cudaFuncAttributeMaxDynamicSharedMemorySize, F16_SMEM);
    cudaFuncSetAttribute(hmma_gemm_f16_splitk,
                         cudaFuncAttributeMaxDynamicSharedMemorySize, F16_SMEM);
    cudaFuncSetAttribute(hmma_gemm_kernel<0, false>,
                         cudaFuncAttributeMaxDynamicSharedMemorySize, BF_SMEM);
    cudaFuncSetAttribute(hmma_gemm_kernel<1, true>,
                         cudaFuncAttributeMaxDynamicSharedMemorySize, BF_SMEM);

    dim3 tb(32, 8);
    // ---- launches ordered so ncu (-s 5 -c 1) captures conv2 (position 6) ----
    conv7s2_v2<true, 1, 32, 220, 220, 107, 107, 4, 8, 224>              // 1
        <<<dim3(NPATCH, 27), 224>>>(img, conv1_w, p_c1);
    pool_strip_kernel<107, 107, 26, 256><<<dim3(NPATCH * 32, 4), 256>>>(p_c1, p_p1);  // 2
    pack_weights_f16_kernel<<<(64 * 1568 + 255) / 256, 256>>>(conv2_w, p_w2, 64 * 1568);  // 3
    pack_weights_f16_kernel<<<(64 * 3136 + 255) / 256, 256>>>(conv3_w, p_w3, 64 * 3136);  // 4
    transpose_pack_kernel<true><<<dim3(16, 512, 1), tb>>>(flat_w, p_flatw, 16384, 512);   // 5
    conv_hmma_f16_kernel<32, 103, 103, 49, 1568, 25>                    // 6 <- ncu capture
        <<<dim3(19, NPATCH), 256, F16_SMEM>>>(p_p1, p_w2, p_c2);
    pool_plane_kernel<49, 256><<<NPATCH * 64, 256>>>(p_c2, p_p2);

    conv_hmma_f16_kernel<64, 45, 45, 20, 3136, 49>
        <<<dim3(4, NPATCH), 256, F16_SMEM>>>(p_p2, p_w3, p_c3);
    pool_plane_kernel<20, 128><<<NPATCH * 64, 128>>>(p_c3, p_p3);

    // ---- flatten linear: f16 split-K=16 ----
    hmma_gemm_f16_splitk<<<dim3(8, 2, 16), 256, F16_SMEM>>>(
        p_p3, p_flatw, p_fpart, NPATCH, 512, 16384, 1024);
    flat_reduce_kernel<<<(NPATCH * 512 + 255) / 256, 256>>>(p_fpart, flat_b, p_tok,
                                                            NPATCH, 512, 16);
    embed_kernel<<<(ROWS * 512 + 255) / 256, 256>>>(cls_tok, pos_emb);

    // ---- transformer weight transposition ----
    transpose_pack_kernel<false><<<dim3(48, 16, 6), tb>>>(qkv_w, p_qkvw, 512, 1536);
    transpose_pack_kernel<false><<<dim3(16, 16, 6), tb>>>(out_w, p_outw, 512, 512);
    transpose_pack_kernel<false><<<dim3(64, 16, 6), tb>>>(ff1_w, p_ff1w, 512, 2048);
    transpose_pack_kernel<false><<<dim3(16, 64, 6), tb>>>(ff2_w, p_ff2w, 2048, 512);

    // ---- transformer layers ----
    for (int L = 0; L < 6; L++) {
        ln_kernel<true, uint32_t><<<ROWS, 128>>>(p_x, ln1_g + L * 512, ln1_b + L * 512, p_hp, 512);
        hmma_gemm_kernel<0, false><<<dim3(24, 3, 1), 256, BF_SMEM>>>(
            p_hp, p_qkvw + (size_t)L * 1536 * 512, nullptr, nullptr, p_qkv, nullptr,
            ROWS, 1536, 512, 512);
        attn_kernel<<<128, 128>>>();
        hmma_gemm_kernel<0, false><<<dim3(8, 3, 1), 256, BF_SMEM>>>(
            p_op, p_outw + (size_t)L * 512 * 512, out_b + L * 512, p_x, p_x, nullptr,
            ROWS, 512, 512, 512);
        ln_kernel<true, uint32_t><<<ROWS, 128>>>(p_x, ln2_g + L * 512, ln2_b + L * 512, p_hp, 512);
        hmma_gemm_kernel<1, true><<<dim3(32, 3, 1), 256, BF_SMEM>>>(
            p_hp, p_ff1w + (size_t)L * 2048 * 512, ff1_b + L * 2048, nullptr, nullptr, p_ffp,
            ROWS, 2048, 512, 512);
        // ff2 via split-K=4 partials + residual reduce
        hmma_gemm_kernel<0, false><<<dim3(8, 3, 4), 256, BF_SMEM>>>(
            p_ffp, p_ff2w + (size_t)L * 512 * 2048, nullptr, nullptr, p_fpart, nullptr,
            ROWS, 512, 2048, 512);
        resadd_reduce_kernel<<<(ROWS * 512 + 255) / 256, 256>>>(p_fpart, ff2_b + L * 512,
                                                                p_x, ROWS, 512, 4);
    }

    // ---- head (small, fp32) ----
    ln_kernel<false, float><<<16, 128>>>(p_x, hln_g, hln_b, p_cls, 17 * 512);
    gemm_kernel<0><<<dim3((1000 + 63) / 64, 1), 256>>>(p_cls, head_w, head_b, nullptr, out, 16, 1000, 512);
}

// round 15
// speedup vs baseline: 1.1008x; 1.1008x over previous
#include <cuda_runtime.h>
#include <cuda_bf16.h>
#include <cuda_fp16.h>
#include <math.h>
#include <float.h>
#include <stdint.h>

// ============================================================================
// HybridViT forward, round 14: R12 base (best: 4295us) +
//   conv1 -> f16 HMMA implicit GEMM (single K-chunk, img gathered w/ cvt)
//   pool1 -> whole-plane fp16-smem kernel (no strip overlap redundancy)
// Everything else byte-identical to the passing R12 kernel.
// ============================================================================

#define NPATCH 256      // B*NP
#define ROWS   272      // B*(NP+1)

// ---------------- scratch (device globals; allocation-free rule) ------------
__device__ float    g_c1 [(size_t)NPATCH*32*107*107];
__device__ __half   g_p1 [(size_t)NPATCH*32*103*103];
__device__ float    g_c2 [(size_t)NPATCH*64*49*49];
__device__ __half   g_p2 [(size_t)NPATCH*64*45*45];
__device__ float    g_c3 [(size_t)NPATCH*64*20*20];
__device__ __half   g_p3 [(size_t)NPATCH*64*16*16];
__device__ uint32_t g_w1 [(size_t)64*64];               // conv1 w padded f16 hi|lo
__device__ uint32_t g_w2 [(size_t)64*1568];
__device__ uint32_t g_w3 [(size_t)64*3136];
__device__ uint32_t g_qkvw [(size_t)6*1536*512];
__device__ uint32_t g_outw [(size_t)6*512*512];
__device__ uint32_t g_ff1w [(size_t)6*2048*512];
__device__ uint32_t g_ff2w [(size_t)6*512*2048];
__device__ uint32_t g_flatw[(size_t)512*16384];
__device__ float    g_fpart[(size_t)16*NPATCH*512];
__device__ float    g_tok[(size_t)NPATCH*512];
__device__ float    g_x  [(size_t)ROWS*512];
__device__ uint32_t g_hp [(size_t)ROWS*512];
__device__ float    g_qkv[(size_t)ROWS*1536];
__device__ uint32_t g_op [(size_t)ROWS*512];
__device__ uint32_t g_ffp[(size_t)ROWS*2048];
__device__ float    g_cls[(size_t)16*512];

// ---------------- packing helpers -------------------------------------------
__device__ __forceinline__ uint32_t pack_hilo_bf16(float v)
{
    __nv_bfloat16 h = __float2bfloat16(v);
    __nv_bfloat16 l = __float2bfloat16(v - __bfloat162float(h));
    uint32_t hu = *reinterpret_cast<unsigned short*>(&h);
    uint32_t lu = *reinterpret_cast<unsigned short*>(&l);
    return hu | (lu << 16);
}
__device__ __forceinline__ uint32_t pack_hilo_f16(float v)
{
    __half h = __float2half_rn(v);
    __half l = __float2half_rn(v - __half2float(h));
    return (uint32_t)__half_as_ushort(h) | ((uint32_t)__half_as_ushort(l) << 16);
}

__global__ void pack_weights_f16_kernel(const float* __restrict__ in, uint32_t* __restrict__ out, int n)
{
    int idx = blockIdx.x * blockDim.x + threadIdx.x;
    if (idx < n) out[idx] = pack_hilo_f16(in[idx]);
}

// conv1 weights: [32,49] fp32 -> [64,64] padded packed f16 (zeros outside)
__global__ void pack_conv1_w_kernel(const float* __restrict__ in, uint32_t* __restrict__ out)
{
    int idx = blockIdx.x * blockDim.x + threadIdx.x;
    if (idx >= 64 * 64) return;
    int n = idx >> 6, k = idx & 63;
    float v = (n < 32 && k < 49) ? in[n * 49 + k] : 0.f;
    out[idx] = pack_hilo_f16(v);
}

template<bool F16>
__global__ void transpose_pack_kernel(const float* __restrict__ in, uint32_t* __restrict__ out,
                                      int K, int N)
{
    __shared__ float tile[32][33];
    const size_t base = (size_t)blockIdx.z * K * N;
    const int n0 = blockIdx.x * 32;
    const int k0 = blockIdx.y * 32;
#pragma unroll
    for (int j = 0; j < 4; j++) {
        int k = k0 + threadIdx.y + j * 8, n = n0 + threadIdx.x;
        if (k < K && n < N) tile[threadIdx.y + j * 8][threadIdx.x] = in[base + (size_t)k * N + n];
    }
    __syncthreads();
#pragma unroll
    for (int j = 0; j < 4; j++) {
        int n = n0 + threadIdx.y + j * 8, k = k0 + threadIdx.x;
        if (n < N && k < K) {
            float v = tile[threadIdx.x][threadIdx.y + j * 8];
            out[base + (size_t)n * K + k] = F16 ? pack_hilo_f16(v) : pack_hilo_bf16(v);
        }
    }
}

// ---------------- warp MMA helpers ------------------------------------------
__device__ __forceinline__ uint32_t smem_u32(const void* p)
{
    uint32_t a;
    asm("{ .reg .u64 t; cvta.to.shared.u64 t, %1; cvt.u32.u64 %0, t; }" : "=r"(a) : "l"(p));
    return a;
}
__device__ __forceinline__ void ldsm4(uint32_t* r, uint32_t addr)
{
    asm volatile("ldmatrix.sync.aligned.m8n8.x4.shared.b16 {%0,%1,%2,%3}, [%4];"
                 : "=r"(r[0]), "=r"(r[1]), "=r"(r[2]), "=r"(r[3]) : "r"(addr));
}
__device__ __forceinline__ void mma_bf16(float* d, const uint32_t* a, const uint32_t* b)
{
    asm volatile("mma.sync.aligned.m16n8k16.row.col.f32.bf16.bf16.f32 "
                 "{%0,%1,%2,%3}, {%4,%5,%6,%7}, {%8,%9}, {%0,%1,%2,%3};"
                 : "+f"(d[0]), "+f"(d[1]), "+f"(d[2]), "+f"(d[3])
                 : "r"(a[0]), "r"(a[1]), "r"(a[2]), "r"(a[3]), "r"(b[0]), "r"(b[1]));
}
__device__ __forceinline__ void mma_f16(float* d, const uint32_t* a, const uint32_t* b)
{
    asm volatile("mma.sync.aligned.m16n8k16.row.col.f32.f16.f16.f32 "
                 "{%0,%1,%2,%3}, {%4,%5,%6,%7}, {%8,%9}, {%0,%1,%2,%3};"
                 : "+f"(d[0]), "+f"(d[1]), "+f"(d[2]), "+f"(d[3])
                 : "r"(a[0]), "r"(a[1]), "r"(a[2]), "r"(a[3]), "r"(b[0]), "r"(b[1]));
}

__device__ __forceinline__ float gelu_f(float x)
{
    return 0.5f * x * (1.0f + erff(x * 0.7071067811865476f));
}

// ---------------- conv1 via f16 HMMA (single K-chunk of 64, K=49 real) ------
// A[pos][k] gathered from fp32 img (cvt to f16); W padded packed [64][64].
__global__ __launch_bounds__(256) void conv1_hmma_kernel(const float* __restrict__ img,
                                                         const uint32_t* __restrict__ w,
                                                         float* __restrict__ out)
{
    constexpr int OUT_HW = 107;
    constexpr int NPOS = OUT_HW * OUT_HW;   // 11449
    constexpr int STR  = 72;
    extern __shared__ __align__(16) char smem_raw[];
    __half* sA   = reinterpret_cast<__half*>(smem_raw);
    __half* sBhi = sA + 128 * STR;
    __half* sBlo = sBhi + 64 * STR;
    const uint32_t uA   = smem_u32(sA);
    const uint32_t uBhi = smem_u32(sBhi);
    const uint32_t uBlo = smem_u32(sBlo);

    const int t    = threadIdx.x;
    const int lane = t & 31;
    const int wid  = t >> 5;
    const int tile  = blockIdx.x;
    const int patch = blockIdx.y;
    const int m_base = (wid >> 1) * 32;
    const int n_base = (wid & 1) * 32;

    const int a_row_off = ((lane >> 3) & 1) * 8 + (lane & 7);
    const int a_kcol    = (lane >> 4) * 8;
    const int b_row     = (lane >> 4) * 8 + (lane & 7);
    const int b_kcol    = ((lane >> 3) & 1) * 8;

    const int b = patch >> 4, gh = (patch >> 2) & 3, gw = patch & 3;
    const size_t img_base = ((size_t)(b * 880 + gh * 220)) * 880 + gw * 220;

    const int kloc = (t & 31) * 2;
    const int pos0 = t >> 5;

    // ---- A tile gather (one chunk) ----
    {
        int koff[2]; bool kval[2];
#pragma unroll
        for (int e = 0; e < 2; e++) {
            int k = kloc + e;
            kval[e] = (k < 49);
            int kh = k / 7, kw = k - kh * 7;
            koff[e] = kh * 880 + kw;
        }
        int P  = tile * 128 + pos0;
        int oy = P / OUT_HW;
        int ox = P - oy * OUT_HW;
        uint32_t soff = (uint32_t)(pos0 * STR + kloc) * 2;
#pragma unroll
        for (int i = 0; i < 16; i++) {
            bool pv = (P < NPOS);
            size_t sbase = img_base + (size_t)(2 * oy) * 880 + 2 * ox;
            float v0 = (pv && kval[0]) ? img[sbase + koff[0]] : 0.f;
            float v1 = (pv && kval[1]) ? img[sbase + koff[1]] : 0.f;
            uint32_t h0 = (uint32_t)__half_as_ushort(__float2half_rn(v0));
            uint32_t h1 = (uint32_t)__half_as_ushort(__float2half_rn(v1));
            *reinterpret_cast<uint32_t*>(reinterpret_cast<char*>(sA) + soff) = h0 | (h1 << 16);
            P += 8; ox += 8;
            if (ox >= OUT_HW) { ox -= OUT_HW; oy++; }
            soff += 8 * STR * 2;
        }
    }
    // ---- B tile (padded 64x64 packed) ----
    {
        uint32_t soff = (uint32_t)(pos0 * STR + kloc) * 2;
#pragma unroll
        for (int i = 0; i < 8; i++) {
            int n = pos0 + i * 8;
            const uint32_t* wr = w + n * 64 + kloc;
            uint32_t w0 = wr[0], w1 = wr[1];
            *reinterpret_cast<uint32_t*>(reinterpret_cast<char*>(sBhi) + soff) = __byte_perm(w0, w1, 0x5410);
            *reinterpret_cast<uint32_t*>(reinterpret_cast<char*>(sBlo) + soff) = __byte_perm(w0, w1, 0x7632);
            soff += 8 * STR * 2;
        }
    }
    __syncthreads();

    float acc[2][4][4];
#pragma unroll
    for (int i = 0; i < 2; i++)
#pragma unroll
        for (int j = 0; j < 4; j++)
#pragma unroll
            for (int e = 0; e < 4; e++) acc[i][j][e] = 0.f;

#pragma unroll
    for (int ks = 0; ks < 4; ks++) {
        uint32_t av[2][4], bh[2][4], bl[2][4];
#pragma unroll
        for (int mt = 0; mt < 2; mt++) {
            uint32_t off = (uint32_t)((m_base + mt * 16 + a_row_off) * STR + ks * 16 + a_kcol) * 2;
            ldsm4(av[mt], uA + off);
        }
#pragma unroll
        for (int pr = 0; pr < 2; pr++) {
            uint32_t off = (uint32_t)((n_base + pr * 16 + b_row) * STR + ks * 16 + b_kcol) * 2;
            ldsm4(bh[pr], uBhi + off);
            ldsm4(bl[pr], uBlo + off);
        }
#pragma unroll
        for (int mt = 0; mt < 2; mt++) {
#pragma unroll
            for (int g = 0; g < 4; g++) {
                const uint32_t* ph = &bh[g >> 1][(g & 1) * 2];
                const uint32_t* pl = &bl[g >> 1][(g & 1) * 2];
                mma_f16(acc[mt][g], av[mt], ph);
                mma_f16(acc[mt][g], av[mt], pl);
            }
        }
    }

    if (n_base >= 32) return;   // oc in [32,64) are padding
    const int gid  = lane >> 2;
    const int tid4 = lane & 3;
    float* out_p = out + (size_t)patch * 32 * NPOS;
#pragma unroll
    for (int mt = 0; mt < 2; mt++) {
#pragma unroll
        for (int g = 0; g < 4; g++) {
            int pos_a = tile * 128 + m_base + mt * 16 + gid;
            int oc0   = n_base + g * 8 + tid4 * 2;
            if (pos_a < NPOS) {
                out_p[(size_t)oc0 * NPOS + pos_a]       = fmaxf(acc[mt][g][0], 0.f);
                out_p[(size_t)(oc0 + 1) * NPOS + pos_a] = fmaxf(acc[mt][g][1], 0.f);
            }
            if (pos_a + 8 < NPOS) {
                out_p[(size_t)oc0 * NPOS + pos_a + 8]       = fmaxf(acc[mt][g][2], 0.f);
                out_p[(size_t)(oc0 + 1) * NPOS + pos_a + 8] = fmaxf(acc[mt][g][3], 0.f);
            }
        }
    }
}

// ---------------- f16 HMMA implicit-GEMM conv7x7 s2 + ReLU (R12, proven) ----
template<int IC, int IN_H, int IN_W, int OUT_HW, int KTOT, int NCHUNK>
__global__ __launch_bounds__(256) void conv_hmma_f16_kernel(const __half* __restrict__ in,
                                                            const uint32_t* __restrict__ w,
                                                            float* __restrict__ out)
{
    constexpr int NPOS = OUT_HW * OUT_HW;
    constexpr int STR  = 72;
    extern __shared__ __align__(16) char smem_raw[];
    __half* sA   = reinterpret_cast<__half*>(smem_raw);
    __half* sBhi = sA + 128 * STR;
    __half* sBlo = sBhi + 64 * STR;
    const uint32_t uA   = smem_u32(sA);
    const uint32_t uBhi = smem_u32(sBhi);
    const uint32_t uBlo = smem_u32(sBlo);

    const int t    = threadIdx.x;
    const int lane = t & 31;
    const int wid  = t >> 5;
    const int tile  = blockIdx.x;
    const int patch = blockIdx.y;
    const int m_base = (wid >> 1) * 32;
    const int n_base = (wid & 1) * 32;

    const int a_row_off = ((lane >> 3) & 1) * 8 + (lane & 7);
    const int a_kcol    = (lane >> 4) * 8;
    const int b_row     = (lane >> 4) * 8 + (lane & 7);
    const int b_kcol    = ((lane >> 3) & 1) * 8;

    const __half* in_p = in + (size_t)patch * IC * IN_H * IN_W;
    const int kloc = (t & 31) * 2;
    const int pos0 = t >> 5;

    float acc[2][4][4];
#pragma unroll
    for (int i = 0; i < 2; i++)
#pragma unroll
        for (int j = 0; j < 4; j++)
#pragma unroll
            for (int e = 0; e < 4; e++) acc[i][j][e] = 0.f;

    for (int c = 0; c < NCHUNK; c++) {
        const int kbase = c * 64;
        int koff[2]; bool kval[2];
#pragma unroll
        for (int e = 0; e < 2; e++) {
            int k = kbase + kloc + e;
            kval[e] = (k < KTOT);
            int ci = k / 49, r = k - ci * 49;
            int kh = r / 7,  kw = r - kh * 7;
            koff[e] = (ci * IN_H + kh) * IN_W + kw;
        }
        {
            int P  = tile * 128 + pos0;
            int oy = P / OUT_HW;
            int ox = P - oy * OUT_HW;
            uint32_t soff = (uint32_t)(pos0 * STR + kloc) * 2;
#pragma unroll
            for (int i = 0; i < 16; i++) {
                bool pv = (P < NPOS);
                int sbase = (2 * oy) * IN_W + 2 * ox;
                uint32_t h0 = (pv && kval[0]) ? (uint32_t)__half_as_ushort(in_p[koff[0] + sbase]) : 0u;
                uint32_t h1 = (pv && kval[1]) ? (uint32_t)__half_as_ushort(in_p[koff[1] + sbase]) : 0u;
                *reinterpret_cast<uint32_t*>(reinterpret_cast<char*>(sA) + soff) = h0 | (h1 << 16);
                P += 8; ox += 8;
                if (ox >= OUT_HW) { ox -= OUT_HW; oy++; }
                soff += 8 * STR * 2;
            }
        }
        {
            uint32_t soff = (uint32_t)(pos0 * STR + kloc) * 2;
#pragma unroll
            for (int i = 0; i < 8; i++) {
                int n = pos0 + i * 8;
                const uint32_t* wrow = w + (size_t)n * KTOT + kbase + kloc;
                uint32_t w0 = kval[0] ? wrow[0] : 0u;
                uint32_t w1 = kval[1] ? wrow[1] : 0u;
                *reinterpret_cast<uint32_t*>(reinterpret_cast<char*>(sBhi) + soff) = __byte_perm(w0, w1, 0x5410);
                *reinterpret_cast<uint32_t*>(reinterpret_cast<char*>(sBlo) + soff) = __byte_perm(w0, w1, 0x7632);
                soff += 8 * STR * 2;
            }
        }
        __syncthreads();

#pragma unroll
        for (int ks = 0; ks < 4; ks++) {
            uint32_t av[2][4], bh[2][4], bl[2][4];
#pragma unroll
            for (int mt = 0; mt < 2; mt++) {
                uint32_t off = (uint32_t)((m_base + mt * 16 + a_row_off) * STR + ks * 16 + a_kcol) * 2;
                ldsm4(av[mt], uA + off);
            }
#pragma unroll
            for (int pr = 0; pr < 2; pr++) {
                uint32_t off = (uint32_t)((n_base + pr * 16 + b_row) * STR + ks * 16 + b_kcol) * 2;
                ldsm4(bh[pr], uBhi + off);
                ldsm4(bl[pr], uBlo + off);
            }
#pragma unroll
            for (int mt = 0; mt < 2; mt++) {
#pragma unroll
                for (int g = 0; g < 4; g++) {
                    const uint32_t* ph = &bh[g >> 1][(g & 1) * 2];
                    const uint32_t* pl = &bl[g >> 1][(g & 1) * 2];
                    mma_f16(acc[mt][g], av[mt], ph);
                    mma_f16(acc[mt][g], av[mt], pl);
                }
            }
        }
        __syncthreads();
    }

    const int gid  = lane >> 2;
    const int tid4 = lane & 3;
    float* out_p = out + (size_t)patch * 64 * NPOS;
#pragma unroll
    for (int mt = 0; mt < 2; mt++) {
#pragma unroll
        for (int g = 0; g < 4; g++) {
            int pos_a = tile * 128 + m_base + mt * 16 + gid;
            int oc0   = n_base + g * 8 + tid4 * 2;
            if (pos_a < NPOS) {
                out_p[(size_t)oc0 * NPOS + pos_a]       = fmaxf(acc[mt][g][0], 0.f);
                out_p[(size_t)(oc0 + 1) * NPOS + pos_a] = fmaxf(acc[mt][g][1], 0.f);
            }
            if (pos_a + 8 < NPOS) {
                out_p[(size_t)oc0 * NPOS + pos_a + 8]       = fmaxf(acc[mt][g][2], 0.f);
                out_p[(size_t)(oc0 + 1) * NPOS + pos_a + 8] = fmaxf(acc[mt][g][3], 0.f);
            }
        }
    }
}

// ---------------- f16 split-K GEMM (flat linear; R12, proven) ---------------
__global__ __launch_bounds__(256) void hmma_gemm_f16_splitk(const __half* __restrict__ A,
                                                            const uint32_t* __restrict__ B,
                                                            float* __restrict__ Cpart,
                                                            int M, int N, int K, int KC)
{
    constexpr int STR = 72;
    extern __shared__ __align__(16) char smem_raw[];
    __half* sA   = reinterpret_cast<__half*>(smem_raw);
    __half* sBhi = sA + 128 * STR;
    __half* sBlo = sBhi + 64 * STR;
    const uint32_t uA   = smem_u32(sA);
    const uint32_t uBhi = smem_u32(sBhi);
    const uint32_t uBlo = smem_u32(sBlo);

    const int t    = threadIdx.x;
    const int lane = t & 31;
    const int wid  = t >> 5;
    const int bn = blockIdx.x * 64;
    const int bm = blockIdx.y * 128;
    const int z  = blockIdx.z;
    const int m_base = (wid >> 1) * 32;
    const int n_base = (wid & 1) * 32;

    const int a_row_off = ((lane >> 3) & 1) * 8 + (lane & 7);
    const int a_kcol    = (lane >> 4) * 8;
    const int b_row     = (lane >> 4) * 8 + (lane & 7);
    const int b_kcol    = ((lane >> 3) & 1) * 8;

    const int kloc = (t & 31) * 2;
    const int r0   = t >> 5;
    const uint32_t* A32 = reinterpret_cast<const uint32_t*>(A);

    float acc[2][4][4];
#pragma unroll
    for (int i = 0; i < 2; i++)
#pragma unroll
        for (int j = 0; j < 4; j++)
#pragma unroll
            for (int e = 0; e < 4; e++) acc[i][j][e] = 0.f;

    const int nchunk = KC / 64;
    for (int c = 0; c < nchunk; c++) {
        const int kbase = z * KC + c * 64;
        {
            uint32_t soff = (uint32_t)(r0 * STR + kloc) * 2;
#pragma unroll
            for (int i = 0; i < 16; i++) {
                int m = bm + r0 + i * 8;
                uint32_t wv = (m < M) ? A32[((size_t)m * K + kbase + kloc) >> 1] : 0u;
                *reinterpret_cast<uint32_t*>(reinterpret_cast<char*>(sA) + soff) = wv;
                soff += 8 * STR * 2;
            }
        }
        {
            uint32_t soff = (uint32_t)(r0 * STR + kloc) * 2;
#pragma unroll
            for (int i = 0; i < 8; i++) {
                int n = bn + r0 + i * 8;
                const uint32_t* br = B + (size_t)n * K + kbase + kloc;
                uint32_t w0 = br[0], w1 = br[1];
                *reinterpret_cast<uint32_t*>(reinterpret_cast<char*>(sBhi) + soff) = __byte_perm(w0, w1, 0x5410);
                *reinterpret_cast<uint32_t*>(reinterpret_cast<char*>(sBlo) + soff) = __byte_perm(w0, w1, 0x7632);
                soff += 8 * STR * 2;
            }
        }
        __syncthreads();

#pragma unroll
        for (int ks = 0; ks < 4; ks++) {
            uint32_t av[2][4], bh[2][4], bl[2][4];
#pragma unroll
            for (int mt = 0; mt < 2; mt++) {
                uint32_t off = (uint32_t)((m_base + mt * 16 + a_row_off) * STR + ks * 16 + a_kcol) * 2;
                ldsm4(av[mt], uA + off);
            }
#pragma unroll
            for (int pr = 0; pr < 2; pr++) {
                uint32_t off = (uint32_t)((n_base + pr * 16 + b_row) * STR + ks * 16 + b_kcol) * 2;
                ldsm4(bh[pr], uBhi + off);
                ldsm4(bl[pr], uBlo + off);
            }
#pragma unroll
            for (int mt = 0; mt < 2; mt++) {
#pragma unroll
                for (int g = 0; g < 4; g++) {
                    const uint32_t* ph = &bh[g >> 1][(g & 1) * 2];
                    const uint32_t* pl = &bl[g >> 1][(g & 1) * 2];
                    mma_f16(acc[mt][g], av[mt], ph);
                    mma_f16(acc[mt][g], av[mt], pl);
                }
            }
        }
        __syncthreads();
    }

    const int gid  = lane >> 2;
    const int tid4 = lane & 3;
    float* oF = Cpart + (size_t)z * M * N;
#pragma unroll
    for (int mt = 0; mt < 2; mt++) {
#pragma unroll
        for (int g = 0; g < 4; g++) {
#pragma unroll
            for (int half = 0; half < 2; half++) {
                int m = bm + m_base + mt * 16 + gid + half * 8;
                if (m >= M) continue;
                int n0 = bn + n_base + g * 8 + tid4 * 2;
#pragma unroll
                for (int e = 0; e < 2; e++)
                    oF[(size_t)m * N + n0 + e] = acc[mt][g][half * 2 + e];
            }
        }
    }
}

// ---------------- bf16 3-term dense GEMM (transformer; R12, proven) ---------
template<int ACT, bool PACKOUT>
__global__ __launch_bounds__(256) void hmma_gemm_kernel(const uint32_t* __restrict__ A,
                                                        const uint32_t* __restrict__ B,
                                                        const float* __restrict__ bias,
                                                        const float* __restrict__ res,
                                                        float* __restrict__ outF,
                                                        uint32_t* __restrict__ outP,
                                                        int M, int N, int K, int KC)
{
    constexpr int STR = 72;
    extern __shared__ __align__(16) char smem_raw[];
    __nv_bfloat16* sAhi = reinterpret_cast<__nv_bfloat16*>(smem_raw);
    __nv_bfloat16* sAlo = sAhi + 128 * STR;
    __nv_bfloat16* sBhi = sAlo + 128 * STR;
    __nv_bfloat16* sBlo = sBhi + 64 * STR;
    const uint32_t uAhi = smem_u32(sAhi);
    const uint32_t uAlo = smem_u32(sAlo);
    const uint32_t uBhi = smem_u32(sBhi);
    const uint32_t uBlo = smem_u32(sBlo);

    const int t    = threadIdx.x;
    const int lane = t & 31;
    const int wid  = t >> 5;
    const int bn = blockIdx.x * 64;
    const int bm = blockIdx.y * 128;
    const int z  = blockIdx.z;
    const int m_base = (wid >> 1) * 32;
    const int n_base = (wid & 1) * 32;

    const int a_row_off = ((lane >> 3) & 1) * 8 + (lane & 7);
    const int a_kcol    = (lane >> 4) * 8;
    const int b_row     = (lane >> 4) * 8 + (lane & 7);
    const int b_kcol    = ((lane >> 3) & 1) * 8;

    const int kloc = (t & 31) * 2;
    const int r0   = t >> 5;

    float acc[2][4][4];
#pragma unroll
    for (int i = 0; i < 2; i++)
#pragma unroll
        for (int j = 0; j < 4; j++)
#pragma unroll
            for (int e = 0; e < 4; e++) acc[i][j][e] = 0.f;

    const int nchunk = KC / 64;
    for (int c = 0; c < nchunk; c++) {
        const int kbase = z * KC + c * 64;
        {
            uint32_t soff = (uint32_t)(r0 * STR + kloc) * 2;
#pragma unroll
            for (int i = 0; i < 16; i++) {
                int m = bm + r0 + i * 8;
                uint32_t w0 = 0u, w1 = 0u;
                if (m < M) {
                    const uint32_t* ar = A + (size_t)m * K + kbase + kloc;
                    w0 = ar[0]; w1 = ar[1];
                }
                *reinterpret_cast<uint32_t*>(reinterpret_cast<char*>(sAhi) + soff) = __byte_perm(w0, w1, 0x5410);
                *reinterpret_cast<uint32_t*>(reinterpret_cast<char*>(sAlo) + soff) = __byte_perm(w0, w1, 0x7632);
                soff += 8 * STR * 2;
            }
        }
        {
            uint32_t soff = (uint32_t)(r0 * STR + kloc) * 2;
#pragma unroll
            for (int i = 0; i < 8; i++) {
                int n = bn + r0 + i * 8;
                const uint32_t* br = B + (size_t)n * K + kbase + kloc;
                uint32_t w0 = br[0], w1 = br[1];
                *reinterpret_cast<uint32_t*>(reinterpret_cast<char*>(sBhi) + soff) = __byte_perm(w0, w1, 0x5410);
                *reinterpret_cast<uint32_t*>(reinterpret_cast<char*>(sBlo) + soff) = __byte_perm(w0, w1, 0x7632);
                soff += 8 * STR * 2;
            }
        }
        __syncthreads();

#pragma unroll
        for (int ks = 0; ks < 4; ks++) {
            uint32_t ah[2][4], al[2][4], bh[2][4], bl[2][4];
#pragma unroll
            for (int mt = 0; mt < 2; mt++) {
                uint32_t off = (uint32_t)((m_base + mt * 16 + a_row_off) * STR + ks * 16 + a_kcol) * 2;
                ldsm4(ah[mt], uAhi + off);
                ldsm4(al[mt], uAlo + off);
            }
#pragma unroll
            for (int pr = 0; pr < 2; pr++) {
                uint32_t off = (uint32_t)((n_base + pr * 16 + b_row) * STR + ks * 16 + b_kcol) * 2;
                ldsm4(bh[pr], uBhi + off);
                ldsm4(bl[pr], uBlo + off);
            }
#pragma unroll
            for (int mt = 0; mt < 2; mt++) {
#pragma unroll
                for (int g = 0; g < 4; g++) {
                    const uint32_t* ph = &bh[g >> 1][(g & 1) * 2];
                    const uint32_t* pl = &bl[g >> 1][(g & 1) * 2];
                    mma_bf16(acc[mt][g], ah[mt], ph);
                    mma_bf16(acc[mt][g], ah[mt], pl);
                    mma_bf16(acc[mt][g], al[mt], ph);
                }
            }
        }
        __syncthreads();
    }

    const int gid  = lane >> 2;
    const int tid4 = lane & 3;
    float* oF = outF ? outF + (size_t)z * M * N : nullptr;
#pragma unroll
    for (int mt = 0; mt < 2; mt++) {
#pragma unroll
        for (int g = 0; g < 4; g++) {
#pragma unroll
            for (int half = 0; half < 2; half++) {
                int m = bm + m_base + mt * 16 + gid + half * 8;
                if (m >= M) continue;
                int n0 = bn + n_base + g * 8 + tid4 * 2;
#pragma unroll
                for (int e = 0; e < 2; e++) {
                    int n = n0 + e;
                    float v = acc[mt][g][half * 2 + e];
                    if (bias) v += bias[n];
                    if (ACT == 1) v = gelu_f(v);
                    if (res) v += res[(size_t)m * N + n];
                    if (PACKOUT) outP[(size_t)m * N + n] = pack_hilo_bf16(v);
                    else         oF[(size_t)m * N + n] = v;
                }
            }
        }
    }
}

// ---------------- pool helpers ----------------------------------------------
__device__ __forceinline__ void win7x4(const float* tp, float* o)
{
    float p[9], q[7];
#pragma unroll
    for (int i = 0; i < 9; i++) p[i] = fmaxf(tp[i], tp[i + 1]);
#pragma unroll
    for (int i = 0; i < 7; i++) q[i] = fmaxf(p[i], p[i + 2]);
#pragma unroll
    for (int j = 0; j < 4; j++) o[j] = fmaxf(q[j], fmaxf(p[j + 4], tp[j + 6]));
}

// pool1: whole 107x107 plane per CTA, fp16 smem (exact: rn-cvt is monotone).
__global__ __launch_bounds__(256) void pool1_plane_kernel(const float* __restrict__ in,
                                                          __half* __restrict__ out)
{
    constexpr int IN_HW = 107, OUT = 103;
    constexpr int CW4 = (OUT + 3) / 4;    // 26
    __shared__ __half s_raw[IN_HW * IN_HW];
    __shared__ __half s_col[IN_HW * OUT];
    const size_t plane = blockIdx.x;
    const float* ip = in + plane * IN_HW * IN_HW;
    for (int idx = threadIdx.x; idx < IN_HW * IN_HW; idx += 256)
        s_raw[idx] = __float2half_rn(ip[idx]);
    __syncthreads();
    for (int idx = threadIdx.x; idx < IN_HW * CW4; idx += 256) {
        int r = idx / CW4, ox0 = (idx - r * CW4) * 4;
        const __half* rowp = &s_raw[r * IN_HW];
        float tp[10], o[4];
#pragma unroll
        for (int j = 0; j < 10; j++) {
            int xi = min(max(ox0 - 1 + j, 0), IN_HW - 1);
            tp[j] = __half2float(rowp[xi]);
        }
        win7x4(tp, o);
#pragma unroll
        for (int j = 0; j < 4; j++)
            if (ox0 + j < OUT) s_col[r * OUT + ox0 + j] = __float2half_rn(o[j]);
    }
    __syncthreads();
    __half* op = out + plane * OUT * OUT;
    for (int idx = threadIdx.x; idx < CW4 * OUT; idx += 256) {
        int oy0 = (idx / OUT) * 4, ox = idx - (idx / OUT) * OUT;
        float tp[10], o[4];
#pragma unroll
        for (int j = 0; j < 10; j++) {
            int yi = min(max(oy0 - 1 + j, 0), IN_HW - 1);
            tp[j] = __half2float(s_col[yi * OUT + ox]);
        }
        win7x4(tp, o);
#pragma unroll
        for (int j = 0; j < 4; j++) {
            int oyy = oy0 + j;
            if (oyy < OUT) op[(size_t)oyy * OUT + ox] = __float2half_rn(o[j]);
        }
    }
}

template<int IN_HW, int NT>
__global__ __launch_bounds__(NT) void pool_plane_kernel(const float* __restrict__ in,
                                                        __half* __restrict__ out)
{
    constexpr int OUT = IN_HW - 4;
    constexpr int CW4 = (OUT + 3) / 4;
    __shared__ float s_raw[IN_HW * IN_HW];
    __shared__ float s_col[IN_HW * OUT];
    const size_t plane = blockIdx.x;
    const float* ip = in + plane * IN_HW * IN_HW;
    for (int idx = threadIdx.x; idx < IN_HW * IN_HW; idx += NT) s_raw[idx] = ip[idx];
    __syncthreads();
    for (int idx = threadIdx.x; idx < IN_HW * CW4; idx += NT) {
        int r = idx / CW4, ox0 = (idx - r * CW4) * 4;
        const float* rowp = &s_raw[r * IN_HW];
        float tp[10], o[4];
#pragma unroll
        for (int j = 0; j < 10; j++) {
            int xi = min(max(ox0 - 1 + j, 0), IN_HW - 1);
            tp[j] = rowp[xi];
        }
        win7x4(tp, o);
#pragma unroll
        for (int j = 0; j < 4; j++)
            if (ox0 + j < OUT) s_col[r * OUT + ox0 + j] = o[j];
    }
    __syncthreads();
    __half* op = out + plane * OUT * OUT;
    for (int idx = threadIdx.x; idx < CW4 * OUT; idx += NT) {
        int oy0 = (idx / OUT) * 4, ox = idx - (idx / OUT) * OUT;
        float tp[10], o[4];
#pragma unroll
        for (int j = 0; j < 10; j++) {
            int yi = min(max(oy0 - 1 + j, 0), IN_HW - 1);
            tp[j] = s_col[yi * OUT + ox];
        }
        win7x4(tp, o);
#pragma unroll
        for (int j = 0; j < 4; j++) {
            int oyy = oy0 + j;
            if (oyy < OUT) op[(size_t)oyy * OUT + ox] = __float2half_rn(o[j]);
        }
    }
}

// ---------------- fp32 GEMM (head only) -------------------------------------
template<int ACT>
__global__ void gemm_kernel(const float* __restrict__ A, const float* __restrict__ Bm,
                            const float* __restrict__ bias, const float* __restrict__ res,
                            float* __restrict__ C, int M, int N, int K)
{
    __shared__ float sA[16][33];
    __shared__ float sB[16][64];
    const int bm = blockIdx.y * 32;
    const int bn = blockIdx.x * 64;
    const int t  = threadIdx.x;
    const int tm = (t >> 4) << 1;
    const int tn = (t & 15) << 2;
    float acc[2][4] = {{0, 0, 0, 0}, {0, 0, 0, 0}};
    for (int k0 = 0; k0 < K; k0 += 16) {
#pragma unroll
        for (int i = 0; i < 2; i++) {
            int e = t * 2 + i, m = e >> 4, kk = e & 15;
            sA[kk][m] = (bm + m < M) ? A[(size_t)(bm + m) * K + k0 + kk] : 0.f;
        }
#pragma unroll
        for (int i = 0; i < 4; i++) {
            int e = t * 4 + i, kk = e >> 6, n = e & 63;
            sB[kk][n] = (bn + n < N) ? Bm[(size_t)(k0 + kk) * N + bn + n] : 0.f;
        }
        __syncthreads();
#pragma unroll
        for (int kk = 0; kk < 16; kk++) {
            float a0 = sA[kk][tm], a1 = sA[kk][tm + 1];
            float b0 = sB[kk][tn + 0], b1 = sB[kk][tn + 1];
            float b2 = sB[kk][tn + 2], b3 = sB[kk][tn + 3];
            acc[0][0] = fmaf(a0, b0, acc[0][0]); acc[0][1] = fmaf(a0, b1, acc[0][1]);
            acc[0][2] = fmaf(a0, b2, acc[0][2]); acc[0][3] = fmaf(a0, b3, acc[0][3]);
            acc[1][0] = fmaf(a1, b0, acc[1][0]); acc[1][1] = fmaf(a1, b1, acc[1][1]);
            acc[1][2] = fmaf(a1, b2, acc[1][2]); acc[1][3] = fmaf(a1, b3, acc[1][3]);
        }
        __syncthreads();
    }
#pragma unroll
    for (int i = 0; i < 2; i++) {
        int m = bm + tm + i;
        if (m >= M) continue;
#pragma unroll
        for (int j = 0; j < 4; j++) {
            int n = bn + tn + j;
            if (n >= N) continue;
            float v = acc[i][j];
            if (bias) v += bias[n];
            if (ACT == 1) v = gelu_f(v);
            if (res) v += res[(size_t)m * N + n];
            C[(size_t)m * N + n] = v;
        }
    }
}

__global__ void flat_reduce_kernel(const float* __restrict__ part, const float* __restrict__ bias,
                                   float* __restrict__ outp, int M, int N, int S)
{
    int idx = blockIdx.x * blockDim.x + threadIdx.x;
    if (idx >= M * N) return;
    float v = bias[idx % N];
    for (int s = 0; s < S; s++) v += part[(size_t)s * M * N + idx];
    outp[idx] = v;
}

// ---------------- LayerNorm over 512 ----------------------------------------
template<bool PACK, typename OT>
__global__ void ln_kernel(const float* __restrict__ x, const float* __restrict__ g,
                          const float* __restrict__ bb, OT* __restrict__ out,
                          int row_stride)
{
    const int row = blockIdx.x;
    const float* xr = x + (size_t)row * row_stride;
    OT* orow = out + (size_t)row * 512;
    const int t = threadIdx.x;
    float v[4], s = 0.f, s2 = 0.f;
#pragma unroll
    for (int i = 0; i < 4; i++) { v[i] = xr[i * 128 + t]; s += v[i]; s2 += v[i] * v[i]; }
#pragma unroll
    for (int o = 16; o; o >>= 1) {
        s  += __shfl_xor_sync(0xffffffffu, s,  o);
        s2 += __shfl_xor_sync(0xffffffffu, s2, o);
    }
    __shared__ float rs[4], rs2[4];
    if ((t & 31) == 0) { rs[t >> 5] = s; rs2[t >> 5] = s2; }
    __syncthreads();
    float tot  = rs[0] + rs[1] + rs[2] + rs[3];
    float tot2 = rs2[0] + rs2[1] + rs2[2] + rs2[3];
    float mean = tot  * (1.f / 512.f);
    float var  = tot2 * (1.f / 512.f) - mean * mean;
    float rstd = rsqrtf(var + 1e-5f);
#pragma unroll
    for (int i = 0; i < 4; i++) {
        int c = i * 128 + t;
        float ov = (v[i] - mean) * rstd * g[c] + bb[c];
        if (PACK) orow[c] = (OT)pack_hilo_bf16(ov);
        else      orow[c] = (OT)ov;
    }
}

// ---------------- token assembly --------------------------------------------
__global__ void embed_kernel(const float* __restrict__ cls_token, const float* __restrict__ pos_emb)
{
    int idx = blockIdx.x * blockDim.x + threadIdx.x;
    if (idx >= ROWS * 512) return;
    int row = idx >> 9, c = idx & 511;
    int b = row / 17, n = row - b * 17;
    float v = (n == 0) ? cls_token[c] : g_tok[(size_t)(b * 16 + n - 1) * 512 + c];
    g_x[idx] = v + pos_emb[n * 512 + c];
}

// ---------------- attention (writes packed bf16 output) ----------------------
__global__ void attn_kernel()
{
    const int bh = blockIdx.x;
    const int b = bh >> 3, h = bh & 7;
    __shared__ float q[17][64], kk[17][64], vv[17][64], s[17][17];
    const int t = threadIdx.x;
    for (int idx = t; idx < 17 * 64; idx += 128) {
        int n = idx >> 6, d = idx & 63;
        const float* base = g_qkv + (size_t)(b * 17 + n) * 1536 + h * 64 + d;
        q[n][d]  = base[0];
        kk[n][d] = base[512];
        vv[n][d] = base[1024];
    }
    __syncthreads();
    for (int idx = t; idx < 289; idx += 128) {
        int i = idx / 17, j = idx - i * 17;
        float a = 0.f;
#pragma unroll
        for (int d = 0; d < 64; d++) a = fmaf(q[i][d], kk[j][d], a);
        s[i][j] = a * 0.125f;
    }
    __syncthreads();
    if (t < 17) {
        float mx = -FLT_MAX;
        for (int j = 0; j < 17; j++) mx = fmaxf(mx, s[t][j]);
        float sum = 0.f;
        for (int j = 0; j < 17; j++) { float e = expf(s[t][j] - mx); s[t][j] = e; sum += e; }
        float inv = 1.f / sum;
        for (int j = 0; j < 17; j++) s[t][j] *= inv;
    }
    __syncthreads();
    for (int idx = t; idx < 17 * 64; idx += 128) {
        int n = idx >> 6, d = idx & 63;
        float a = 0.f;
#pragma unroll
        for (int j = 0; j < 17; j++) a = fmaf(s[n][j], vv[j][d], a);
        g_op[(size_t)(b * 17 + n) * 512 + h * 64 + d] = pack_hilo_bf16(a);
    }
}

// ---------------- host ------------------------------------------------------
extern "C" void kernel_launch(void* const* d_in, const int* in_sizes, int n_in,
                              void* d_out, int out_size)
{
    (void)in_sizes; (void)n_in; (void)out_size;
    const float* img     = (const float*)d_in[0];
    const float* conv1_w = (const float*)d_in[1];
    const float* conv2_w = (const float*)d_in[2];
    const float* conv3_w = (const float*)d_in[3];
    const float* flat_w  = (const float*)d_in[4];
    const float* flat_b  = (const float*)d_in[5];
    const float* cls_tok = (const float*)d_in[6];
    const float* pos_emb = (const float*)d_in[7];
    const float* ln1_g   = (const float*)d_in[8];
    const float* ln1_b   = (const float*)d_in[9];
    const float* qkv_w   = (const float*)d_in[10];
    const float* out_w   = (const float*)d_in[11];
    const float* out_b   = (const float*)d_in[12];
    const float* ln2_g   = (const float*)d_in[13];
    const float* ln2_b   = (const float*)d_in[14];
    const float* ff1_w   = (const float*)d_in[15];
    const float* ff1_b   = (const float*)d_in[16];
    const float* ff2_w   = (const float*)d_in[17];
    const float* ff2_b   = (const float*)d_in[18];
    const float* hln_g   = (const float*)d_in[19];
    const float* hln_b   = (const float*)d_in[20];
    const float* head_w  = (const float*)d_in[21];
    const float* head_b  = (const float*)d_in[22];
    float* out = (float*)d_out;

    float *p_c1, *p_c2, *p_c3;
    __half *p_p1, *p_p2, *p_p3;
    uint32_t *p_w1, *p_w2, *p_w3;
    uint32_t *p_qkvw, *p_outw, *p_ff1w, *p_ff2w, *p_flatw, *p_hp, *p_op, *p_ffp;
    float *p_fpart, *p_tok, *p_x, *p_qkv, *p_cls;
    cudaGetSymbolAddress((void**)&p_c1, g_c1);
    cudaGetSymbolAddress((void**)&p_p1, g_p1);
    cudaGetSymbolAddress((void**)&p_c2, g_c2);
    cudaGetSymbolAddress((void**)&p_p2, g_p2);
    cudaGetSymbolAddress((void**)&p_c3, g_c3);
    cudaGetSymbolAddress((void**)&p_p3, g_p3);
    cudaGetSymbolAddress((void**)&p_w1, g_w1);
    cudaGetSymbolAddress((void**)&p_w2, g_w2);
    cudaGetSymbolAddress((void**)&p_w3, g_w3);
    cudaGetSymbolAddress((void**)&p_qkvw, g_qkvw);
    cudaGetSymbolAddress((void**)&p_outw, g_outw);
    cudaGetSymbolAddress((void**)&p_ff1w, g_ff1w);
    cudaGetSymbolAddress((void**)&p_ff2w, g_ff2w);
    cudaGetSymbolAddress((void**)&p_flatw, g_flatw);
    cudaGetSymbolAddress((void**)&p_hp,  g_hp);
    cudaGetSymbolAddress((void**)&p_op,  g_op);
    cudaGetSymbolAddress((void**)&p_ffp, g_ffp);
    cudaGetSymbolAddress((void**)&p_fpart, g_fpart);
    cudaGetSymbolAddress((void**)&p_tok, g_tok);
    cudaGetSymbolAddress((void**)&p_x,   g_x);
    cudaGetSymbolAddress((void**)&p_qkv, g_qkv);
    cudaGetSymbolAddress((void**)&p_cls, g_cls);

    const int F16_SMEM = (128 + 2 * 64) * 72 * 2;      // 36864 bytes
    const int BF_SMEM  = (2 * 128 + 2 * 64) * 72 * 2;  // 55296 bytes
    cudaFuncSetAttribute(conv1_hmma_kernel,
                         cudaFuncAttributeMaxDynamicSharedMemorySize, F16_SMEM);
    cudaFuncSetAttribute(conv_hmma_f16_kernel<32, 103, 103, 49, 1568, 25>,
                         cudaFuncAttributeMaxDynamicSharedMemorySize, F16_SMEM);
    cudaFuncSetAttribute(conv_hmma_f16_kernel<64, 45, 45, 20, 3136, 49>,
                         cudaFuncAttributeMaxDynamicSharedMemorySize, F16_SMEM);
    cudaFuncSetAttribute(hmma_gemm_f16_splitk,
                         cudaFuncAttributeMaxDynamicSharedMemorySize, F16_SMEM);
    cudaFuncSetAttribute(hmma_gemm_kernel<0, false>,
                         cudaFuncAttributeMaxDynamicSharedMemorySize, BF_SMEM);
    cudaFuncSetAttribute(hmma_gemm_kernel<1, true>,
                         cudaFuncAttributeMaxDynamicSharedMemorySize, BF_SMEM);

    dim3 tb(32, 8);
    // ---- weight packing ----
    pack_conv1_w_kernel<<<(64 * 64 + 255) / 256, 256>>>(conv1_w, p_w1);
    pack_weights_f16_kernel<<<(64 * 1568 + 255) / 256, 256>>>(conv2_w, p_w2, 64 * 1568);
    pack_weights_f16_kernel<<<(64 * 3136 + 255) / 256, 256>>>(conv3_w, p_w3, 64 * 3136);

    // ---- CNN ----
    conv1_hmma_kernel<<<dim3(90, NPATCH), 256, F16_SMEM>>>(img, p_w1, p_c1);
    pool1_plane_kernel<<<NPATCH * 32, 256>>>(p_c1, p_p1);

    conv_hmma_f16_kernel<32, 103, 103, 49, 1568, 25>
        <<<dim3(19, NPATCH), 256, F16_SMEM>>>(p_p1, p_w2, p_c2);
    pool_plane_kernel<49, 256><<<NPATCH * 64, 256>>>(p_c2, p_p2);

    conv_hmma_f16_kernel<64, 45, 45, 20, 3136, 49>
        <<<dim3(4, NPATCH), 256, F16_SMEM>>>(p_p2, p_w3, p_c3);
    pool_plane_kernel<20, 128><<<NPATCH * 64, 128>>>(p_c3, p_p3);

    // ---- flatten linear: f16 split-K=16 ----
    transpose_pack_kernel<true><<<dim3(16, 512, 1), tb>>>(flat_w, p_flatw, 16384, 512);
    hmma_gemm_f16_splitk<<<dim3(8, 2, 16), 256, F16_SMEM>>>(
        p_p3, p_flatw, p_fpart, NPATCH, 512, 16384, 1024);
    flat_reduce_kernel<<<(NPATCH * 512 + 255) / 256, 256>>>(p_fpart, flat_b, p_tok,
                                                            NPATCH, 512, 16);
    embed_kernel<<<(ROWS * 512 + 255) / 256, 256>>>(cls_tok, pos_emb);

    // ---- transformer weight transposition ----
    transpose_pack_kernel<false><<<dim3(48, 16, 6), tb>>>(qkv_w, p_qkvw, 512, 1536);
    transpose_pack_kernel<false><<<dim3(16, 16, 6), tb>>>(out_w, p_outw, 512, 512);
    transpose_pack_kernel<false><<<dim3(64, 16, 6), tb>>>(ff1_w, p_ff1w, 512, 2048);
    transpose_pack_kernel<false><<<dim3(16, 64, 6), tb>>>(ff2_w, p_ff2w, 2048, 512);

    // ---- transformer layers (R12 structure, proven) ----
    for (int L = 0; L < 6; L++) {
        ln_kernel<true, uint32_t><<<ROWS, 128>>>(p_x, ln1_g + L * 512, ln1_b + L * 512, p_hp, 512);
        hmma_gemm_kernel<0, false><<<dim3(24, 3, 1), 256, BF_SMEM>>>(
            p_hp, p_qkvw + (size_t)L * 1536 * 512, nullptr, nullptr, p_qkv, nullptr,
            ROWS, 1536, 512, 512);
        attn_kernel<<<128, 128>>>();
        hmma_gemm_kernel<0, false><<<dim3(8, 3, 1), 256, BF_SMEM>>>(
            p_op, p_outw + (size_t)L * 512 * 512, out_b + L * 512, p_x, p_x, nullptr,
            ROWS, 512, 512, 512);
        ln_kernel<true, uint32_t><<<ROWS, 128>>>(p_x, ln2_g + L * 512, ln2_b + L * 512, p_hp, 512);
        hmma_gemm_kernel<1, true><<<dim3(32, 3, 1), 256, BF_SMEM>>>(
            p_hp, p_ff1w + (size_t)L * 2048 * 512, ff1_b + L * 2048, nullptr, nullptr, p_ffp,
            ROWS, 2048, 512, 512);
        hmma_gemm_kernel<0, false><<<dim3(8, 3, 1), 256, BF_SMEM>>>(
            p_ffp, p_ff2w + (size_t)L * 512 * 2048, ff2_b + L * 512, p_x, p_x, nullptr,
            ROWS, 512, 2048, 2048);
    }

    // ---- head (small, fp32) ----
    ln_kernel<false, float><<<16, 128>>>(p_x, hln_g, hln_b, p_cls, 17 * 512);
    gemm_kernel<0><<<dim3((1000 + 63) / 64, 1), 256>>>(p_cls, head_w, head_b, nullptr, out, 16, 1000, 512);
}

// round 16
// speedup vs baseline: 1.4602x; 1.3265x over previous
#include <cuda_runtime.h>
#include <cuda_bf16.h>
#include <cuda_fp16.h>
#include <math.h>
#include <float.h>
#include <stdint.h>

// ============================================================================
// HybridViT forward, round 15: R14 base (4034us) with conv gathers remapped:
// lane indexes POSITION (coalesced LDG), A staged as [k][m] in smem,
// A-fragments via ldmatrix.trans. Attacks the measured L1=94.5% bottleneck.
// ============================================================================

#define NPATCH 256      // B*NP
#define ROWS   272      // B*(NP+1)

// ---------------- scratch (device globals; allocation-free rule) ------------
__device__ float    g_c1 [(size_t)NPATCH*32*107*107];
__device__ __half   g_p1 [(size_t)NPATCH*32*103*103];
__device__ float    g_c2 [(size_t)NPATCH*64*49*49];
__device__ __half   g_p2 [(size_t)NPATCH*64*45*45];
__device__ float    g_c3 [(size_t)NPATCH*64*20*20];
__device__ __half   g_p3 [(size_t)NPATCH*64*16*16];
__device__ uint32_t g_w1 [(size_t)64*64];
__device__ uint32_t g_w2 [(size_t)64*1568];
__device__ uint32_t g_w3 [(size_t)64*3136];
__device__ uint32_t g_qkvw [(size_t)6*1536*512];
__device__ uint32_t g_outw [(size_t)6*512*512];
__device__ uint32_t g_ff1w [(size_t)6*2048*512];
__device__ uint32_t g_ff2w [(size_t)6*512*2048];
__device__ uint32_t g_flatw[(size_t)512*16384];
__device__ float    g_fpart[(size_t)16*NPATCH*512];
__device__ float    g_tok[(size_t)NPATCH*512];
__device__ float    g_x  [(size_t)ROWS*512];
__device__ uint32_t g_hp [(size_t)ROWS*512];
__device__ float    g_qkv[(size_t)ROWS*1536];
__device__ uint32_t g_op [(size_t)ROWS*512];
__device__ uint32_t g_ffp[(size_t)ROWS*2048];
__device__ float    g_cls[(size_t)16*512];

// ---------------- packing helpers -------------------------------------------
__device__ __forceinline__ uint32_t pack_hilo_bf16(float v)
{
    __nv_bfloat16 h = __float2bfloat16(v);
    __nv_bfloat16 l = __float2bfloat16(v - __bfloat162float(h));
    uint32_t hu = *reinterpret_cast<unsigned short*>(&h);
    uint32_t lu = *reinterpret_cast<unsigned short*>(&l);
    return hu | (lu << 16);
}
__device__ __forceinline__ uint32_t pack_hilo_f16(float v)
{
    __half h = __float2half_rn(v);
    __half l = __float2half_rn(v - __half2float(h));
    return (uint32_t)__half_as_ushort(h) | ((uint32_t)__half_as_ushort(l) << 16);
}

__global__ void pack_weights_f16_kernel(const float* __restrict__ in, uint32_t* __restrict__ out, int n)
{
    int idx = blockIdx.x * blockDim.x + threadIdx.x;
    if (idx < n) out[idx] = pack_hilo_f16(in[idx]);
}

__global__ void pack_conv1_w_kernel(const float* __restrict__ in, uint32_t* __restrict__ out)
{
    int idx = blockIdx.x * blockDim.x + threadIdx.x;
    if (idx >= 64 * 64) return;
    int n = idx >> 6, k = idx & 63;
    float v = (n < 32 && k < 49) ? in[n * 49 + k] : 0.f;
    out[idx] = pack_hilo_f16(v);
}

template<bool F16>
__global__ void transpose_pack_kernel(const float* __restrict__ in, uint32_t* __restrict__ out,
                                      int K, int N)
{
    __shared__ float tile[32][33];
    const size_t base = (size_t)blockIdx.z * K * N;
    const int n0 = blockIdx.x * 32;
    const int k0 = blockIdx.y * 32;
#pragma unroll
    for (int j = 0; j < 4; j++) {
        int k = k0 + threadIdx.y + j * 8, n = n0 + threadIdx.x;
        if (k < K && n < N) tile[threadIdx.y + j * 8][threadIdx.x] = in[base + (size_t)k * N + n];
    }
    __syncthreads();
#pragma unroll
    for (int j = 0; j < 4; j++) {
        int n = n0 + threadIdx.y + j * 8, k = k0 + threadIdx.x;
        if (n < N && k < K) {
            float v = tile[threadIdx.x][threadIdx.y + j * 8];
            out[base + (size_t)n * K + k] = F16 ? pack_hilo_f16(v) : pack_hilo_bf16(v);
        }
    }
}

// ---------------- warp MMA helpers ------------------------------------------
__device__ __forceinline__ uint32_t smem_u32(const void* p)
{
    uint32_t a;
    asm("{ .reg .u64 t; cvta.to.shared.u64 t, %1; cvt.u32.u64 %0, t; }" : "=r"(a) : "l"(p));
    return a;
}
__device__ __forceinline__ void ldsm4(uint32_t* r, uint32_t addr)
{
    asm volatile("ldmatrix.sync.aligned.m8n8.x4.shared.b16 {%0,%1,%2,%3}, [%4];"
                 : "=r"(r[0]), "=r"(r[1]), "=r"(r[2]), "=r"(r[3]) : "r"(addr));
}
__device__ __forceinline__ void ldsm4_t(uint32_t* r, uint32_t addr)
{
    asm volatile("ldmatrix.sync.aligned.m8n8.x4.trans.shared.b16 {%0,%1,%2,%3}, [%4];"
                 : "=r"(r[0]), "=r"(r[1]), "=r"(r[2]), "=r"(r[3]) : "r"(addr));
}
__device__ __forceinline__ void mma_bf16(float* d, const uint32_t* a, const uint32_t* b)
{
    asm volatile("mma.sync.aligned.m16n8k16.row.col.f32.bf16.bf16.f32 "
                 "{%0,%1,%2,%3}, {%4,%5,%6,%7}, {%8,%9}, {%0,%1,%2,%3};"
                 : "+f"(d[0]), "+f"(d[1]), "+f"(d[2]), "+f"(d[3])
                 : "r"(a[0]), "r"(a[1]), "r"(a[2]), "r"(a[3]), "r"(b[0]), "r"(b[1]));
}
__device__ __forceinline__ void mma_f16(float* d, const uint32_t* a, const uint32_t* b)
{
    asm volatile("mma.sync.aligned.m16n8k16.row.col.f32.f16.f16.f32 "
                 "{%0,%1,%2,%3}, {%4,%5,%6,%7}, {%8,%9}, {%0,%1,%2,%3};"
                 : "+f"(d[0]), "+f"(d[1]), "+f"(d[2]), "+f"(d[3])
                 : "r"(a[0]), "r"(a[1]), "r"(a[2]), "r"(a[3]), "r"(b[0]), "r"(b[1]));
}

__device__ __forceinline__ float gelu_f(float x)
{
    return 0.5f * x * (1.0f + erff(x * 0.7071067811865476f));
}

// ---------------- conv common constants --------------------------------------
// A staged as S[k][m]: 64 k-rows x 128 m, LDA=136 halfs -> conflict-free
// trans-ldmatrix (row starts at banks 0,4,...,28).
#define CONV_LDA 136

// ---------------- conv1 via f16 HMMA, lane-position gather -------------------
__global__ __launch_bounds__(256) void conv1_hmma_kernel(const float* __restrict__ img,
                                                         const uint32_t* __restrict__ w,
                                                         float* __restrict__ out)
{
    constexpr int OUT_HW = 107;
    constexpr int NPOS = OUT_HW * OUT_HW;
    constexpr int STR  = 72;
    extern __shared__ __align__(16) char smem_raw[];
    __half* sA   = reinterpret_cast<__half*>(smem_raw);          // [64][CONV_LDA]
    __half* sBhi = sA + 64 * CONV_LDA;
    __half* sBlo = sBhi + 64 * STR;
    const uint32_t uA   = smem_u32(sA);
    const uint32_t uBhi = smem_u32(sBhi);
    const uint32_t uBlo = smem_u32(sBlo);

    const int t    = threadIdx.x;
    const int lane = t & 31;
    const int wid  = t >> 5;
    const int tile  = blockIdx.x;
    const int patch = blockIdx.y;
    const int m_base = (wid >> 1) * 32;
    const int n_base = (wid & 1) * 32;

    // A trans-frag addressing (S[k][m]): lanes 0-7 k0..7@m0, 8-15 @m0+8,
    // 16-23 k0+8@m0, 24-31 k0+8@m0+8.
    const int a_krow = (lane & 7) + ((lane >> 4) << 3);
    const int a_mcol = ((lane >> 3) & 1) << 3;
    const int b_row  = (lane >> 4) * 8 + (lane & 7);
    const int b_kcol = ((lane >> 3) & 1) * 8;

    const int b = patch >> 4, gh = (patch >> 2) & 3, gw = patch & 3;
    const size_t img_base = ((size_t)(b * 880 + gh * 220)) * 880 + gw * 220;

    const int kloc = (t & 31) * 2;   // B-gather (unchanged)
    const int pos0 = t >> 5;

    // positions for A gather: pos = lane + 32j (chunk-invariant)
    size_t sbase[4]; bool pvalid[4];
#pragma unroll
    for (int j = 0; j < 4; j++) {
        int P = tile * 128 + lane + 32 * j;
        pvalid[j] = (P < NPOS);
        int oy = P / OUT_HW, ox = P - oy * OUT_HW;
        sbase[j] = pvalid[j] ? img_base + (size_t)(2 * oy) * 880 + 2 * ox : img_base;
    }

    // ---- A gather: warp wid handles k-rows wid*8..wid*8+7 ----
    {
        int k = wid * 8;
        int kh = k / 7, kw = k - kh * 7;
#pragma unroll
        for (int i = 0; i < 8; i++) {
            bool kv = (k < 49);
            int koff = kh * 880 + kw;
            __half* dst = sA + (wid * 8 + i) * CONV_LDA + lane;
#pragma unroll
            for (int j = 0; j < 4; j++) {
                float v = (kv && pvalid[j]) ? img[sbase[j] + koff] : 0.f;
                dst[32 * j] = __float2half_rn(v);
            }
            k++; kw++;
            if (kw == 7) { kw = 0; kh++; }
        }
    }
    // ---- B tile (padded 64x64 packed) ----
    {
        uint32_t soff = (uint32_t)(pos0 * STR + kloc) * 2;
#pragma unroll
        for (int i = 0; i < 8; i++) {
            int n = pos0 + i * 8;
            const uint32_t* wr = w + n * 64 + kloc;
            uint32_t w0 = wr[0], w1 = wr[1];
            *reinterpret_cast<uint32_t*>(reinterpret_cast<char*>(sBhi) + soff) = __byte_perm(w0, w1, 0x5410);
            *reinterpret_cast<uint32_t*>(reinterpret_cast<char*>(sBlo) + soff) = __byte_perm(w0, w1, 0x7632);
            soff += 8 * STR * 2;
        }
    }
    __syncthreads();

    float acc[2][4][4];
#pragma unroll
    for (int i = 0; i < 2; i++)
#pragma unroll
        for (int j = 0; j < 4; j++)
#pragma unroll
            for (int e = 0; e < 4; e++) acc[i][j][e] = 0.f;

#pragma unroll
    for (int ks = 0; ks < 4; ks++) {
        uint32_t av[2][4], bh[2][4], bl[2][4];
#pragma unroll
        for (int mt = 0; mt < 2; mt++) {
            uint32_t off = (uint32_t)((ks * 16 + a_krow) * CONV_LDA + m_base + mt * 16 + a_mcol) * 2;
            ldsm4_t(av[mt], uA + off);
        }
#pragma unroll
        for (int pr = 0; pr < 2; pr++) {
            uint32_t off = (uint32_t)((n_base + pr * 16 + b_row) * STR + ks * 16 + b_kcol) * 2;
            ldsm4(bh[pr], uBhi + off);
            ldsm4(bl[pr], uBlo + off);
        }
#pragma unroll
        for (int mt = 0; mt < 2; mt++) {
#pragma unroll
            for (int g = 0; g < 4; g++) {
                const uint32_t* ph = &bh[g >> 1][(g & 1) * 2];
                const uint32_t* pl = &bl[g >> 1][(g & 1) * 2];
                mma_f16(acc[mt][g], av[mt], ph);
                mma_f16(acc[mt][g], av[mt], pl);
            }
        }
    }

    if (n_base >= 32) return;
    const int gid  = lane >> 2;
    const int tid4 = lane & 3;
    float* out_p = out + (size_t)patch * 32 * NPOS;
#pragma unroll
    for (int mt = 0; mt < 2; mt++) {
#pragma unroll
        for (int g = 0; g < 4; g++) {
            int pos_a = tile * 128 + m_base + mt * 16 + gid;
            int oc0   = n_base + g * 8 + tid4 * 2;
            if (pos_a < NPOS) {
                out_p[(size_t)oc0 * NPOS + pos_a]       = fmaxf(acc[mt][g][0], 0.f);
                out_p[(size_t)(oc0 + 1) * NPOS + pos_a] = fmaxf(acc[mt][g][1], 0.f);
            }
            if (pos_a + 8 < NPOS) {
                out_p[(size_t)oc0 * NPOS + pos_a + 8]       = fmaxf(acc[mt][g][2], 0.f);
                out_p[(size_t)(oc0 + 1) * NPOS + pos_a + 8] = fmaxf(acc[mt][g][3], 0.f);
            }
        }
    }
}

// ---------------- conv2/conv3: f16 HMMA, lane-position gather ---------------
template<int IC, int IN_H, int IN_W, int OUT_HW, int KTOT, int NCHUNK>
__global__ __launch_bounds__(256) void conv_hmma_f16_kernel(const __half* __restrict__ in,
                                                            const uint32_t* __restrict__ w,
                                                            float* __restrict__ out)
{
    constexpr int NPOS = OUT_HW * OUT_HW;
    constexpr int STR  = 72;
    extern __shared__ __align__(16) char smem_raw[];
    __half* sA   = reinterpret_cast<__half*>(smem_raw);          // [64][CONV_LDA]
    __half* sBhi = sA + 64 * CONV_LDA;
    __half* sBlo = sBhi + 64 * STR;
    const uint32_t uA   = smem_u32(sA);
    const uint32_t uBhi = smem_u32(sBhi);
    const uint32_t uBlo = smem_u32(sBlo);

    const int t    = threadIdx.x;
    const int lane = t & 31;
    const int wid  = t >> 5;
    const int tile  = blockIdx.x;
    const int patch = blockIdx.y;
    const int m_base = (wid >> 1) * 32;
    const int n_base = (wid & 1) * 32;

    const int a_krow = (lane & 7) + ((lane >> 4) << 3);
    const int a_mcol = ((lane >> 3) & 1) << 3;
    const int b_row  = (lane >> 4) * 8 + (lane & 7);
    const int b_kcol = ((lane >> 3) & 1) * 8;

    const __half* in_p = in + (size_t)patch * IC * IN_H * IN_W;
    const int kloc = (t & 31) * 2;
    const int pos0 = t >> 5;

    // positions (chunk-invariant)
    int sbase[4]; bool pvalid[4];
#pragma unroll
    for (int j = 0; j < 4; j++) {
        int P = tile * 128 + lane + 32 * j;
        pvalid[j] = (P < NPOS);
        int oy = P / OUT_HW, ox = P - oy * OUT_HW;
        sbase[j] = pvalid[j] ? (2 * oy) * IN_W + 2 * ox : 0;
    }

    float acc[2][4][4];
#pragma unroll
    for (int i = 0; i < 2; i++)
#pragma unroll
        for (int j = 0; j < 4; j++)
#pragma unroll
            for (int e = 0; e < 4; e++) acc[i][j][e] = 0.f;

    for (int c = 0; c < NCHUNK; c++) {
        const int kbase = c * 64;
        // ---- A gather: warp wid -> k-rows wid*8..+7, lane -> position ----
        {
            int k = kbase + wid * 8;
            int ci = k / 49, r = k - ci * 49;
            int kh = r / 7,  kw = r - kh * 7;
#pragma unroll
            for (int i = 0; i < 8; i++) {
                bool kv = (k < KTOT);
                int koff = (ci * IN_H + kh) * IN_W + kw;
                __half* dst = sA + (wid * 8 + i) * CONV_LDA + lane;
#pragma unroll
                for (int j = 0; j < 4; j++) {
                    __half v = (kv && pvalid[j]) ? in_p[koff + sbase[j]] : __ushort_as_half((unsigned short)0);
                    dst[32 * j] = v;
                }
                k++; kw++;
                if (kw == 7) { kw = 0; kh++; if (kh == 7) { kh = 0; ci++; } }
            }
        }
        // ---- B tile (unchanged mapping; already coalesced) ----
        {
            uint32_t soff = (uint32_t)(pos0 * STR + kloc) * 2;
#pragma unroll
            for (int i = 0; i < 8; i++) {
                int n = pos0 + i * 8;
                const uint32_t* wrow = w + (size_t)n * KTOT + kbase + kloc;
                bool kv0 = (kbase + kloc < KTOT);
                bool kv1 = (kbase + kloc + 1 < KTOT);
                uint32_t w0 = kv0 ? wrow[0] : 0u;
                uint32_t w1 = kv1 ? wrow[1] : 0u;
                *reinterpret_cast<uint32_t*>(reinterpret_cast<char*>(sBhi) + soff) = __byte_perm(w0, w1, 0x5410);
                *reinterpret_cast<uint32_t*>(reinterpret_cast<char*>(sBlo) + soff) = __byte_perm(w0, w1, 0x7632);
                soff += 8 * STR * 2;
            }
        }
        __syncthreads();

#pragma unroll
        for (int ks = 0; ks < 4; ks++) {
            uint32_t av[2][4], bh[2][4], bl[2][4];
#pragma unroll
            for (int mt = 0; mt < 2; mt++) {
                uint32_t off = (uint32_t)((ks * 16 + a_krow) * CONV_LDA + m_base + mt * 16 + a_mcol) * 2;
                ldsm4_t(av[mt], uA + off);
            }
#pragma unroll
            for (int pr = 0; pr < 2; pr++) {
                uint32_t off = (uint32_t)((n_base + pr * 16 + b_row) * STR + ks * 16 + b_kcol) * 2;
                ldsm4(bh[pr], uBhi + off);
                ldsm4(bl[pr], uBlo + off);
            }
#pragma unroll
            for (int mt = 0; mt < 2; mt++) {
#pragma unroll
                for (int g = 0; g < 4; g++) {
                    const uint32_t* ph = &bh[g >> 1][(g & 1) * 2];
                    const uint32_t* pl = &bl[g >> 1][(g & 1) * 2];
                    mma_f16(acc[mt][g], av[mt], ph);
                    mma_f16(acc[mt][g], av[mt], pl);
                }
            }
        }
        __syncthreads();
    }

    const int gid  = lane >> 2;
    const int tid4 = lane & 3;
    float* out_p = out + (size_t)patch * 64 * NPOS;
#pragma unroll
    for (int mt = 0; mt < 2; mt++) {
#pragma unroll
        for (int g = 0; g < 4; g++) {
            int pos_a = tile * 128 + m_base + mt * 16 + gid;
            int oc0   = n_base + g * 8 + tid4 * 2;
            if (pos_a < NPOS) {
                out_p[(size_t)oc0 * NPOS + pos_a]       = fmaxf(acc[mt][g][0], 0.f);
                out_p[(size_t)(oc0 + 1) * NPOS + pos_a] = fmaxf(acc[mt][g][1], 0.f);
            }
            if (pos_a + 8 < NPOS) {
                out_p[(size_t)oc0 * NPOS + pos_a + 8]       = fmaxf(acc[mt][g][2], 0.f);
                out_p[(size_t)(oc0 + 1) * NPOS + pos_a + 8] = fmaxf(acc[mt][g][3], 0.f);
            }
        }
    }
}

// ---------------- f16 split-K GEMM (flat linear; unchanged, proven) ---------
__global__ __launch_bounds__(256) void hmma_gemm_f16_splitk(const __half* __restrict__ A,
                                                            const uint32_t* __restrict__ B,
                                                            float* __restrict__ Cpart,
                                                            int M, int N, int K, int KC)
{
    constexpr int STR = 72;
    extern __shared__ __align__(16) char smem_raw[];
    __half* sA   = reinterpret_cast<__half*>(smem_raw);
    __half* sBhi = sA + 128 * STR;
    __half* sBlo = sBhi + 64 * STR;
    const uint32_t uA   = smem_u32(sA);
    const uint32_t uBhi = smem_u32(sBhi);
    const uint32_t uBlo = smem_u32(sBlo);

    const int t    = threadIdx.x;
    const int lane = t & 31;
    const int wid  = t >> 5;
    const int bn = blockIdx.x * 64;
    const int bm = blockIdx.y * 128;
    const int z  = blockIdx.z;
    const int m_base = (wid >> 1) * 32;
    const int n_base = (wid & 1) * 32;

    const int a_row_off = ((lane >> 3) & 1) * 8 + (lane & 7);
    const int a_kcol    = (lane >> 4) * 8;
    const int b_row     = (lane >> 4) * 8 + (lane & 7);
    const int b_kcol    = ((lane >> 3) & 1) * 8;

    const int kloc = (t & 31) * 2;
    const int r0   = t >> 5;
    const uint32_t* A32 = reinterpret_cast<const uint32_t*>(A);

    float acc[2][4][4];
#pragma unroll
    for (int i = 0; i < 2; i++)
#pragma unroll
        for (int j = 0; j < 4; j++)
#pragma unroll
            for (int e = 0; e < 4; e++) acc[i][j][e] = 0.f;

    const int nchunk = KC / 64;
    for (int c = 0; c < nchunk; c++) {
        const int kbase = z * KC + c * 64;
        {
            uint32_t soff = (uint32_t)(r0 * STR + kloc) * 2;
#pragma unroll
            for (int i = 0; i < 16; i++) {
                int m = bm + r0 + i * 8;
                uint32_t wv = (m < M) ? A32[((size_t)m * K + kbase + kloc) >> 1] : 0u;
                *reinterpret_cast<uint32_t*>(reinterpret_cast<char*>(sA) + soff) = wv;
                soff += 8 * STR * 2;
            }
        }
        {
            uint32_t soff = (uint32_t)(r0 * STR + kloc) * 2;
#pragma unroll
            for (int i = 0; i < 8; i++) {
                int n = bn + r0 + i * 8;
                const uint32_t* br = B + (size_t)n * K + kbase + kloc;
                uint32_t w0 = br[0], w1 = br[1];
                *reinterpret_cast<uint32_t*>(reinterpret_cast<char*>(sBhi) + soff) = __byte_perm(w0, w1, 0x5410);
                *reinterpret_cast<uint32_t*>(reinterpret_cast<char*>(sBlo) + soff) = __byte_perm(w0, w1, 0x7632);
                soff += 8 * STR * 2;
            }
        }
        __syncthreads();

#pragma unroll
        for (int ks = 0; ks < 4; ks++) {
            uint32_t av[2][4], bh[2][4], bl[2][4];
#pragma unroll
            for (int mt = 0; mt < 2; mt++) {
                uint32_t off = (uint32_t)((m_base + mt * 16 + a_row_off) * STR + ks * 16 + a_kcol) * 2;
                ldsm4(av[mt], uA + off);
            }
#pragma unroll
            for (int pr = 0; pr < 2; pr++) {
                uint32_t off = (uint32_t)((n_base + pr * 16 + b_row) * STR + ks * 16 + b_kcol) * 2;
                ldsm4(bh[pr], uBhi + off);
                ldsm4(bl[pr], uBlo + off);
            }
#pragma unroll
            for (int mt = 0; mt < 2; mt++) {
#pragma unroll
                for (int g = 0; g < 4; g++) {
                    const uint32_t* ph = &bh[g >> 1][(g & 1) * 2];
                    const uint32_t* pl = &bl[g >> 1][(g & 1) * 2];
                    mma_f16(acc[mt][g], av[mt], ph);
                    mma_f16(acc[mt][g], av[mt], pl);
                }
            }
        }
        __syncthreads();
    }

    const int gid  = lane >> 2;
    const int tid4 = lane & 3;
    float* oF = Cpart + (size_t)z * M * N;
#pragma unroll
    for (int mt = 0; mt < 2; mt++) {
#pragma unroll
        for (int g = 0; g < 4; g++) {
#pragma unroll
            for (int half = 0; half < 2; half++) {
                int m = bm + m_base + mt * 16 + gid + half * 8;
                if (m >= M) continue;
                int n0 = bn + n_base + g * 8 + tid4 * 2;
#pragma unroll
                for (int e = 0; e < 2; e++)
                    oF[(size_t)m * N + n0 + e] = acc[mt][g][half * 2 + e];
            }
        }
    }
}

// ---------------- bf16 3-term dense GEMM (transformer; unchanged) -----------
template<int ACT, bool PACKOUT>
__global__ __launch_bounds__(256) void hmma_gemm_kernel(const uint32_t* __restrict__ A,
                                                        const uint32_t* __restrict__ B,
                                                        const float* __restrict__ bias,
                                                        const float* __restrict__ res,
                                                        float* __restrict__ outF,
                                                        uint32_t* __restrict__ outP,
                                                        int M, int N, int K, int KC)
{
    constexpr int STR = 72;
    extern __shared__ __align__(16) char smem_raw[];
    __nv_bfloat16* sAhi = reinterpret_cast<__nv_bfloat16*>(smem_raw);
    __nv_bfloat16* sAlo = sAhi + 128 * STR;
    __nv_bfloat16* sBhi = sAlo + 128 * STR;
    __nv_bfloat16* sBlo = sBhi + 64 * STR;
    const uint32_t uAhi = smem_u32(sAhi);
    const uint32_t uAlo = smem_u32(sAlo);
    const uint32_t uBhi = smem_u32(sBhi);
    const uint32_t uBlo = smem_u32(sBlo);

    const int t    = threadIdx.x;
    const int lane = t & 31;
    const int wid  = t >> 5;
    const int bn = blockIdx.x * 64;
    const int bm = blockIdx.y * 128;
    const int z  = blockIdx.z;
    const int m_base = (wid >> 1) * 32;
    const int n_base = (wid & 1) * 32;

    const int a_row_off = ((lane >> 3) & 1) * 8 + (lane & 7);
    const int a_kcol    = (lane >> 4) * 8;
    const int b_row     = (lane >> 4) * 8 + (lane & 7);
    const int b_kcol    = ((lane >> 3) & 1) * 8;

    const int kloc = (t & 31) * 2;
    const int r0   = t >> 5;

    float acc[2][4][4];
#pragma unroll
    for (int i = 0; i < 2; i++)
#pragma unroll
        for (int j = 0; j < 4; j++)
#pragma unroll
            for (int e = 0; e < 4; e++) acc[i][j][e] = 0.f;

    const int nchunk = KC / 64;
    for (int c = 0; c < nchunk; c++) {
        const int kbase = z * KC + c * 64;
        {
            uint32_t soff = (uint32_t)(r0 * STR + kloc) * 2;
#pragma unroll
            for (int i = 0; i < 16; i++) {
                int m = bm + r0 + i * 8;
                uint32_t w0 = 0u, w1 = 0u;
                if (m < M) {
                    const uint32_t* ar = A + (size_t)m * K + kbase + kloc;
                    w0 = ar[0]; w1 = ar[1];
                }
                *reinterpret_cast<uint32_t*>(reinterpret_cast<char*>(sAhi) + soff) = __byte_perm(w0, w1, 0x5410);
                *reinterpret_cast<uint32_t*>(reinterpret_cast<char*>(sAlo) + soff) = __byte_perm(w0, w1, 0x7632);
                soff += 8 * STR * 2;
            }
        }
        {
            uint32_t soff = (uint32_t)(r0 * STR + kloc) * 2;
#pragma unroll
            for (int i = 0; i < 8; i++) {
                int n = bn + r0 + i * 8;
                const uint32_t* br = B + (size_t)n * K + kbase + kloc;
                uint32_t w0 = br[0], w1 = br[1];
                *reinterpret_cast<uint32_t*>(reinterpret_cast<char*>(sBhi) + soff) = __byte_perm(w0, w1, 0x5410);
                *reinterpret_cast<uint32_t*>(reinterpret_cast<char*>(sBlo) + soff) = __byte_perm(w0, w1, 0x7632);
                soff += 8 * STR * 2;
            }
        }
        __syncthreads();

#pragma unroll
        for (int ks = 0; ks < 4; ks++) {
            uint32_t ah[2][4], al[2][4], bh[2][4], bl[2][4];
#pragma unroll
            for (int mt = 0; mt < 2; mt++) {
                uint32_t off = (uint32_t)((m_base + mt * 16 + a_row_off) * STR + ks * 16 + a_kcol) * 2;
                ldsm4(ah[mt], uAhi + off);
                ldsm4(al[mt], uAlo + off);
            }
#pragma unroll
            for (int pr = 0; pr < 2; pr++) {
                uint32_t off = (uint32_t)((n_base + pr * 16 + b_row) * STR + ks * 16 + b_kcol) * 2;
                ldsm4(bh[pr], uBhi + off);
                ldsm4(bl[pr], uBlo + off);
            }
#pragma unroll
            for (int mt = 0; mt < 2; mt++) {
#pragma unroll
                for (int g = 0; g < 4; g++) {
                    const uint32_t* ph = &bh[g >> 1][(g & 1) * 2];
                    const uint32_t* pl = &bl[g >> 1][(g & 1) * 2];
                    mma_bf16(acc[mt][g], ah[mt], ph);
                    mma_bf16(acc[mt][g], ah[mt], pl);
                    mma_bf16(acc[mt][g], al[mt], ph);
                }
            }
        }
        __syncthreads();
    }

    const int gid  = lane >> 2;
    const int tid4 = lane & 3;
    float* oF = outF ? outF + (size_t)z * M * N : nullptr;
#pragma unroll
    for (int mt = 0; mt < 2; mt++) {
#pragma unroll
        for (int g = 0; g < 4; g++) {
#pragma unroll
            for (int half = 0; half < 2; half++) {
                int m = bm + m_base + mt * 16 + gid + half * 8;
                if (m >= M) continue;
                int n0 = bn + n_base + g * 8 + tid4 * 2;
#pragma unroll
                for (int e = 0; e < 2; e++) {
                    int n = n0 + e;
                    float v = acc[mt][g][half * 2 + e];
                    if (bias) v += bias[n];
                    if (ACT == 1) v = gelu_f(v);
                    if (res) v += res[(size_t)m * N + n];
                    if (PACKOUT) outP[(size_t)m * N + n] = pack_hilo_bf16(v);
                    else         oF[(size_t)m * N + n] = v;
                }
            }
        }
    }
}

// ---------------- pool helpers ----------------------------------------------
__device__ __forceinline__ void win7x4(const float* tp, float* o)
{
    float p[9], q[7];
#pragma unroll
    for (int i = 0; i < 9; i++) p[i] = fmaxf(tp[i], tp[i + 1]);
#pragma unroll
    for (int i = 0; i < 7; i++) q[i] = fmaxf(p[i], p[i + 2]);
#pragma unroll
    for (int j = 0; j < 4; j++) o[j] = fmaxf(q[j], fmaxf(p[j + 4], tp[j + 6]));
}

__global__ __launch_bounds__(256) void pool1_plane_kernel(const float* __restrict__ in,
                                                          __half* __restrict__ out)
{
    constexpr int IN_HW = 107, OUT = 103;
    constexpr int CW4 = (OUT + 3) / 4;
    __shared__ __half s_raw[IN_HW * IN_HW];
    __shared__ __half s_col[IN_HW * OUT];
    const size_t plane = blockIdx.x;
    const float* ip = in + plane * IN_HW * IN_HW;
    for (int idx = threadIdx.x; idx < IN_HW * IN_HW; idx += 256)
        s_raw[idx] = __float2half_rn(ip[idx]);
    __syncthreads();
    for (int idx = threadIdx.x; idx < IN_HW * CW4; idx += 256) {
        int r = idx / CW4, ox0 = (idx - r * CW4) * 4;
        const __half* rowp = &s_raw[r * IN_HW];
        float tp[10], o[4];
#pragma unroll
        for (int j = 0; j < 10; j++) {
            int xi = min(max(ox0 - 1 + j, 0), IN_HW - 1);
            tp[j] = __half2float(rowp[xi]);
        }
        win7x4(tp, o);
#pragma unroll
        for (int j = 0; j < 4; j++)
            if (ox0 + j < OUT) s_col[r * OUT + ox0 + j] = __float2half_rn(o[j]);
    }
    __syncthreads();
    __half* op = out + plane * OUT * OUT;
    for (int idx = threadIdx.x; idx < CW4 * OUT; idx += 256) {
        int oy0 = (idx / OUT) * 4, ox = idx - (idx / OUT) * OUT;
        float tp[10], o[4];
#pragma unroll
        for (int j = 0; j < 10; j++) {
            int yi = min(max(oy0 - 1 + j, 0), IN_HW - 1);
            tp[j] = __half2float(s_col[yi * OUT + ox]);
        }
        win7x4(tp, o);
#pragma unroll
        for (int j = 0; j < 4; j++) {
            int oyy = oy0 + j;
            if (oyy < OUT) op[(size_t)oyy * OUT + ox] = __float2half_rn(o[j]);
        }
    }
}

template<int IN_HW, int NT>
__global__ __launch_bounds__(NT) void pool_plane_kernel(const float* __restrict__ in,
                                                        __half* __restrict__ out)
{
    constexpr int OUT = IN_HW - 4;
    constexpr int CW4 = (OUT + 3) / 4;
    __shared__ float s_raw[IN_HW * IN_HW];
    __shared__ float s_col[IN_HW * OUT];
    const size_t plane = blockIdx.x;
    const float* ip = in + plane * IN_HW * IN_HW;
    for (int idx = threadIdx.x; idx < IN_HW * IN_HW; idx += NT) s_raw[idx] = ip[idx];
    __syncthreads();
    for (int idx = threadIdx.x; idx < IN_HW * CW4; idx += NT) {
        int r = idx / CW4, ox0 = (idx - r * CW4) * 4;
        const float* rowp = &s_raw[r * IN_HW];
        float tp[10], o[4];
#pragma unroll
        for (int j = 0; j < 10; j++) {
            int xi = min(max(ox0 - 1 + j, 0), IN_HW - 1);
            tp[j] = rowp[xi];
        }
        win7x4(tp, o);
#pragma unroll
        for (int j = 0; j < 4; j++)
            if (ox0 + j < OUT) s_col[r * OUT + ox0 + j] = o[j];
    }
    __syncthreads();
    __half* op = out + plane * OUT * OUT;
    for (int idx = threadIdx.x; idx < CW4 * OUT; idx += NT) {
        int oy0 = (idx / OUT) * 4, ox = idx - (idx / OUT) * OUT;
        float tp[10], o[4];
#pragma unroll
        for (int j = 0; j < 10; j++) {
            int yi = min(max(oy0 - 1 + j, 0), IN_HW - 1);
            tp[j] = s_col[yi * OUT + ox];
        }
        win7x4(tp, o);
#pragma unroll
        for (int j = 0; j < 4; j++) {
            int oyy = oy0 + j;
            if (oyy < OUT) op[(size_t)oyy * OUT + ox] = __float2half_rn(o[j]);
        }
    }
}

// ---------------- fp32 GEMM (head only) -------------------------------------
template<int ACT>
__global__ void gemm_kernel(const float* __restrict__ A, const float* __restrict__ Bm,
                            const float* __restrict__ bias, const float* __restrict__ res,
                            float* __restrict__ C, int M, int N, int K)
{
    __shared__ float sA[16][33];
    __shared__ float sB[16][64];
    const int bm = blockIdx.y * 32;
    const int bn = blockIdx.x * 64;
    const int t  = threadIdx.x;
    const int tm = (t >> 4) << 1;
    const int tn = (t & 15) << 2;
    float acc[2][4] = {{0, 0, 0, 0}, {0, 0, 0, 0}};
    for (int k0 = 0; k0 < K; k0 += 16) {
#pragma unroll
        for (int i = 0; i < 2; i++) {
            int e = t * 2 + i, m = e >> 4, kk = e & 15;
            sA[kk][m] = (bm + m < M) ? A[(size_t)(bm + m) * K + k0 + kk] : 0.f;
        }
#pragma unroll
        for (int i = 0; i < 4; i++) {
            int e = t * 4 + i, kk = e >> 6, n = e & 63;
            sB[kk][n] = (bn + n < N) ? Bm[(size_t)(k0 + kk) * N + bn + n] : 0.f;
        }
        __syncthreads();
#pragma unroll
        for (int kk = 0; kk < 16; kk++) {
            float a0 = sA[kk][tm], a1 = sA[kk][tm + 1];
            float b0 = sB[kk][tn + 0], b1 = sB[kk][tn + 1];
            float b2 = sB[kk][tn + 2], b3 = sB[kk][tn + 3];
            acc[0][0] = fmaf(a0, b0, acc[0][0]); acc[0][1] = fmaf(a0, b1, acc[0][1]);
            acc[0][2] = fmaf(a0, b2, acc[0][2]); acc[0][3] = fmaf(a0, b3, acc[0][3]);
            acc[1][0] = fmaf(a1, b0, acc[1][0]); acc[1][1] = fmaf(a1, b1, acc[1][1]);
            acc[1][2] = fmaf(a1, b2, acc[1][2]); acc[1][3] = fmaf(a1, b3, acc[1][3]);
        }
        __syncthreads();
    }
#pragma unroll
    for (int i = 0; i < 2; i++) {
        int m = bm + tm + i;
        if (m >= M) continue;
#pragma unroll
        for (int j = 0; j < 4; j++) {
            int n = bn + tn + j;
            if (n >= N) continue;
            float v = acc[i][j];
            if (bias) v += bias[n];
            if (ACT == 1) v = gelu_f(v);
            if (res) v += res[(size_t)m * N + n];
            C[(size_t)m * N + n] = v;
        }
    }
}

__global__ void flat_reduce_kernel(const float* __restrict__ part, const float* __restrict__ bias,
                                   float* __restrict__ outp, int M, int N, int S)
{
    int idx = blockIdx.x * blockDim.x + threadIdx.x;
    if (idx >= M * N) return;
    float v = bias[idx % N];
    for (int s = 0; s < S; s++) v += part[(size_t)s * M * N + idx];
    outp[idx] = v;
}

// ---------------- LayerNorm over 512 ----------------------------------------
template<bool PACK, typename OT>
__global__ void ln_kernel(const float* __restrict__ x, const float* __restrict__ g,
                          const float* __restrict__ bb, OT* __restrict__ out,
                          int row_stride)
{
    const int row = blockIdx.x;
    const float* xr = x + (size_t)row * row_stride;
    OT* orow = out + (size_t)row * 512;
    const int t = threadIdx.x;
    float v[4], s = 0.f, s2 = 0.f;
#pragma unroll
    for (int i = 0; i < 4; i++) { v[i] = xr[i * 128 + t]; s += v[i]; s2 += v[i] * v[i]; }
#pragma unroll
    for (int o = 16; o; o >>= 1) {
        s  += __shfl_xor_sync(0xffffffffu, s,  o);
        s2 += __shfl_xor_sync(0xffffffffu, s2, o);
    }
    __shared__ float rs[4], rs2[4];
    if ((t & 31) == 0) { rs[t >> 5] = s; rs2[t >> 5] = s2; }
    __syncthreads();
    float tot  = rs[0] + rs[1] + rs[2] + rs[3];
    float tot2 = rs2[0] + rs2[1] + rs2[2] + rs2[3];
    float mean = tot  * (1.f / 512.f);
    float var  = tot2 * (1.f / 512.f) - mean * mean;
    float rstd = rsqrtf(var + 1e-5f);
#pragma unroll
    for (int i = 0; i < 4; i++) {
        int c = i * 128 + t;
        float ov = (v[i] - mean) * rstd * g[c] + bb[c];
        if (PACK) orow[c] = (OT)pack_hilo_bf16(ov);
        else      orow[c] = (OT)ov;
    }
}

// ---------------- token assembly --------------------------------------------
__global__ void embed_kernel(const float* __restrict__ cls_token, const float* __restrict__ pos_emb)
{
    int idx = blockIdx.x * blockDim.x + threadIdx.x;
    if (idx >= ROWS * 512) return;
    int row = idx >> 9, c = idx & 511;
    int b = row / 17, n = row - b * 17;
    float v = (n == 0) ? cls_token[c] : g_tok[(size_t)(b * 16 + n - 1) * 512 + c];
    g_x[idx] = v + pos_emb[n * 512 + c];
}

// ---------------- attention (writes packed bf16 output) ----------------------
__global__ void attn_kernel()
{
    const int bh = blockIdx.x;
    const int b = bh >> 3, h = bh & 7;
    __shared__ float q[17][64], kk[17][64], vv[17][64], s[17][17];
    const int t = threadIdx.x;
    for (int idx = t; idx < 17 * 64; idx += 128) {
        int n = idx >> 6, d = idx & 63;
        const float* base = g_qkv + (size_t)(b * 17 + n) * 1536 + h * 64 + d;
        q[n][d]  = base[0];
        kk[n][d] = base[512];
        vv[n][d] = base[1024];
    }
    __syncthreads();
    for (int idx = t; idx < 289; idx += 128) {
        int i = idx / 17, j = idx - i * 17;
        float a = 0.f;
#pragma unroll
        for (int d = 0; d < 64; d++) a = fmaf(q[i][d], kk[j][d], a);
        s[i][j] = a * 0.125f;
    }
    __syncthreads();
    if (t < 17) {
        float mx = -FLT_MAX;
        for (int j = 0; j < 17; j++) mx = fmaxf(mx, s[t][j]);
        float sum = 0.f;
        for (int j = 0; j < 17; j++) { float e = expf(s[t][j] - mx); s[t][j] = e; sum += e; }
        float inv = 1.f / sum;
        for (int j = 0; j < 17; j++) s[t][j] *= inv;
    }
    __syncthreads();
    for (int idx = t; idx < 17 * 64; idx += 128) {
        int n = idx >> 6, d = idx & 63;
        float a = 0.f;
#pragma unroll
        for (int j = 0; j < 17; j++) a = fmaf(s[n][j], vv[j][d], a);
        g_op[(size_t)(b * 17 + n) * 512 + h * 64 + d] = pack_hilo_bf16(a);
    }
}

// ---------------- host ------------------------------------------------------
extern "C" void kernel_launch(void* const* d_in, const int* in_sizes, int n_in,
                              void* d_out, int out_size)
{
    (void)in_sizes; (void)n_in; (void)out_size;
    const float* img     = (const float*)d_in[0];
    const float* conv1_w = (const float*)d_in[1];
    const float* conv2_w = (const float*)d_in[2];
    const float* conv3_w = (const float*)d_in[3];
    const float* flat_w  = (const float*)d_in[4];
    const float* flat_b  = (const float*)d_in[5];
    const float* cls_tok = (const float*)d_in[6];
    const float* pos_emb = (const float*)d_in[7];
    const float* ln1_g   = (const float*)d_in[8];
    const float* ln1_b   = (const float*)d_in[9];
    const float* qkv_w   = (const float*)d_in[10];
    const float* out_w   = (const float*)d_in[11];
    const float* out_b   = (const float*)d_in[12];
    const float* ln2_g   = (const float*)d_in[13];
    const float* ln2_b   = (const float*)d_in[14];
    const float* ff1_w   = (const float*)d_in[15];
    const float* ff1_b   = (const float*)d_in[16];
    const float* ff2_w   = (const float*)d_in[17];
    const float* ff2_b   = (const float*)d_in[18];
    const float* hln_g   = (const float*)d_in[19];
    const float* hln_b   = (const float*)d_in[20];
    const float* head_w  = (const float*)d_in[21];
    const float* head_b  = (const float*)d_in[22];
    float* out = (float*)d_out;

    float *p_c1, *p_c2, *p_c3;
    __half *p_p1, *p_p2, *p_p3;
    uint32_t *p_w1, *p_w2, *p_w3;
    uint32_t *p_qkvw, *p_outw, *p_ff1w, *p_ff2w, *p_flatw, *p_hp, *p_op, *p_ffp;
    float *p_fpart, *p_tok, *p_x, *p_qkv, *p_cls;
    cudaGetSymbolAddress((void**)&p_c1, g_c1);
    cudaGetSymbolAddress((void**)&p_p1, g_p1);
    cudaGetSymbolAddress((void**)&p_c2, g_c2);
    cudaGetSymbolAddress((void**)&p_p2, g_p2);
    cudaGetSymbolAddress((void**)&p_c3, g_c3);
    cudaGetSymbolAddress((void**)&p_p3, g_p3);
    cudaGetSymbolAddress((void**)&p_w1, g_w1);
    cudaGetSymbolAddress((void**)&p_w2, g_w2);
    cudaGetSymbolAddress((void**)&p_w3, g_w3);
    cudaGetSymbolAddress((void**)&p_qkvw, g_qkvw);
    cudaGetSymbolAddress((void**)&p_outw, g_outw);
    cudaGetSymbolAddress((void**)&p_ff1w, g_ff1w);
    cudaGetSymbolAddress((void**)&p_ff2w, g_ff2w);
    cudaGetSymbolAddress((void**)&p_flatw, g_flatw);
    cudaGetSymbolAddress((void**)&p_hp,  g_hp);
    cudaGetSymbolAddress((void**)&p_op,  g_op);
    cudaGetSymbolAddress((void**)&p_ffp, g_ffp);
    cudaGetSymbolAddress((void**)&p_fpart, g_fpart);
    cudaGetSymbolAddress((void**)&p_tok, g_tok);
    cudaGetSymbolAddress((void**)&p_x,   g_x);
    cudaGetSymbolAddress((void**)&p_qkv, g_qkv);
    cudaGetSymbolAddress((void**)&p_cls, g_cls);

    // conv smem: A [64][136] + Bhi/Blo [64][72] each, halfs
    const int CONV_SMEM = (64 * CONV_LDA + 2 * 64 * 72) * 2;   // 35840
    const int F16_SMEM  = (128 + 2 * 64) * 72 * 2;             // 36864 (flat gemm)
    const int BF_SMEM   = (2 * 128 + 2 * 64) * 72 * 2;         // 55296
    cudaFuncSetAttribute(conv1_hmma_kernel,
                         cudaFuncAttributeMaxDynamicSharedMemorySize, CONV_SMEM);
    cudaFuncSetAttribute(conv_hmma_f16_kernel<32, 103, 103, 49, 1568, 25>,
                         cudaFuncAttributeMaxDynamicSharedMemorySize, CONV_SMEM);
    cudaFuncSetAttribute(conv_hmma_f16_kernel<64, 45, 45, 20, 3136, 49>,
                         cudaFuncAttributeMaxDynamicSharedMemorySize, CONV_SMEM);
    cudaFuncSetAttribute(hmma_gemm_f16_splitk,
                         cudaFuncAttributeMaxDynamicSharedMemorySize, F16_SMEM);
    cudaFuncSetAttribute(hmma_gemm_kernel<0, false>,
                         cudaFuncAttributeMaxDynamicSharedMemorySize, BF_SMEM);
    cudaFuncSetAttribute(hmma_gemm_kernel<1, true>,
                         cudaFuncAttributeMaxDynamicSharedMemorySize, BF_SMEM);

    dim3 tb(32, 8);
    // ---- weight packing ----
    pack_conv1_w_kernel<<<(64 * 64 + 255) / 256, 256>>>(conv1_w, p_w1);
    pack_weights_f16_kernel<<<(64 * 1568 + 255) / 256, 256>>>(conv2_w, p_w2, 64 * 1568);
    pack_weights_f16_kernel<<<(64 * 3136 + 255) / 256, 256>>>(conv3_w, p_w3, 64 * 3136);

    // ---- CNN ----
    conv1_hmma_kernel<<<dim3(90, NPATCH), 256, CONV_SMEM>>>(img, p_w1, p_c1);
    pool1_plane_kernel<<<NPATCH * 32, 256>>>(p_c1, p_p1);   // pos 5

    conv_hmma_f16_kernel<32, 103, 103, 49, 1568, 25>        // pos 6 <- ncu capture
        <<<dim3(19, NPATCH), 256, CONV_SMEM>>>(p_p1, p_w2, p_c2);
    pool_plane_kernel<49, 256><<<NPATCH * 64, 256>>>(p_c2, p_p2);

    conv_hmma_f16_kernel<64, 45, 45, 20, 3136, 49>
        <<<dim3(4, NPATCH), 256, CONV_SMEM>>>(p_p2, p_w3, p_c3);
    pool_plane_kernel<20, 128><<<NPATCH * 64, 128>>>(p_c3, p_p3);

    // ---- flatten linear: f16 split-K=16 ----
    transpose_pack_kernel<true><<<dim3(16, 512, 1), tb>>>(flat_w, p_flatw, 16384, 512);
    hmma_gemm_f16_splitk<<<dim3(8, 2, 16), 256, F16_SMEM>>>(
        p_p3, p_flatw, p_fpart, NPATCH, 512, 16384, 1024);
    flat_reduce_kernel<<<(NPATCH * 512 + 255) / 256, 256>>>(p_fpart, flat_b, p_tok,
                                                            NPATCH, 512, 16);
    embed_kernel<<<(ROWS * 512 + 255) / 256, 256>>>(cls_tok, pos_emb);

    // ---- transformer weight transposition ----
    transpose_pack_kernel<false><<<dim3(48, 16, 6), tb>>>(qkv_w, p_qkvw, 512, 1536);
    transpose_pack_kernel<false><<<dim3(16, 16, 6), tb>>>(out_w, p_outw, 512, 512);
    transpose_pack_kernel<false><<<dim3(64, 16, 6), tb>>>(ff1_w, p_ff1w, 512, 2048);
    transpose_pack_kernel<false><<<dim3(16, 64, 6), tb>>>(ff2_w, p_ff2w, 2048, 512);

    // ---- transformer layers (unchanged, proven) ----
    for (int L = 0; L < 6; L++) {
        ln_kernel<true, uint32_t><<<ROWS, 128>>>(p_x, ln1_g + L * 512, ln1_b + L * 512, p_hp, 512);
        hmma_gemm_kernel<0, false><<<dim3(24, 3, 1), 256, BF_SMEM>>>(
            p_hp, p_qkvw + (size_t)L * 1536 * 512, nullptr, nullptr, p_qkv, nullptr,
            ROWS, 1536, 512, 512);
        attn_kernel<<<128, 128>>>();
        hmma_gemm_kernel<0, false><<<dim3(8, 3, 1), 256, BF_SMEM>>>(
            p_op, p_outw + (size_t)L * 512 * 512, out_b + L * 512, p_x, p_x, nullptr,
            ROWS, 512, 512, 512);
        ln_kernel<true, uint32_t><<<ROWS, 128>>>(p_x, ln2_g + L * 512, ln2_b + L * 512, p_hp, 512);
        hmma_gemm_kernel<1, true><<<dim3(32, 3, 1), 256, BF_SMEM>>>(
            p_hp, p_ff1w + (size_t)L * 2048 * 512, ff1_b + L * 2048, nullptr, nullptr, p_ffp,
            ROWS, 2048, 512, 512);
        hmma_gemm_kernel<0, false><<<dim3(8, 3, 1), 256, BF_SMEM>>>(
            p_ffp, p_ff2w + (size_t)L * 512 * 2048, ff2_b + L * 512, p_x, p_x, nullptr,
            ROWS, 512, 2048, 2048);
    }

    // ---- head (small, fp32) ----
    ln_kernel<false, float><<<16, 128>>>(p_x, hln_g, hln_b, p_cls, 17 * 512);
    gemm_kernel<0><<<dim3((1000 + 63) / 64, 1), 256>>>(p_cls, head_w, head_b, nullptr, out, 16, 1000, 512);
}

// round 17
// speedup vs baseline: 1.5828x; 1.0839x over previous
#include <cuda_runtime.h>
#include <cuda_bf16.h>
#include <cuda_fp16.h>
#include <math.h>
#include <float.h>
#include <stdint.h>

// ============================================================================
// HybridViT forward, round 16: R15 base (3041us) +
//   img pre-converted to f16; conv gathers use paired u32 loads (one load
//   serves taps kw and kw+1) on even-stride-padded inputs; ff2 split-K=4.
// ============================================================================

#define NPATCH 256      // B*NP
#define ROWS   272      // B*(NP+1)
#define P1W 104         // pool1 out row stride (103 valid + 1 pad)
#define P2W 46          // pool2 out row stride (45 valid + 1 pad)

// ---------------- scratch (device globals; allocation-free rule) ------------
__device__ __half   g_imgh[(size_t)16*880*880];
__device__ float    g_c1 [(size_t)NPATCH*32*107*107];
__device__ __half   g_p1 [(size_t)NPATCH*32*103*P1W];
__device__ float    g_c2 [(size_t)NPATCH*64*49*49];
__device__ __half   g_p2 [(size_t)NPATCH*64*45*P2W];
__device__ float    g_c3 [(size_t)NPATCH*64*20*20];
__device__ __half   g_p3 [(size_t)NPATCH*64*16*16];
__device__ uint32_t g_w1 [(size_t)64*64];
__device__ uint32_t g_w2 [(size_t)64*1568];
__device__ uint32_t g_w3 [(size_t)64*3136];
__device__ uint32_t g_qkvw [(size_t)6*1536*512];
__device__ uint32_t g_outw [(size_t)6*512*512];
__device__ uint32_t g_ff1w [(size_t)6*2048*512];
__device__ uint32_t g_ff2w [(size_t)6*512*2048];
__device__ uint32_t g_flatw[(size_t)512*16384];
__device__ float    g_fpart[(size_t)16*NPATCH*512];
__device__ float    g_tok[(size_t)NPATCH*512];
__device__ float    g_x  [(size_t)ROWS*512];
__device__ uint32_t g_hp [(size_t)ROWS*512];
__device__ float    g_qkv[(size_t)ROWS*1536];
__device__ uint32_t g_op [(size_t)ROWS*512];
__device__ uint32_t g_ffp[(size_t)ROWS*2048];
__device__ float    g_cls[(size_t)16*512];

// ---------------- packing helpers -------------------------------------------
__device__ __forceinline__ uint32_t pack_hilo_bf16(float v)
{
    __nv_bfloat16 h = __float2bfloat16(v);
    __nv_bfloat16 l = __float2bfloat16(v - __bfloat162float(h));
    uint32_t hu = *reinterpret_cast<unsigned short*>(&h);
    uint32_t lu = *reinterpret_cast<unsigned short*>(&l);
    return hu | (lu << 16);
}
__device__ __forceinline__ uint32_t pack_hilo_f16(float v)
{
    __half h = __float2half_rn(v);
    __half l = __float2half_rn(v - __half2float(h));
    return (uint32_t)__half_as_ushort(h) | ((uint32_t)__half_as_ushort(l) << 16);
}

__global__ void img2h_kernel(const float* __restrict__ in, __half* __restrict__ out, int n)
{
    int idx = blockIdx.x * blockDim.x + threadIdx.x;
    if (idx < n) out[idx] = __float2half_rn(in[idx]);
}

__global__ void pack_weights_f16_kernel(const float* __restrict__ in, uint32_t* __restrict__ out, int n)
{
    int idx = blockIdx.x * blockDim.x + threadIdx.x;
    if (idx < n) out[idx] = pack_hilo_f16(in[idx]);
}

__global__ void pack_conv1_w_kernel(const float* __restrict__ in, uint32_t* __restrict__ out)
{
    int idx = blockIdx.x * blockDim.x + threadIdx.x;
    if (idx >= 64 * 64) return;
    int n = idx >> 6, k = idx & 63;
    float v = (n < 32 && k < 49) ? in[n * 49 + k] : 0.f;
    out[idx] = pack_hilo_f16(v);
}

template<bool F16>
__global__ void transpose_pack_kernel(const float* __restrict__ in, uint32_t* __restrict__ out,
                                      int K, int N)
{
    __shared__ float tile[32][33];
    const size_t base = (size_t)blockIdx.z * K * N;
    const int n0 = blockIdx.x * 32;
    const int k0 = blockIdx.y * 32;
#pragma unroll
    for (int j = 0; j < 4; j++) {
        int k = k0 + threadIdx.y + j * 8, n = n0 + threadIdx.x;
        if (k < K && n < N) tile[threadIdx.y + j * 8][threadIdx.x] = in[base + (size_t)k * N + n];
    }
    __syncthreads();
#pragma unroll
    for (int j = 0; j < 4; j++) {
        int n = n0 + threadIdx.y + j * 8, k = k0 + threadIdx.x;
        if (n < N && k < K) {
            float v = tile[threadIdx.x][threadIdx.y + j * 8];
            out[base + (size_t)n * K + k] = F16 ? pack_hilo_f16(v) : pack_hilo_bf16(v);
        }
    }
}

// ---------------- warp MMA helpers ------------------------------------------
__device__ __forceinline__ uint32_t smem_u32(const void* p)
{
    uint32_t a;
    asm("{ .reg .u64 t; cvta.to.shared.u64 t, %1; cvt.u32.u64 %0, t; }" : "=r"(a) : "l"(p));
    return a;
}
__device__ __forceinline__ void ldsm4(uint32_t* r, uint32_t addr)
{
    asm volatile("ldmatrix.sync.aligned.m8n8.x4.shared.b16 {%0,%1,%2,%3}, [%4];"
                 : "=r"(r[0]), "=r"(r[1]), "=r"(r[2]), "=r"(r[3]) : "r"(addr));
}
__device__ __forceinline__ void ldsm4_t(uint32_t* r, uint32_t addr)
{
    asm volatile("ldmatrix.sync.aligned.m8n8.x4.trans.shared.b16 {%0,%1,%2,%3}, [%4];"
                 : "=r"(r[0]), "=r"(r[1]), "=r"(r[2]), "=r"(r[3]) : "r"(addr));
}
__device__ __forceinline__ void mma_bf16(float* d, const uint32_t* a, const uint32_t* b)
{
    asm volatile("mma.sync.aligned.m16n8k16.row.col.f32.bf16.bf16.f32 "
                 "{%0,%1,%2,%3}, {%4,%5,%6,%7}, {%8,%9}, {%0,%1,%2,%3};"
                 : "+f"(d[0]), "+f"(d[1]), "+f"(d[2]), "+f"(d[3])
                 : "r"(a[0]), "r"(a[1]), "r"(a[2]), "r"(a[3]), "r"(b[0]), "r"(b[1]));
}
__device__ __forceinline__ void mma_f16(float* d, const uint32_t* a, const uint32_t* b)
{
    asm volatile("mma.sync.aligned.m16n8k16.row.col.f32.f16.f16.f32 "
                 "{%0,%1,%2,%3}, {%4,%5,%6,%7}, {%8,%9}, {%0,%1,%2,%3};"
                 : "+f"(d[0]), "+f"(d[1]), "+f"(d[2]), "+f"(d[3])
                 : "r"(a[0]), "r"(a[1]), "r"(a[2]), "r"(a[3]), "r"(b[0]), "r"(b[1]));
}

__device__ __forceinline__ float gelu_f(float x)
{
    return 0.5f * x * (1.0f + erff(x * 0.7071067811865476f));
}

#define CONV_LDA 136

// ---------------- conv1 via f16 HMMA, paired gather -------------------------
__global__ __launch_bounds__(256) void conv1_hmma_kernel(const __half* __restrict__ imgh,
                                                         const uint32_t* __restrict__ w,
                                                         float* __restrict__ out)
{
    constexpr int OUT_HW = 107;
    constexpr int NPOS = OUT_HW * OUT_HW;
    constexpr int STR  = 72;
    extern __shared__ __align__(16) char smem_raw[];
    __half* sA   = reinterpret_cast<__half*>(smem_raw);
    __half* sBhi = sA + 64 * CONV_LDA;
    __half* sBlo = sBhi + 64 * STR;
    const uint32_t uA   = smem_u32(sA);
    const uint32_t uBhi = smem_u32(sBhi);
    const uint32_t uBlo = smem_u32(sBlo);

    const int t    = threadIdx.x;
    const int lane = t & 31;
    const int wid  = t >> 5;
    const int tile  = blockIdx.x;
    const int patch = blockIdx.y;
    const int m_base = (wid >> 1) * 32;
    const int n_base = (wid & 1) * 32;

    const int a_krow = (lane & 7) + ((lane >> 4) << 3);
    const int a_mcol = ((lane >> 3) & 1) << 3;
    const int b_row  = (lane >> 4) * 8 + (lane & 7);
    const int b_kcol = ((lane >> 3) & 1) * 8;

    const int b = patch >> 4, gh = (patch >> 2) & 3, gw = patch & 3;
    const size_t img_base = ((size_t)(b * 880 + gh * 220)) * 880 + gw * 220;

    const int kloc = (t & 31) * 2;
    const int pos0 = t >> 5;

    size_t sbase[4]; bool pvalid[4];
#pragma unroll
    for (int j = 0; j < 4; j++) {
        int P = tile * 128 + lane + 32 * j;
        pvalid[j] = (P < NPOS);
        int oy = P / OUT_HW, ox = P - oy * OUT_HW;
        sbase[j] = pvalid[j] ? img_base + (size_t)(2 * oy) * 880 + 2 * ox : img_base;
    }

    // ---- A gather with paired u32 loads (kw even serves kw, kw+1) ----
    {
        int k = wid * 8;
        int kh = k / 7, kw = k - kh * 7;
        int i = 0;
        while (i < 8) {
            bool kv = (k < 49);
            bool pair = kv && ((kw & 1) == 0) && (kw < 6) && (i + 1 < 8) && (k + 1 < 49);
            __half* d0 = sA + (wid * 8 + i) * CONV_LDA + lane;
            int koff = kh * 880 + kw;
            if (pair) {
#pragma unroll
                for (int j = 0; j < 4; j++) {
                    uint32_t v = pvalid[j] ? *reinterpret_cast<const uint32_t*>(imgh + sbase[j] + koff) : 0u;
                    d0[32 * j]            = __ushort_as_half((unsigned short)(v & 0xFFFF));
                    d0[CONV_LDA + 32 * j] = __ushort_as_half((unsigned short)(v >> 16));
                }
                i += 2; k += 2; kw += 2;
            } else {
#pragma unroll
                for (int j = 0; j < 4; j++)
                    d0[32 * j] = (kv && pvalid[j]) ? imgh[sbase[j] + koff]
                                                   : __ushort_as_half((unsigned short)0);
                i++; k++; kw++;
            }
            if (kw >= 7) { kw = 0; kh++; }
        }
    }
    // ---- B tile ----
    {
        uint32_t soff = (uint32_t)(pos0 * STR + kloc) * 2;
#pragma unroll
        for (int i = 0; i < 8; i++) {
            int n = pos0 + i * 8;
            const uint32_t* wr = w + n * 64 + kloc;
            uint32_t w0 = wr[0], w1 = wr[1];
            *reinterpret_cast<uint32_t*>(reinterpret_cast<char*>(sBhi) + soff) = __byte_perm(w0, w1, 0x5410);
            *reinterpret_cast<uint32_t*>(reinterpret_cast<char*>(sBlo) + soff) = __byte_perm(w0, w1, 0x7632);
            soff += 8 * STR * 2;
        }
    }
    __syncthreads();

    float acc[2][4][4];
#pragma unroll
    for (int i = 0; i < 2; i++)
#pragma unroll
        for (int j = 0; j < 4; j++)
#pragma unroll
            for (int e = 0; e < 4; e++) acc[i][j][e] = 0.f;

#pragma unroll
    for (int ks = 0; ks < 4; ks++) {
        uint32_t av[2][4], bh[2][4], bl[2][4];
#pragma unroll
        for (int mt = 0; mt < 2; mt++) {
            uint32_t off = (uint32_t)((ks * 16 + a_krow) * CONV_LDA + m_base + mt * 16 + a_mcol) * 2;
            ldsm4_t(av[mt], uA + off);
        }
#pragma unroll
        for (int pr = 0; pr < 2; pr++) {
            uint32_t off = (uint32_t)((n_base + pr * 16 + b_row) * STR + ks * 16 + b_kcol) * 2;
            ldsm4(bh[pr], uBhi + off);
            ldsm4(bl[pr], uBlo + off);
        }
#pragma unroll
        for (int mt = 0; mt < 2; mt++) {
#pragma unroll
            for (int g = 0; g < 4; g++) {
                const uint32_t* ph = &bh[g >> 1][(g & 1) * 2];
                const uint32_t* pl = &bl[g >> 1][(g & 1) * 2];
                mma_f16(acc[mt][g], av[mt], ph);
                mma_f16(acc[mt][g], av[mt], pl);
            }
        }
    }

    if (n_base >= 32) return;
    const int gid  = lane >> 2;
    const int tid4 = lane & 3;
    float* out_p = out + (size_t)patch * 32 * NPOS;
#pragma unroll
    for (int mt = 0; mt < 2; mt++) {
#pragma unroll
        for (int g = 0; g < 4; g++) {
            int pos_a = tile * 128 + m_base + mt * 16 + gid;
            int oc0   = n_base + g * 8 + tid4 * 2;
            if (pos_a < NPOS) {
                out_p[(size_t)oc0 * NPOS + pos_a]       = fmaxf(acc[mt][g][0], 0.f);
                out_p[(size_t)(oc0 + 1) * NPOS + pos_a] = fmaxf(acc[mt][g][1], 0.f);
            }
            if (pos_a + 8 < NPOS) {
                out_p[(size_t)oc0 * NPOS + pos_a + 8]       = fmaxf(acc[mt][g][2], 0.f);
                out_p[(size_t)(oc0 + 1) * NPOS + pos_a + 8] = fmaxf(acc[mt][g][3], 0.f);
            }
        }
    }
}

// ---------------- conv2/conv3: paired gather (IN_W = even row stride) -------
template<int IC, int IN_H, int IN_W, int OUT_HW, int KTOT, int NCHUNK>
__global__ __launch_bounds__(256) void conv_hmma_f16_kernel(const __half* __restrict__ in,
                                                            const uint32_t* __restrict__ w,
                                                            float* __restrict__ out)
{
    constexpr int NPOS = OUT_HW * OUT_HW;
    constexpr int STR  = 72;
    extern __shared__ __align__(16) char smem_raw[];
    __half* sA   = reinterpret_cast<__half*>(smem_raw);
    __half* sBhi = sA + 64 * CONV_LDA;
    __half* sBlo = sBhi + 64 * STR;
    const uint32_t uA   = smem_u32(sA);
    const uint32_t uBhi = smem_u32(sBhi);
    const uint32_t uBlo = smem_u32(sBlo);

    const int t    = threadIdx.x;
    const int lane = t & 31;
    const int wid  = t >> 5;
    const int tile  = blockIdx.x;
    const int patch = blockIdx.y;
    const int m_base = (wid >> 1) * 32;
    const int n_base = (wid & 1) * 32;

    const int a_krow = (lane & 7) + ((lane >> 4) << 3);
    const int a_mcol = ((lane >> 3) & 1) << 3;
    const int b_row  = (lane >> 4) * 8 + (lane & 7);
    const int b_kcol = ((lane >> 3) & 1) * 8;

    const __half* in_p = in + (size_t)patch * IC * IN_H * IN_W;
    const int kloc = (t & 31) * 2;
    const int pos0 = t >> 5;

    int sbase[4]; bool pvalid[4];
#pragma unroll
    for (int j = 0; j < 4; j++) {
        int P = tile * 128 + lane + 32 * j;
        pvalid[j] = (P < NPOS);
        int oy = P / OUT_HW, ox = P - oy * OUT_HW;
        sbase[j] = pvalid[j] ? (2 * oy) * IN_W + 2 * ox : 0;
    }

    float acc[2][4][4];
#pragma unroll
    for (int i = 0; i < 2; i++)
#pragma unroll
        for (int j = 0; j < 4; j++)
#pragma unroll
            for (int e = 0; e < 4; e++) acc[i][j][e] = 0.f;

    for (int c = 0; c < NCHUNK; c++) {
        const int kbase = c * 64;
        // ---- A gather with paired u32 loads ----
        {
            int k = kbase + wid * 8;
            int ci = k / 49, r = k - ci * 49;
            int kh = r / 7,  kw = r - kh * 7;
            int i = 0;
            while (i < 8) {
                bool kv = (k < KTOT);
                bool pair = kv && ((kw & 1) == 0) && (kw < 6) && (i + 1 < 8) && (k + 1 < KTOT);
                __half* d0 = sA + (wid * 8 + i) * CONV_LDA + lane;
                int koff = (ci * IN_H + kh) * IN_W + kw;
                if (pair) {
#pragma unroll
                    for (int j = 0; j < 4; j++) {
                        uint32_t v = pvalid[j] ? *reinterpret_cast<const uint32_t*>(in_p + koff + sbase[j]) : 0u;
                        d0[32 * j]            = __ushort_as_half((unsigned short)(v & 0xFFFF));
                        d0[CONV_LDA + 32 * j] = __ushort_as_half((unsigned short)(v >> 16));
                    }
                    i += 2; k += 2; kw += 2;
                } else {
#pragma unroll
                    for (int j = 0; j < 4; j++)
                        d0[32 * j] = (kv && pvalid[j]) ? in_p[koff + sbase[j]]
                                                       : __ushort_as_half((unsigned short)0);
                    i++; k++; kw++;
                }
                if (kw >= 7) { kw = 0; kh++; if (kh == 7) { kh = 0; ci++; } }
            }
        }
        // ---- B tile ----
        {
            uint32_t soff = (uint32_t)(pos0 * STR + kloc) * 2;
#pragma unroll
            for (int i = 0; i < 8; i++) {
                int n = pos0 + i * 8;
                const uint32_t* wrow = w + (size_t)n * KTOT + kbase + kloc;
                bool kv0 = (kbase + kloc < KTOT);
                bool kv1 = (kbase + kloc + 1 < KTOT);
                uint32_t w0 = kv0 ? wrow[0] : 0u;
                uint32_t w1 = kv1 ? wrow[1] : 0u;
                *reinterpret_cast<uint32_t*>(reinterpret_cast<char*>(sBhi) + soff) = __byte_perm(w0, w1, 0x5410);
                *reinterpret_cast<uint32_t*>(reinterpret_cast<char*>(sBlo) + soff) = __byte_perm(w0, w1, 0x7632);
                soff += 8 * STR * 2;
            }
        }
        __syncthreads();

#pragma unroll
        for (int ks = 0; ks < 4; ks++) {
            uint32_t av[2][4], bh[2][4], bl[2][4];
#pragma unroll
            for (int mt = 0; mt < 2; mt++) {
                uint32_t off = (uint32_t)((ks * 16 + a_krow) * CONV_LDA + m_base + mt * 16 + a_mcol) * 2;
                ldsm4_t(av[mt], uA + off);
            }
#pragma unroll
            for (int pr = 0; pr < 2; pr++) {
                uint32_t off = (uint32_t)((n_base + pr * 16 + b_row) * STR + ks * 16 + b_kcol) * 2;
                ldsm4(bh[pr], uBhi + off);
                ldsm4(bl[pr], uBlo + off);
            }
#pragma unroll
            for (int mt = 0; mt < 2; mt++) {
#pragma unroll
                for (int g = 0; g < 4; g++) {
                    const uint32_t* ph = &bh[g >> 1][(g & 1) * 2];
                    const uint32_t* pl = &bl[g >> 1][(g & 1) * 2];
                    mma_f16(acc[mt][g], av[mt], ph);
                    mma_f16(acc[mt][g], av[mt], pl);
                }
            }
        }
        __syncthreads();
    }

    const int gid  = lane >> 2;
    const int tid4 = lane & 3;
    float* out_p = out + (size_t)patch * 64 * NPOS;
#pragma unroll
    for (int mt = 0; mt < 2; mt++) {
#pragma unroll
        for (int g = 0; g < 4; g++) {
            int pos_a = tile * 128 + m_base + mt * 16 + gid;
            int oc0   = n_base + g * 8 + tid4 * 2;
            if (pos_a < NPOS) {
                out_p[(size_t)oc0 * NPOS + pos_a]       = fmaxf(acc[mt][g][0], 0.f);
                out_p[(size_t)(oc0 + 1) * NPOS + pos_a] = fmaxf(acc[mt][g][1], 0.f);
            }
            if (pos_a + 8 < NPOS) {
                out_p[(size_t)oc0 * NPOS + pos_a + 8]       = fmaxf(acc[mt][g][2], 0.f);
                out_p[(size_t)(oc0 + 1) * NPOS + pos_a + 8] = fmaxf(acc[mt][g][3], 0.f);
            }
        }
    }
}

// ---------------- f16 split-K GEMM (flat linear; unchanged) -----------------
__global__ __launch_bounds__(256) void hmma_gemm_f16_splitk(const __half* __restrict__ A,
                                                            const uint32_t* __restrict__ B,
                                                            float* __restrict__ Cpart,
                                                            int M, int N, int K, int KC)
{
    constexpr int STR = 72;
    extern __shared__ __align__(16) char smem_raw[];
    __half* sA   = reinterpret_cast<__half*>(smem_raw);
    __half* sBhi = sA + 128 * STR;
    __half* sBlo = sBhi + 64 * STR;
    const uint32_t uA   = smem_u32(sA);
    const uint32_t uBhi = smem_u32(sBhi);
    const uint32_t uBlo = smem_u32(sBlo);

    const int t    = threadIdx.x;
    const int lane = t & 31;
    const int wid  = t >> 5;
    const int bn = blockIdx.x * 64;
    const int bm = blockIdx.y * 128;
    const int z  = blockIdx.z;
    const int m_base = (wid >> 1) * 32;
    const int n_base = (wid & 1) * 32;

    const int a_row_off = ((lane >> 3) & 1) * 8 + (lane & 7);
    const int a_kcol    = (lane >> 4) * 8;
    const int b_row     = (lane >> 4) * 8 + (lane & 7);
    const int b_kcol    = ((lane >> 3) & 1) * 8;

    const int kloc = (t & 31) * 2;
    const int r0   = t >> 5;
    const uint32_t* A32 = reinterpret_cast<const uint32_t*>(A);

    float acc[2][4][4];
#pragma unroll
    for (int i = 0; i < 2; i++)
#pragma unroll
        for (int j = 0; j < 4; j++)
#pragma unroll
            for (int e = 0; e < 4; e++) acc[i][j][e] = 0.f;

    const int nchunk = KC / 64;
    for (int c = 0; c < nchunk; c++) {
        const int kbase = z * KC + c * 64;
        {
            uint32_t soff = (uint32_t)(r0 * STR + kloc) * 2;
#pragma unroll
            for (int i = 0; i < 16; i++) {
                int m = bm + r0 + i * 8;
                uint32_t wv = (m < M) ? A32[((size_t)m * K + kbase + kloc) >> 1] : 0u;
                *reinterpret_cast<uint32_t*>(reinterpret_cast<char*>(sA) + soff) = wv;
                soff += 8 * STR * 2;
            }
        }
        {
            uint32_t soff = (uint32_t)(r0 * STR + kloc) * 2;
#pragma unroll
            for (int i = 0; i < 8; i++) {
                int n = bn + r0 + i * 8;
                const uint32_t* br = B + (size_t)n * K + kbase + kloc;
                uint32_t w0 = br[0], w1 = br[1];
                *reinterpret_cast<uint32_t*>(reinterpret_cast<char*>(sBhi) + soff) = __byte_perm(w0, w1, 0x5410);
                *reinterpret_cast<uint32_t*>(reinterpret_cast<char*>(sBlo) + soff) = __byte_perm(w0, w1, 0x7632);
                soff += 8 * STR * 2;
            }
        }
        __syncthreads();

#pragma unroll
        for (int ks = 0; ks < 4; ks++) {
            uint32_t av[2][4], bh[2][4], bl[2][4];
#pragma unroll
            for (int mt = 0; mt < 2; mt++) {
                uint32_t off = (uint32_t)((m_base + mt * 16 + a_row_off) * STR + ks * 16 + a_kcol) * 2;
                ldsm4(av[mt], uA + off);
            }
#pragma unroll
            for (int pr = 0; pr < 2; pr++) {
                uint32_t off = (uint32_t)((n_base + pr * 16 + b_row) * STR + ks * 16 + b_kcol) * 2;
                ldsm4(bh[pr], uBhi + off);
                ldsm4(bl[pr], uBlo + off);
            }
#pragma unroll
            for (int mt = 0; mt < 2; mt++) {
#pragma unroll
                for (int g = 0; g < 4; g++) {
                    const uint32_t* ph = &bh[g >> 1][(g & 1) * 2];
                    const uint32_t* pl = &bl[g >> 1][(g & 1) * 2];
                    mma_f16(acc[mt][g], av[mt], ph);
                    mma_f16(acc[mt][g], av[mt], pl);
                }
            }
        }
        __syncthreads();
    }

    const int gid  = lane >> 2;
    const int tid4 = lane & 3;
    float* oF = Cpart + (size_t)z * M * N;
#pragma unroll
    for (int mt = 0; mt < 2; mt++) {
#pragma unroll
        for (int g = 0; g < 4; g++) {
#pragma unroll
            for (int half = 0; half < 2; half++) {
                int m = bm + m_base + mt * 16 + gid + half * 8;
                if (m >= M) continue;
                int n0 = bn + n_base + g * 8 + tid4 * 2;
#pragma unroll
                for (int e = 0; e < 2; e++)
                    oF[(size_t)m * N + n0 + e] = acc[mt][g][half * 2 + e];
            }
        }
    }
}

// ---------------- bf16 3-term dense GEMM (transformer; unchanged) -----------
template<int ACT, bool PACKOUT>
__global__ __launch_bounds__(256) void hmma_gemm_kernel(const uint32_t* __restrict__ A,
                                                        const uint32_t* __restrict__ B,
                                                        const float* __restrict__ bias,
                                                        const float* __restrict__ res,
                                                        float* __restrict__ outF,
                                                        uint32_t* __restrict__ outP,
                                                        int M, int N, int K, int KC)
{
    constexpr int STR = 72;
    extern __shared__ __align__(16) char smem_raw[];
    __nv_bfloat16* sAhi = reinterpret_cast<__nv_bfloat16*>(smem_raw);
    __nv_bfloat16* sAlo = sAhi + 128 * STR;
    __nv_bfloat16* sBhi = sAlo + 128 * STR;
    __nv_bfloat16* sBlo = sBhi + 64 * STR;
    const uint32_t uAhi = smem_u32(sAhi);
    const uint32_t uAlo = smem_u32(sAlo);
    const uint32_t uBhi = smem_u32(sBhi);
    const uint32_t uBlo = smem_u32(sBlo);

    const int t    = threadIdx.x;
    const int lane = t & 31;
    const int wid  = t >> 5;
    const int bn = blockIdx.x * 64;
    const int bm = blockIdx.y * 128;
    const int z  = blockIdx.z;
    const int m_base = (wid >> 1) * 32;
    const int n_base = (wid & 1) * 32;

    const int a_row_off = ((lane >> 3) & 1) * 8 + (lane & 7);
    const int a_kcol    = (lane >> 4) * 8;
    const int b_row     = (lane >> 4) * 8 + (lane & 7);
    const int b_kcol    = ((lane >> 3) & 1) * 8;

    const int kloc = (t & 31) * 2;
    const int r0   = t >> 5;

    float acc[2][4][4];
#pragma unroll
    for (int i = 0; i < 2; i++)
#pragma unroll
        for (int j = 0; j < 4; j++)
#pragma unroll
            for (int e = 0; e < 4; e++) acc[i][j][e] = 0.f;

    const int nchunk = KC / 64;
    for (int c = 0; c < nchunk; c++) {
        const int kbase = z * KC + c * 64;
        {
            uint32_t soff = (uint32_t)(r0 * STR + kloc) * 2;
#pragma unroll
            for (int i = 0; i < 16; i++) {
                int m = bm + r0 + i * 8;
                uint32_t w0 = 0u, w1 = 0u;
                if (m < M) {
                    const uint32_t* ar = A + (size_t)m * K + kbase + kloc;
                    w0 = ar[0]; w1 = ar[1];
                }
                *reinterpret_cast<uint32_t*>(reinterpret_cast<char*>(sAhi) + soff) = __byte_perm(w0, w1, 0x5410);
                *reinterpret_cast<uint32_t*>(reinterpret_cast<char*>(sAlo) + soff) = __byte_perm(w0, w1, 0x7632);
                soff += 8 * STR * 2;
            }
        }
        {
            uint32_t soff = (uint32_t)(r0 * STR + kloc) * 2;
#pragma unroll
            for (int i = 0; i < 8; i++) {
                int n = bn + r0 + i * 8;
                const uint32_t* br = B + (size_t)n * K + kbase + kloc;
                uint32_t w0 = br[0], w1 = br[1];
                *reinterpret_cast<uint32_t*>(reinterpret_cast<char*>(sBhi) + soff) = __byte_perm(w0, w1, 0x5410);
                *reinterpret_cast<uint32_t*>(reinterpret_cast<char*>(sBlo) + soff) = __byte_perm(w0, w1, 0x7632);
                soff += 8 * STR * 2;
            }
        }
        __syncthreads();

#pragma unroll
        for (int ks = 0; ks < 4; ks++) {
            uint32_t ah[2][4], al[2][4], bh[2][4], bl[2][4];
#pragma unroll
            for (int mt = 0; mt < 2; mt++) {
                uint32_t off = (uint32_t)((m_base + mt * 16 + a_row_off) * STR + ks * 16 + a_kcol) * 2;
                ldsm4(ah[mt], uAhi + off);
                ldsm4(al[mt], uAlo + off);
            }
#pragma unroll
            for (int pr = 0; pr < 2; pr++) {
                uint32_t off = (uint32_t)((n_base + pr * 16 + b_row) * STR + ks * 16 + b_kcol) * 2;
                ldsm4(bh[pr], uBhi + off);
                ldsm4(bl[pr], uBlo + off);
            }
#pragma unroll
            for (int mt = 0; mt < 2; mt++) {
#pragma unroll
                for (int g = 0; g < 4; g++) {
                    const uint32_t* ph = &bh[g >> 1][(g & 1) * 2];
                    const uint32_t* pl = &bl[g >> 1][(g & 1) * 2];
                    mma_bf16(acc[mt][g], ah[mt], ph);
                    mma_bf16(acc[mt][g], ah[mt], pl);
                    mma_bf16(acc[mt][g], al[mt], ph);
                }
            }
        }
        __syncthreads();
    }

    const int gid  = lane >> 2;
    const int tid4 = lane & 3;
    float* oF = outF ? outF + (size_t)z * M * N : nullptr;
#pragma unroll
    for (int mt = 0; mt < 2; mt++) {
#pragma unroll
        for (int g = 0; g < 4; g++) {
#pragma unroll
            for (int half = 0; half < 2; half++) {
                int m = bm + m_base + mt * 16 + gid + half * 8;
                if (m >= M) continue;
                int n0 = bn + n_base + g * 8 + tid4 * 2;
#pragma unroll
                for (int e = 0; e < 2; e++) {
                    int n = n0 + e;
                    float v = acc[mt][g][half * 2 + e];
                    if (bias) v += bias[n];
                    if (ACT == 1) v = gelu_f(v);
                    if (res) v += res[(size_t)m * N + n];
                    if (PACKOUT) outP[(size_t)m * N + n] = pack_hilo_bf16(v);
                    else         oF[(size_t)m * N + n] = v;
                }
            }
        }
    }
}

// ---------------- pool helpers ----------------------------------------------
__device__ __forceinline__ void win7x4(const float* tp, float* o)
{
    float p[9], q[7];
#pragma unroll
    for (int i = 0; i < 9; i++) p[i] = fmaxf(tp[i], tp[i + 1]);
#pragma unroll
    for (int i = 0; i < 7; i++) q[i] = fmaxf(p[i], p[i + 2]);
#pragma unroll
    for (int j = 0; j < 4; j++) o[j] = fmaxf(q[j], fmaxf(p[j + 4], tp[j + 6]));
}

// pool1: 107x107 -> 103 x (stride P1W), fp16 smem
__global__ __launch_bounds__(256) void pool1_plane_kernel(const float* __restrict__ in,
                                                          __half* __restrict__ out)
{
    constexpr int IN_HW = 107, OUT = 103;
    constexpr int CW4 = (OUT + 3) / 4;
    __shared__ __half s_raw[IN_HW * IN_HW];
    __shared__ __half s_col[IN_HW * OUT];
    const size_t plane = blockIdx.x;
    const float* ip = in + plane * IN_HW * IN_HW;
    for (int idx = threadIdx.x; idx < IN_HW * IN_HW; idx += 256)
        s_raw[idx] = __float2half_rn(ip[idx]);
    __syncthreads();
    for (int idx = threadIdx.x; idx < IN_HW * CW4; idx += 256) {
        int r = idx / CW4, ox0 = (idx - r * CW4) * 4;
        const __half* rowp = &s_raw[r * IN_HW];
        float tp[10], o[4];
#pragma unroll
        for (int j = 0; j < 10; j++) {
            int xi = min(max(ox0 - 1 + j, 0), IN_HW - 1);
            tp[j] = __half2float(rowp[xi]);
        }
        win7x4(tp, o);
#pragma unroll
        for (int j = 0; j < 4; j++)
            if (ox0 + j < OUT) s_col[r * OUT + ox0 + j] = __float2half_rn(o[j]);
    }
    __syncthreads();
    __half* op = out + plane * OUT * P1W;
    for (int idx = threadIdx.x; idx < CW4 * OUT; idx += 256) {
        int oy0 = (idx / OUT) * 4, ox = idx - (idx / OUT) * OUT;
        float tp[10], o[4];
#pragma unroll
        for (int j = 0; j < 10; j++) {
            int yi = min(max(oy0 - 1 + j, 0), IN_HW - 1);
            tp[j] = __half2float(s_col[yi * OUT + ox]);
        }
        win7x4(tp, o);
#pragma unroll
        for (int j = 0; j < 4; j++) {
            int oyy = oy0 + j;
            if (oyy < OUT) op[(size_t)oyy * P1W + ox] = __float2half_rn(o[j]);
        }
    }
}

// generic plane pool: IN_HW -> OUT x (stride OSTR)
template<int IN_HW, int OSTR, int NT>
__global__ __launch_bounds__(NT) void pool_plane_kernel(const float* __restrict__ in,
                                                        __half* __restrict__ out)
{
    constexpr int OUT = IN_HW - 4;
    constexpr int CW4 = (OUT + 3) / 4;
    __shared__ float s_raw[IN_HW * IN_HW];
    __shared__ float s_col[IN_HW * OUT];
    const size_t plane = blockIdx.x;
    const float* ip = in + plane * IN_HW * IN_HW;
    for (int idx = threadIdx.x; idx < IN_HW * IN_HW; idx += NT) s_raw[idx] = ip[idx];
    __syncthreads();
    for (int idx = threadIdx.x; idx < IN_HW * CW4; idx += NT) {
        int r = idx / CW4, ox0 = (idx - r * CW4) * 4;
        const float* rowp = &s_raw[r * IN_HW];
        float tp[10], o[4];
#pragma unroll
        for (int j = 0; j < 10; j++) {
            int xi = min(max(ox0 - 1 + j, 0), IN_HW - 1);
            tp[j] = rowp[xi];
        }
        win7x4(tp, o);
#pragma unroll
        for (int j = 0; j < 4; j++)
            if (ox0 + j < OUT) s_col[r * OUT + ox0 + j] = o[j];
    }
    __syncthreads();
    __half* op = out + plane * OUT * OSTR;
    for (int idx = threadIdx.x; idx < CW4 * OUT; idx += NT) {
        int oy0 = (idx / OUT) * 4, ox = idx - (idx / OUT) * OUT;
        float tp[10], o[4];
#pragma unroll
        for (int j = 0; j < 10; j++) {
            int yi = min(max(oy0 - 1 + j, 0), IN_HW - 1);
            tp[j] = s_col[yi * OUT + ox];
        }
        win7x4(tp, o);
#pragma unroll
        for (int j = 0; j < 4; j++) {
            int oyy = oy0 + j;
            if (oyy < OUT) op[(size_t)oyy * OSTR + ox] = __float2half_rn(o[j]);
        }
    }
}

// ---------------- fp32 GEMM (head only) -------------------------------------
template<int ACT>
__global__ void gemm_kernel(const float* __restrict__ A, const float* __restrict__ Bm,
                            const float* __restrict__ bias, const float* __restrict__ res,
                            float* __restrict__ C, int M, int N, int K)
{
    __shared__ float sA[16][33];
    __shared__ float sB[16][64];
    const int bm = blockIdx.y * 32;
    const int bn = blockIdx.x * 64;
    const int t  = threadIdx.x;
    const int tm = (t >> 4) << 1;
    const int tn = (t & 15) << 2;
    float acc[2][4] = {{0, 0, 0, 0}, {0, 0, 0, 0}};
    for (int k0 = 0; k0 < K; k0 += 16) {
#pragma unroll
        for (int i = 0; i < 2; i++) {
            int e = t * 2 + i, m = e >> 4, kk = e & 15;
            sA[kk][m] = (bm + m < M) ? A[(size_t)(bm + m) * K + k0 + kk] : 0.f;
        }
#pragma unroll
        for (int i = 0; i < 4; i++) {
            int e = t * 4 + i, kk = e >> 6, n = e & 63;
            sB[kk][n] = (bn + n < N) ? Bm[(size_t)(k0 + kk) * N + bn + n] : 0.f;
        }
        __syncthreads();
#pragma unroll
        for (int kk = 0; kk < 16; kk++) {
            float a0 = sA[kk][tm], a1 = sA[kk][tm + 1];
            float b0 = sB[kk][tn + 0], b1 = sB[kk][tn + 1];
            float b2 = sB[kk][tn + 2], b3 = sB[kk][tn + 3];
            acc[0][0] = fmaf(a0, b0, acc[0][0]); acc[0][1] = fmaf(a0, b1, acc[0][1]);
            acc[0][2] = fmaf(a0, b2, acc[0][2]); acc[0][3] = fmaf(a0, b3, acc[0][3]);
            acc[1][0] = fmaf(a1, b0, acc[1][0]); acc[1][1] = fmaf(a1, b1, acc[1][1]);
            acc[1][2] = fmaf(a1, b2, acc[1][2]); acc[1][3] = fmaf(a1, b3, acc[1][3]);
        }
        __syncthreads();
    }
#pragma unroll
    for (int i = 0; i < 2; i++) {
        int m = bm + tm + i;
        if (m >= M) continue;
#pragma unroll
        for (int j = 0; j < 4; j++) {
            int n = bn + tn + j;
            if (n >= N) continue;
            float v = acc[i][j];
            if (bias) v += bias[n];
            if (ACT == 1) v = gelu_f(v);
            if (res) v += res[(size_t)m * N + n];
            C[(size_t)m * N + n] = v;
        }
    }
}

__global__ void flat_reduce_kernel(const float* __restrict__ part, const float* __restrict__ bias,
                                   float* __restrict__ outp, int M, int N, int S)
{
    int idx = blockIdx.x * blockDim.x + threadIdx.x;
    if (idx >= M * N) return;
    float v = bias[idx % N];
    for (int s = 0; s < S; s++) v += part[(size_t)s * M * N + idx];
    outp[idx] = v;
}

// ff2 split-K reduce: x = x + bias + sum(partials)
__global__ void resadd_reduce_kernel(const float* __restrict__ part, const float* __restrict__ bias,
                                     float* __restrict__ x, int M, int N, int S)
{
    int idx = blockIdx.x * blockDim.x + threadIdx.x;
    if (idx >= M * N) return;
    float v = x[idx] + bias[idx % N];
    for (int s = 0; s < S; s++) v += part[(size_t)s * M * N + idx];
    x[idx] = v;
}

// ---------------- LayerNorm over 512 ----------------------------------------
template<bool PACK, typename OT>
__global__ void ln_kernel(const float* __restrict__ x, const float* __restrict__ g,
                          const float* __restrict__ bb, OT* __restrict__ out,
                          int row_stride)
{
    const int row = blockIdx.x;
    const float* xr = x + (size_t)row * row_stride;
    OT* orow = out + (size_t)row * 512;
    const int t = threadIdx.x;
    float v[4], s = 0.f, s2 = 0.f;
#pragma unroll
    for (int i = 0; i < 4; i++) { v[i] = xr[i * 128 + t]; s += v[i]; s2 += v[i] * v[i]; }
#pragma unroll
    for (int o = 16; o; o >>= 1) {
        s  += __shfl_xor_sync(0xffffffffu, s,  o);
        s2 += __shfl_xor_sync(0xffffffffu, s2, o);
    }
    __shared__ float rs[4], rs2[4];
    if ((t & 31) == 0) { rs[t >> 5] = s; rs2[t >> 5] = s2; }
    __syncthreads();
    float tot  = rs[0] + rs[1] + rs[2] + rs[3];
    float tot2 = rs2[0] + rs2[1] + rs2[2] + rs2[3];
    float mean = tot  * (1.f / 512.f);
    float var  = tot2 * (1.f / 512.f) - mean * mean;
    float rstd = rsqrtf(var + 1e-5f);
#pragma unroll
    for (int i = 0; i < 4; i++) {
        int c = i * 128 + t;
        float ov = (v[i] - mean) * rstd * g[c] + bb[c];
        if (PACK) orow[c] = (OT)pack_hilo_bf16(ov);
        else      orow[c] = (OT)ov;
    }
}

// ---------------- token assembly --------------------------------------------
__global__ void embed_kernel(const float* __restrict__ cls_token, const float* __restrict__ pos_emb)
{
    int idx = blockIdx.x * blockDim.x + threadIdx.x;
    if (idx >= ROWS * 512) return;
    int row = idx >> 9, c = idx & 511;
    int b = row / 17, n = row - b * 17;
    float v = (n == 0) ? cls_token[c] : g_tok[(size_t)(b * 16 + n - 1) * 512 + c];
    g_x[idx] = v + pos_emb[n * 512 + c];
}

// ---------------- attention (writes packed bf16 output) ----------------------
__global__ void attn_kernel()
{
    const int bh = blockIdx.x;
    const int b = bh >> 3, h = bh & 7;
    __shared__ float q[17][64], kk[17][64], vv[17][64], s[17][17];
    const int t = threadIdx.x;
    for (int idx = t; idx < 17 * 64; idx += 128) {
        int n = idx >> 6, d = idx & 63;
        const float* base = g_qkv + (size_t)(b * 17 + n) * 1536 + h * 64 + d;
        q[n][d]  = base[0];
        kk[n][d] = base[512];
        vv[n][d] = base[1024];
    }
    __syncthreads();
    for (int idx = t; idx < 289; idx += 128) {
        int i = idx / 17, j = idx - i * 17;
        float a = 0.f;
#pragma unroll
        for (int d = 0; d < 64; d++) a = fmaf(q[i][d], kk[j][d], a);
        s[i][j] = a * 0.125f;
    }
    __syncthreads();
    if (t < 17) {
        float mx = -FLT_MAX;
        for (int j = 0; j < 17; j++) mx = fmaxf(mx, s[t][j]);
        float sum = 0.f;
        for (int j = 0; j < 17; j++) { float e = expf(s[t][j] - mx); s[t][j] = e; sum += e; }
        float inv = 1.f / sum;
        for (int j = 0; j < 17; j++) s[t][j] *= inv;
    }
    __syncthreads();
    for (int idx = t; idx < 17 * 64; idx += 128) {
        int n = idx >> 6, d = idx & 63;
        float a = 0.f;
#pragma unroll
        for (int j = 0; j < 17; j++) a = fmaf(s[n][j], vv[j][d], a);
        g_op[(size_t)(b * 17 + n) * 512 + h * 64 + d] = pack_hilo_bf16(a);
    }
}

// ---------------- host ------------------------------------------------------
extern "C" void kernel_launch(void* const* d_in, const int* in_sizes, int n_in,
                              void* d_out, int out_size)
{
    (void)in_sizes; (void)n_in; (void)out_size;
    const float* img     = (const float*)d_in[0];
    const float* conv1_w = (const float*)d_in[1];
    const float* conv2_w = (const float*)d_in[2];
    const float* conv3_w = (const float*)d_in[3];
    const float* flat_w  = (const float*)d_in[4];
    const float* flat_b  = (const float*)d_in[5];
    const float* cls_tok = (const float*)d_in[6];
    const float* pos_emb = (const float*)d_in[7];
    const float* ln1_g   = (const float*)d_in[8];
    const float* ln1_b   = (const float*)d_in[9];
    const float* qkv_w   = (const float*)d_in[10];
    const float* out_w   = (const float*)d_in[11];
    const float* out_b   = (const float*)d_in[12];
    const float* ln2_g   = (const float*)d_in[13];
    const float* ln2_b   = (const float*)d_in[14];
    const float* ff1_w   = (const float*)d_in[15];
    const float* ff1_b   = (const float*)d_in[16];
    const float* ff2_w   = (const float*)d_in[17];
    const float* ff2_b   = (const float*)d_in[18];
    const float* hln_g   = (const float*)d_in[19];
    const float* hln_b   = (const float*)d_in[20];
    const float* head_w  = (const float*)d_in[21];
    const float* head_b  = (const float*)d_in[22];
    float* out = (float*)d_out;

    float *p_c1, *p_c2, *p_c3;
    __half *p_imgh, *p_p1, *p_p2, *p_p3;
    uint32_t *p_w1, *p_w2, *p_w3;
    uint32_t *p_qkvw, *p_outw, *p_ff1w, *p_ff2w, *p_flatw, *p_hp, *p_op, *p_ffp;
    float *p_fpart, *p_tok, *p_x, *p_qkv, *p_cls;
    cudaGetSymbolAddress((void**)&p_imgh, g_imgh);
    cudaGetSymbolAddress((void**)&p_c1, g_c1);
    cudaGetSymbolAddress((void**)&p_p1, g_p1);
    cudaGetSymbolAddress((void**)&p_c2, g_c2);
    cudaGetSymbolAddress((void**)&p_p2, g_p2);
    cudaGetSymbolAddress((void**)&p_c3, g_c3);
    cudaGetSymbolAddress((void**)&p_p3, g_p3);
    cudaGetSymbolAddress((void**)&p_w1, g_w1);
    cudaGetSymbolAddress((void**)&p_w2, g_w2);
    cudaGetSymbolAddress((void**)&p_w3, g_w3);
    cudaGetSymbolAddress((void**)&p_qkvw, g_qkvw);
    cudaGetSymbolAddress((void**)&p_outw, g_outw);
    cudaGetSymbolAddress((void**)&p_ff1w, g_ff1w);
    cudaGetSymbolAddress((void**)&p_ff2w, g_ff2w);
    cudaGetSymbolAddress((void**)&p_flatw, g_flatw);
    cudaGetSymbolAddress((void**)&p_hp,  g_hp);
    cudaGetSymbolAddress((void**)&p_op,  g_op);
    cudaGetSymbolAddress((void**)&p_ffp, g_ffp);
    cudaGetSymbolAddress((void**)&p_fpart, g_fpart);
    cudaGetSymbolAddress((void**)&p_tok, g_tok);
    cudaGetSymbolAddress((void**)&p_x,   g_x);
    cudaGetSymbolAddress((void**)&p_qkv, g_qkv);
    cudaGetSymbolAddress((void**)&p_cls, g_cls);

    const int CONV_SMEM = (64 * CONV_LDA + 2 * 64 * 72) * 2;   // 35840
    const int F16_SMEM  = (128 + 2 * 64) * 72 * 2;             // 36864
    const int BF_SMEM   = (2 * 128 + 2 * 64) * 72 * 2;         // 55296
    cudaFuncSetAttribute(conv1_hmma_kernel,
                         cudaFuncAttributeMaxDynamicSharedMemorySize, CONV_SMEM);
    cudaFuncSetAttribute(conv_hmma_f16_kernel<32, 103, P1W, 49, 1568, 25>,
                         cudaFuncAttributeMaxDynamicSharedMemorySize, CONV_SMEM);
    cudaFuncSetAttribute(conv_hmma_f16_kernel<64, 45, P2W, 20, 3136, 49>,
                         cudaFuncAttributeMaxDynamicSharedMemorySize, CONV_SMEM);
    cudaFuncSetAttribute(hmma_gemm_f16_splitk,
                         cudaFuncAttributeMaxDynamicSharedMemorySize, F16_SMEM);
    cudaFuncSetAttribute(hmma_gemm_kernel<0, false>,
                         cudaFuncAttributeMaxDynamicSharedMemorySize, BF_SMEM);
    cudaFuncSetAttribute(hmma_gemm_kernel<1, true>,
                         cudaFuncAttributeMaxDynamicSharedMemorySize, BF_SMEM);

    dim3 tb(32, 8);
    // ---- order: conv2 is 6th launch (ncu -s 5 -c 1 capture) ----
    pack_conv1_w_kernel<<<(64 * 64 + 255) / 256, 256>>>(conv1_w, p_w1);                       // 1
    img2h_kernel<<<(16 * 880 * 880 + 255) / 256, 256>>>(img, p_imgh, 16 * 880 * 880);         // 2
    conv1_hmma_kernel<<<dim3(90, NPATCH), 256, CONV_SMEM>>>(p_imgh, p_w1, p_c1);              // 3
    pack_weights_f16_kernel<<<(64 * 1568 + 255) / 256, 256>>>(conv2_w, p_w2, 64 * 1568);      // 4
    pool1_plane_kernel<<<NPATCH * 32, 256>>>(p_c1, p_p1);                                     // 5
    conv_hmma_f16_kernel<32, 103, P1W, 49, 1568, 25>                                          // 6
        <<<dim3(19, NPATCH), 256, CONV_SMEM>>>(p_p1, p_w2, p_c2);
    pack_weights_f16_kernel<<<(64 * 3136 + 255) / 256, 256>>>(conv3_w, p_w3, 64 * 3136);
    pool_plane_kernel<49, P2W, 256><<<NPATCH * 64, 256>>>(p_c2, p_p2);

    conv_hmma_f16_kernel<64, 45, P2W, 20, 3136, 49>
        <<<dim3(4, NPATCH), 256, CONV_SMEM>>>(p_p2, p_w3, p_c3);
    pool_plane_kernel<20, 16, 128><<<NPATCH * 64, 128>>>(p_c3, p_p3);

    // ---- flatten linear: f16 split-K=16 ----
    transpose_pack_kernel<true><<<dim3(16, 512, 1), tb>>>(flat_w, p_flatw, 16384, 512);
    hmma_gemm_f16_splitk<<<dim3(8, 2, 16), 256, F16_SMEM>>>(
        p_p3, p_flatw, p_fpart, NPATCH, 512, 16384, 1024);
    flat_reduce_kernel<<<(NPATCH * 512 + 255) / 256, 256>>>(p_fpart, flat_b, p_tok,
                                                            NPATCH, 512, 16);
    embed_kernel<<<(ROWS * 512 + 255) / 256, 256>>>(cls_tok, pos_emb);

    // ---- transformer weight transposition ----
    transpose_pack_kernel<false><<<dim3(48, 16, 6), tb>>>(qkv_w, p_qkvw, 512, 1536);
    transpose_pack_kernel<false><<<dim3(16, 16, 6), tb>>>(out_w, p_outw, 512, 512);
    transpose_pack_kernel<false><<<dim3(64, 16, 6), tb>>>(ff1_w, p_ff1w, 512, 2048);
    transpose_pack_kernel<false><<<dim3(16, 64, 6), tb>>>(ff2_w, p_ff2w, 2048, 512);

    // ---- transformer layers ----
    for (int L = 0; L < 6; L++) {
        ln_kernel<true, uint32_t><<<ROWS, 128>>>(p_x, ln1_g + L * 512, ln1_b + L * 512, p_hp, 512);
        hmma_gemm_kernel<0, false><<<dim3(24, 3, 1), 256, BF_SMEM>>>(
            p_hp, p_qkvw + (size_t)L * 1536 * 512, nullptr, nullptr, p_qkv, nullptr,
            ROWS, 1536, 512, 512);
        attn_kernel<<<128, 128>>>();
        hmma_gemm_kernel<0, false><<<dim3(8, 3, 1), 256, BF_SMEM>>>(
            p_op, p_outw + (size_t)L * 512 * 512, out_b + L * 512, p_x, p_x, nullptr,
            ROWS, 512, 512, 512);
        ln_kernel<true, uint32_t><<<ROWS, 128>>>(p_x, ln2_g + L * 512, ln2_b + L * 512, p_hp, 512);
        hmma_gemm_kernel<1, true><<<dim3(32, 3, 1), 256, BF_SMEM>>>(
            p_hp, p_ff1w + (size_t)L * 2048 * 512, ff1_b + L * 2048, nullptr, nullptr, p_ffp,
            ROWS, 2048, 512, 512);
        // ff2: split-K=4 partials + residual reduce
        hmma_gemm_kernel<0, false><<<dim3(8, 3, 4), 256, BF_SMEM>>>(
            p_ffp, p_ff2w + (size_t)L * 512 * 2048, nullptr, nullptr, p_fpart, nullptr,
            ROWS, 512, 2048, 512);
        resadd_reduce_kernel<<<(ROWS * 512 + 255) / 256, 256>>>(p_fpart, ff2_b + L * 512,
                                                                p_x, ROWS, 512, 4);
    }

    // ---- head (small, fp32) ----
    ln_kernel<false, float><<<16, 128>>>(p_x, hln_g, hln_b, p_cls, 17 * 512);
    gemm_kernel<0><<<dim3((1000 + 63) / 64, 1), 256>>>(p_cls, head_w, head_b, nullptr, out, 16, 1000, 512);
}